// round 1
// baseline (speedup 1.0000x reference)
#include <cuda_runtime.h>
#include <math.h>
#include <stdint.h>

// ---------------------------------------------------------------------------
// Problem constants
// ---------------------------------------------------------------------------
constexpr int Bc = 64, Hc = 128, Wc = 128, PSc = 8, Gc = 16, Ec = 256;
constexpr int NSc = 8, ITc = 3, Vc = 10, FDc = 320, HEADSc = 4, HDc = 64;
constexpr int Nc = Gc * Gc;          // 256 tokens per image
constexpr int TOK = Bc * Nc;         // 16384 rows

// ---------------------------------------------------------------------------
// Device scratch (static allocations are the sanctioned workaround)
// ---------------------------------------------------------------------------
__device__ float g_P   [TOK * 768];        // im2col patches; reused for QKV
__device__ float g_x0  [TOK * Ec];
__device__ float g_ln  [TOK * Ec];
__device__ float g_h1  [TOK * 512];
__device__ float g_x2  [TOK * Ec];
__device__ float g_ao  [TOK * Ec];
__device__ float g_x3  [TOK * Ec];
__device__ float g_kin [TOK * FDc];
__device__ float g_vin [TOK * FDc];
__device__ float g_cosT[Nc * HDc];
__device__ float g_sinT[Nc * HDc];
__device__ float g_slots[Bc * NSc * FDc];
__device__ float g_sln  [Bc * NSc * FDc];
__device__ float g_qs   [Bc * NSc * FDc];
__device__ float g_sattn[Bc * Nc * NSc];
__device__ float g_denom[Bc * NSc];
__device__ float g_upd  [Bc * NSc * FDc];
__device__ float g_gi   [Bc * NSc * 3 * FDc];
__device__ float g_gh   [Bc * NSc * 3 * FDc];
__device__ float g_m1   [Bc * NSc * 2 * FDc];

// ---------------------------------------------------------------------------
// Helpers
// ---------------------------------------------------------------------------
__device__ __forceinline__ float gelu_exact(float x) {
    return 0.5f * x * (1.0f + erff(x * 0.70710678118654752f));
}

__device__ __forceinline__ float block_reduce_sum(float v, float* sh) {
    int lane = threadIdx.x & 31, wid = threadIdx.x >> 5;
    #pragma unroll
    for (int o = 16; o; o >>= 1) v += __shfl_xor_sync(0xffffffffu, v, o);
    if (lane == 0) sh[wid] = v;
    __syncthreads();
    float t = (threadIdx.x < (blockDim.x >> 5)) ? sh[threadIdx.x] : 0.f;
    if (wid == 0) {
        #pragma unroll
        for (int o = 4; o; o >>= 1) t += __shfl_xor_sync(0xffffffffu, t, o);
        if (lane == 0) sh[0] = t;
    }
    __syncthreads();
    float r = sh[0];
    __syncthreads();
    return r;
}

// ---------------------------------------------------------------------------
// RoPE tables
// ---------------------------------------------------------------------------
__global__ void rope_init_kernel() {
    int n = blockIdx.x;          // 0..255
    int d = threadIdx.x;         // 0..63
    int gy = n >> 4, gx = n & 15;
    int pos = (d < 32) ? gy : gx;
    int dd  = (d < 32) ? d : d - 32;
    float val;
    if (dd < 16) {
        float inv = expf(-9.210340371976184f * (2.0f * dd) / 32.0f);
        val = sinf((float)pos * inv);
    } else {
        float inv = expf(-9.210340371976184f * (2.0f * (dd - 16)) / 32.0f);
        val = cosf((float)pos * inv);
    }
    g_cosT[n * 64 + d] = cosf(val);
    g_sinT[n * 64 + d] = sinf(val);
}

// ---------------------------------------------------------------------------
// Patch / im2col builder: P[row=b*256+n, c*64+p] with one-hot + Sobel channels
// ---------------------------------------------------------------------------
__global__ void patch_kernel(const float* __restrict__ state, float* __restrict__ P) {
    int bn = blockIdx.x;
    int b = bn >> 8, n = bn & 255;
    int gy = n >> 4, gx = n & 15;
    int p = threadIdx.x;               // 0..63
    int py = p >> 3, px = p & 7;
    int y = gy * 8 + py, x = gx * 8 + px;
    const float* sb = state + (size_t)b * Hc * Wc;
    float* row = P + (size_t)bn * 768;
    for (int k = p; k < 768; k += 64) row[k] = 0.f;

    float v[3][3];
    #pragma unroll
    for (int di = 0; di < 3; di++) {
        int yy = min(max(y + di - 1, 0), Hc - 1);
        #pragma unroll
        for (int dj = 0; dj < 3; dj++) {
            int xx = min(max(x + dj - 1, 0), Wc - 1);
            v[di][dj] = sb[yy * Wc + xx];
        }
    }
    float sx = (v[0][2] + 2.f * v[1][2] + v[2][2]) - (v[0][0] + 2.f * v[1][0] + v[2][0]);
    float sy = (v[2][0] + 2.f * v[2][1] + v[2][2]) - (v[0][0] + 2.f * v[0][1] + v[0][2]);
    int id = (int)sb[y * Wc + x];
    __syncthreads();
    row[id * 64 + p]  = 1.f;
    row[640 + p]      = sx;
    row[704 + p]      = sy;
}

// ---------------------------------------------------------------------------
// Generic NT SGEMM: C[M,N] = act(A[M,K] @ W[N,K]^T + bias) (+ res)
// BM=BN=64, BK=16, 256 threads, 4x4 per thread. M%64==0, N%64==0, K%16==0.
// ---------------------------------------------------------------------------
__global__ __launch_bounds__(256)
void gemm_nt_kernel(const float* __restrict__ A, const float* __restrict__ W,
                    const float* __restrict__ bias, const float* __restrict__ res,
                    float* __restrict__ C, int M, int N, int K, int act) {
    __shared__ float As[16][68];
    __shared__ float Ws[16][68];
    int tid  = threadIdx.x;
    int m0 = blockIdx.y * 64, n0 = blockIdx.x * 64;
    int lrow = tid >> 2;               // 0..63
    int lk   = (tid & 3) << 2;         // 0,4,8,12
    int ty4  = (tid >> 4) << 2;        // row offset 0..60
    int tx4  = (tid & 15) << 2;        // col offset 0..60

    float acc[4][4] = {};
    const float* Ap = A + (size_t)(m0 + lrow) * K + lk;
    const float* Wp = W + (size_t)(n0 + lrow) * K + lk;

    for (int kt = 0; kt < K; kt += 16) {
        float4 av = *(const float4*)(Ap + kt);
        float4 wv = *(const float4*)(Wp + kt);
        As[lk + 0][lrow] = av.x; As[lk + 1][lrow] = av.y;
        As[lk + 2][lrow] = av.z; As[lk + 3][lrow] = av.w;
        Ws[lk + 0][lrow] = wv.x; Ws[lk + 1][lrow] = wv.y;
        Ws[lk + 2][lrow] = wv.z; Ws[lk + 3][lrow] = wv.w;
        __syncthreads();
        #pragma unroll
        for (int kk = 0; kk < 16; kk++) {
            float4 a = *(const float4*)&As[kk][ty4];
            float4 w = *(const float4*)&Ws[kk][tx4];
            float ar[4] = {a.x, a.y, a.z, a.w};
            float wr[4] = {w.x, w.y, w.z, w.w};
            #pragma unroll
            for (int i = 0; i < 4; i++)
                #pragma unroll
                for (int j = 0; j < 4; j++)
                    acc[i][j] += ar[i] * wr[j];
        }
        __syncthreads();
    }

    #pragma unroll
    for (int i = 0; i < 4; i++) {
        int gm = m0 + ty4 + i;
        #pragma unroll
        for (int j = 0; j < 4; j++) {
            int gn = n0 + tx4 + j;
            float c = acc[i][j];
            if (bias) c += bias[gn];
            if (act == 1) c = gelu_exact(c);
            size_t idx = (size_t)gm * N + gn;
            if (res) c += res[idx];
            C[idx] = c;
        }
    }
}

static inline void gemm_nt(const float* A, const float* W, const float* bias,
                           const float* res, float* C, int M, int N, int K, int act) {
    dim3 grid(N / 64, M / 64);
    gemm_nt_kernel<<<grid, 256>>>(A, W, bias, res, C, M, N, K, act);
}

// ---------------------------------------------------------------------------
// LayerNorm over last dim
// ---------------------------------------------------------------------------
__global__ void ln_kernel(const float* __restrict__ x, const float* __restrict__ g,
                          const float* __restrict__ b, float* __restrict__ y, int cols) {
    __shared__ float sh[32];
    int row = blockIdx.x;
    const float* xr = x + (size_t)row * cols;
    float s = 0.f;
    for (int c = threadIdx.x; c < cols; c += blockDim.x) s += xr[c];
    float mean = block_reduce_sum(s, sh) / (float)cols;
    float v = 0.f;
    for (int c = threadIdx.x; c < cols; c += blockDim.x) {
        float d = xr[c] - mean; v += d * d;
    }
    float var = block_reduce_sum(v, sh) / (float)cols;
    float inv = rsqrtf(var + 1e-5f);
    float* yr = y + (size_t)row * cols;
    for (int c = threadIdx.x; c < cols; c += blockDim.x)
        yr[c] = (xr[c] - mean) * inv * g[c] + b[c];
}

// ---------------------------------------------------------------------------
// RoPE apply to q,k inside the packed qkv buffer (row = b*256+n, 768 cols)
// ---------------------------------------------------------------------------
__global__ void rope_apply_kernel(float* __restrict__ qkv) {
    int row = blockIdx.x;
    int n = row & 255;
    int g = threadIdx.x >> 5;   // 0..7 -> (s,h)
    int t = threadIdx.x & 31;
    int s = g >> 2, h = g & 3;
    __shared__ float sh[8][64];
    float* p = qkv + (size_t)row * 768 + s * 256 + h * 64;
    sh[g][t]      = p[t];
    sh[g][t + 32] = p[t + 32];
    __syncwarp();
    float c1 = g_cosT[n * 64 + t],      s1 = g_sinT[n * 64 + t];
    float c2 = g_cosT[n * 64 + t + 32], s2 = g_sinT[n * 64 + t + 32];
    float o1 = sh[g][t]      * c1 - sh[g][2 * t + 1] * s1;
    float o2 = sh[g][t + 32] * c2 + sh[g][2 * t]     * s2;
    p[t]      = o1;
    p[t + 32] = o2;
}

// ---------------------------------------------------------------------------
// Attention: one thread per query, online softmax, 64-key smem tiles.
// grid (HEADS, B), block 256.
// ---------------------------------------------------------------------------
__global__ __launch_bounds__(256)
void attn_kernel(const float* __restrict__ qkv, float* __restrict__ ao) {
    int h = blockIdx.x, b = blockIdx.y;
    int n = threadIdx.x;
    const float* base = qkv + (size_t)b * 256 * 768;

    float q[64];
    {
        const float* qp = base + (size_t)n * 768 + h * 64;
        #pragma unroll
        for (int d = 0; d < 64; d++) q[d] = qp[d];
    }
    float m = -1e30f, l = 0.f;
    float acc[64];
    #pragma unroll
    for (int d = 0; d < 64; d++) acc[d] = 0.f;

    __shared__ float Ks[64][65];
    __shared__ float Vs[64][65];

    for (int t0 = 0; t0 < 256; t0 += 64) {
        for (int idx = threadIdx.x; idx < 64 * 64; idx += 256) {
            int kr = idx >> 6, kd = idx & 63;
            const float* rp = base + (size_t)(t0 + kr) * 768 + h * 64;
            Ks[kr][kd] = rp[256 + kd];
            Vs[kr][kd] = rp[512 + kd];
        }
        __syncthreads();
        for (int j = 0; j < 64; j++) {
            float s0 = 0.f, s1 = 0.f, s2 = 0.f, s3 = 0.f;
            #pragma unroll
            for (int d = 0; d < 64; d += 4) {
                s0 += q[d]     * Ks[j][d];
                s1 += q[d + 1] * Ks[j][d + 1];
                s2 += q[d + 2] * Ks[j][d + 2];
                s3 += q[d + 3] * Ks[j][d + 3];
            }
            float s = ((s0 + s1) + (s2 + s3)) * 0.125f;
            if (s > m) {
                float corr = __expf(m - s);
                l = l * corr + 1.f;
                #pragma unroll
                for (int d = 0; d < 64; d++) acc[d] = acc[d] * corr + Vs[j][d];
                m = s;
            } else {
                float p = __expf(s - m);
                l += p;
                #pragma unroll
                for (int d = 0; d < 64; d++) acc[d] += p * Vs[j][d];
            }
        }
        __syncthreads();
    }
    float inv = 1.f / l;
    float* op = ao + ((size_t)b * 256 + n) * 256 + h * 64;
    #pragma unroll
    for (int d = 0; d < 64; d++) op[d] = acc[d] * inv;
}

// ---------------------------------------------------------------------------
// Slot attention pieces
// ---------------------------------------------------------------------------
__global__ void zero_slots_kernel(float* __restrict__ slots) {
    int idx = blockIdx.x * blockDim.x + threadIdx.x;
    if (idx < Bc * NSc * FDc) slots[idx] = 0.f;
}

// logits + softmax over slots (8). grid(B), block 256 (8 warps).
__global__ void slot_logits_kernel(const float* __restrict__ kin,
                                   const float* __restrict__ qs,
                                   float* __restrict__ sattn) {
    int b = blockIdx.x;
    __shared__ float q[8][320];
    for (int i = threadIdx.x; i < 8 * 320; i += 256)
        q[i / 320][i % 320] = qs[b * 8 * 320 + i];
    __syncthreads();
    int warp = threadIdx.x >> 5, lane = threadIdx.x & 31;
    for (int n = warp; n < 256; n += 8) {
        const float* kr = kin + ((size_t)b * 256 + n) * 320;
        float part[8] = {0.f, 0.f, 0.f, 0.f, 0.f, 0.f, 0.f, 0.f};
        for (int f = lane; f < 320; f += 32) {
            float kv = kr[f];
            #pragma unroll
            for (int s = 0; s < 8; s++) part[s] += kv * q[s][f];
        }
        #pragma unroll
        for (int s = 0; s < 8; s++)
            #pragma unroll
            for (int o = 16; o; o >>= 1)
                part[s] += __shfl_xor_sync(0xffffffffu, part[s], o);
        if (lane == 0) {
            const float scale = 0.05590169943749474f;  // 1/sqrt(320)
            float mx = -1e30f;
            #pragma unroll
            for (int s = 0; s < 8; s++) { part[s] *= scale; mx = fmaxf(mx, part[s]); }
            float e[8], sum = 0.f;
            #pragma unroll
            for (int s = 0; s < 8; s++) { e[s] = expf(part[s] - mx); sum += e[s]; }
            float inv = 1.f / sum;
            #pragma unroll
            for (int s = 0; s < 8; s++)
                sattn[((size_t)b * 256 + n) * 8 + s] = e[s] * inv;
        }
    }
}

// denom[b,s] = sum_n (sattn + 1e-8). grid(B), block 256.
__global__ void colsum_kernel(const float* __restrict__ sattn, float* __restrict__ denom) {
    __shared__ float sh[32];
    int b = blockIdx.x;
    float part[8];
    #pragma unroll
    for (int s = 0; s < 8; s++) part[s] = 0.f;
    for (int n = threadIdx.x; n < 256; n += blockDim.x) {
        #pragma unroll
        for (int s = 0; s < 8; s++)
            part[s] += sattn[((size_t)b * 256 + n) * 8 + s] + 1e-8f;
    }
    #pragma unroll
    for (int s = 0; s < 8; s++) {
        float tot = block_reduce_sum(part[s], sh);
        if (threadIdx.x == 0) denom[b * 8 + s] = tot;
    }
}

// updates[b,s,f] = sum_n an[b,n,s] * vin[b,n,f]. grid (NS, B), block 320.
__global__ void updates_kernel(const float* __restrict__ sattn,
                               const float* __restrict__ denom,
                               const float* __restrict__ vin,
                               float* __restrict__ upd) {
    int s = blockIdx.x, b = blockIdx.y;
    int f = threadIdx.x;
    float inv = 1.f / denom[b * 8 + s];
    float acc = 0.f;
    for (int n = 0; n < 256; n++) {
        float a = (sattn[((size_t)b * 256 + n) * 8 + s] + 1e-8f) * inv;
        acc += a * vin[((size_t)b * 256 + n) * 320 + f];
    }
    upd[((size_t)b * 8 + s) * 320 + f] = acc;
}

__global__ void gru_kernel(const float* __restrict__ gi, const float* __restrict__ gh,
                           float* __restrict__ slots) {
    int idx = blockIdx.x * blockDim.x + threadIdx.x;
    if (idx >= 512 * 320) return;
    int row = idx / 320, f = idx % 320;
    float ir = gi[row * 960 + f], iz = gi[row * 960 + 320 + f], in_ = gi[row * 960 + 640 + f];
    float hr = gh[row * 960 + f], hz = gh[row * 960 + 320 + f], hn  = gh[row * 960 + 640 + f];
    float r = 1.f / (1.f + expf(-(ir + hr)));
    float z = 1.f / (1.f + expf(-(iz + hz)));
    float nn = tanhf(in_ + r * hn);
    float hprev = slots[idx];
    slots[idx] = (1.f - z) * nn + z * hprev;
}

// out = [slots flattened (163840), masks (b,s,n) (131072)]
__global__ void output_kernel(const float* __restrict__ slots,
                              const float* __restrict__ sattn,
                              float* __restrict__ out) {
    int idx = blockIdx.x * blockDim.x + threadIdx.x;
    const int SLOTS = Bc * NSc * FDc;      // 163840
    const int MASKS = Bc * NSc * Nc;       // 131072
    if (idx < SLOTS) {
        out[idx] = slots[idx];
    } else if (idx < SLOTS + MASKS) {
        int k = idx - SLOTS;
        int b = k / (NSc * Nc);
        int r = k % (NSc * Nc);
        int s = r / Nc;
        int n = r % Nc;
        out[idx] = sattn[((size_t)b * Nc + n) * NSc + s];
    }
}

// ---------------------------------------------------------------------------
// Host launcher
// ---------------------------------------------------------------------------
template <typename T>
static float* sym_addr(T& sym) {
    void* p = nullptr;
    cudaGetSymbolAddress(&p, sym);
    return (float*)p;
}

extern "C" void kernel_launch(void* const* d_in, const int* in_sizes, int n_in,
                              void* d_out, int out_size) {
    const float* state    = (const float*)d_in[0];
    const float* conv_w   = (const float*)d_in[1];
    const float* conv_b   = (const float*)d_in[2];
    const float* mlp_ln_g = (const float*)d_in[3];
    const float* mlp_ln_b = (const float*)d_in[4];
    const float* mlp_w1   = (const float*)d_in[5];
    const float* mlp_b1   = (const float*)d_in[6];
    const float* mlp_w2   = (const float*)d_in[7];
    const float* mlp_b2   = (const float*)d_in[8];
    const float* qkv_w    = (const float*)d_in[9];
    const float* qkv_b    = (const float*)d_in[10];
    const float* proj_w   = (const float*)d_in[11];
    const float* proj_b   = (const float*)d_in[12];
    const float* ni_g     = (const float*)d_in[13];
    const float* ni_b     = (const float*)d_in[14];
    const float* ns_g     = (const float*)d_in[15];
    const float* ns_b     = (const float*)d_in[16];
    const float* nm_g     = (const float*)d_in[17];
    const float* nm_b     = (const float*)d_in[18];
    const float* q_w      = (const float*)d_in[19];
    const float* k_w      = (const float*)d_in[20];
    const float* v_w      = (const float*)d_in[21];
    const float* gru_wih  = (const float*)d_in[22];
    const float* gru_whh  = (const float*)d_in[23];
    const float* gru_bih  = (const float*)d_in[24];
    const float* gru_bhh  = (const float*)d_in[25];
    const float* smlp_w1  = (const float*)d_in[26];
    const float* smlp_b1  = (const float*)d_in[27];
    const float* smlp_w2  = (const float*)d_in[28];
    const float* smlp_b2  = (const float*)d_in[29];
    float* out = (float*)d_out;

    float* P     = sym_addr(g_P);
    float* x0    = sym_addr(g_x0);
    float* lnb   = sym_addr(g_ln);
    float* h1    = sym_addr(g_h1);
    float* x2    = sym_addr(g_x2);
    float* ao    = sym_addr(g_ao);
    float* x3    = sym_addr(g_x3);
    float* kin   = sym_addr(g_kin);
    float* vin   = sym_addr(g_vin);
    float* slots = sym_addr(g_slots);
    float* sln   = sym_addr(g_sln);
    float* qs    = sym_addr(g_qs);
    float* sattn = sym_addr(g_sattn);
    float* denom = sym_addr(g_denom);
    float* upd   = sym_addr(g_upd);
    float* gi    = sym_addr(g_gi);
    float* gh    = sym_addr(g_gh);
    float* m1    = sym_addr(g_m1);

    // 1. RoPE tables + patch matrix
    rope_init_kernel<<<Nc, HDc>>>();
    patch_kernel<<<TOK, 64>>>(state, P);

    // 2. Patch conv as GEMM: x0 = P @ conv_w^T + conv_b
    gemm_nt(P, conv_w, conv_b, nullptr, x0, TOK, 256, 768, 0);

    // 3. Token MLP (note: replaces x, no residual)
    ln_kernel<<<TOK, 256>>>(x0, mlp_ln_g, mlp_ln_b, lnb, 256);
    gemm_nt(lnb, mlp_w1, mlp_b1, nullptr, h1, TOK, 512, 256, 1);
    gemm_nt(h1, mlp_w2, mlp_b2, nullptr, x2, TOK, 256, 512, 0);

    // 4. QKV (reuse P buffer) + RoPE + attention + proj (residual with x2)
    gemm_nt(x2, qkv_w, qkv_b, nullptr, P, TOK, 768, 256, 0);
    rope_apply_kernel<<<TOK, 256>>>(P);
    attn_kernel<<<dim3(HEADSc, Bc), 256>>>(P, ao);
    gemm_nt(ao, proj_w, proj_b, x2, x3, TOK, 256, 256, 0);

    // 5. Norm + k/v projections for slot attention
    ln_kernel<<<TOK, 256>>>(x3, ni_g, ni_b, lnb, 256);
    gemm_nt(lnb, k_w, nullptr, nullptr, kin, TOK, 320, 256, 0);
    gemm_nt(lnb, v_w, nullptr, nullptr, vin, TOK, 320, 256, 0);

    // 6. Slot attention, 3 iterations
    zero_slots_kernel<<<(Bc * NSc * FDc + 255) / 256, 256>>>(slots);
    for (int it = 0; it < ITc; it++) {
        ln_kernel<<<Bc * NSc, 256>>>(slots, ns_g, ns_b, sln, 320);
        gemm_nt(sln, q_w, nullptr, nullptr, qs, Bc * NSc, 320, 320, 0);
        slot_logits_kernel<<<Bc, 256>>>(kin, qs, sattn);
        colsum_kernel<<<Bc, 256>>>(sattn, denom);
        updates_kernel<<<dim3(NSc, Bc), FDc>>>(sattn, denom, vin, upd);
        gemm_nt(upd,   gru_wih, gru_bih, nullptr, gi, Bc * NSc, 960, 320, 0);
        gemm_nt(slots, gru_whh, gru_bhh, nullptr, gh, Bc * NSc, 960, 320, 0);
        gru_kernel<<<(512 * 320 + 255) / 256, 256>>>(gi, gh, slots);
        ln_kernel<<<Bc * NSc, 256>>>(slots, nm_g, nm_b, sln, 320);
        gemm_nt(sln, smlp_w1, smlp_b1, nullptr, m1, Bc * NSc, 640, 320, 1);
        gemm_nt(m1, smlp_w2, smlp_b2, slots, slots, Bc * NSc, 320, 640, 0);
    }

    // 7. Pack outputs: slots then masks
    int total = Bc * NSc * FDc + Bc * NSc * Nc;
    output_kernel<<<(total + 255) / 256, 256>>>(slots, sattn, out);
}

// round 2
// speedup vs baseline: 1.3092x; 1.3092x over previous
#include <cuda_runtime.h>
#include <math.h>
#include <stdint.h>

// ---------------------------------------------------------------------------
// Problem constants
// ---------------------------------------------------------------------------
constexpr int Bc = 64, Hc = 128, Wc = 128, PSc = 8, Gc = 16, Ec = 256;
constexpr int NSc = 8, ITc = 3, Vc = 10, FDc = 320, HEADSc = 4, HDc = 64;
constexpr int Nc = Gc * Gc;          // 256 tokens per image
constexpr int TOK = Bc * Nc;         // 16384 rows

// ---------------------------------------------------------------------------
// Device scratch
// ---------------------------------------------------------------------------
__device__ float g_P   [TOK * 768];        // im2col patches; reused for QKV
__device__ float g_x0  [TOK * Ec];
__device__ float g_ln  [TOK * Ec];
__device__ float g_h1  [TOK * 512];
__device__ float g_x2  [TOK * Ec];
__device__ float g_ao  [TOK * Ec];
__device__ float g_x3  [TOK * Ec];
__device__ float g_kin [TOK * FDc];
__device__ float g_vin [TOK * FDc];
__device__ float g_cosT[Nc * HDc];
__device__ float g_sinT[Nc * HDc];
__device__ float g_slots[Bc * NSc * FDc];
__device__ float g_sln  [Bc * NSc * FDc];
__device__ float g_qs   [Bc * NSc * FDc];
__device__ float g_sattn[Bc * Nc * NSc];
__device__ float g_denom[Bc * NSc];
__device__ float g_upd  [Bc * NSc * FDc];
__device__ float g_gi   [Bc * NSc * 3 * FDc];
__device__ float g_gh   [Bc * NSc * 3 * FDc];
__device__ float g_m1   [Bc * NSc * 2 * FDc];

// ---------------------------------------------------------------------------
// Helpers
// ---------------------------------------------------------------------------
__device__ __forceinline__ float gelu_exact(float x) {
    return 0.5f * x * (1.0f + erff(x * 0.70710678118654752f));
}

__device__ __forceinline__ uint32_t f2tf32(float x) {
    uint32_t r;
    asm("cvt.rna.tf32.f32 %0, %1;" : "=r"(r) : "f"(x));
    return r;
}

__device__ __forceinline__ void mma_tf32(float (&d)[4], const uint32_t (&a)[4],
                                         const uint32_t (&b)[2]) {
    asm volatile(
        "mma.sync.aligned.m16n8k8.row.col.f32.tf32.tf32.f32 "
        "{%0,%1,%2,%3}, {%4,%5,%6,%7}, {%8,%9}, {%0,%1,%2,%3};\n"
        : "+f"(d[0]), "+f"(d[1]), "+f"(d[2]), "+f"(d[3])
        : "r"(a[0]), "r"(a[1]), "r"(a[2]), "r"(a[3]), "r"(b[0]), "r"(b[1]));
}

__device__ __forceinline__ float block_reduce_sum(float v, float* sh) {
    int lane = threadIdx.x & 31, wid = threadIdx.x >> 5;
    #pragma unroll
    for (int o = 16; o; o >>= 1) v += __shfl_xor_sync(0xffffffffu, v, o);
    if (lane == 0) sh[wid] = v;
    __syncthreads();
    float t = (threadIdx.x < (blockDim.x >> 5)) ? sh[threadIdx.x] : 0.f;
    if (wid == 0) {
        #pragma unroll
        for (int o = 4; o; o >>= 1) t += __shfl_xor_sync(0xffffffffu, t, o);
        if (lane == 0) sh[0] = t;
    }
    __syncthreads();
    float r = sh[0];
    __syncthreads();
    return r;
}

// ---------------------------------------------------------------------------
// RoPE tables
// ---------------------------------------------------------------------------
__global__ void rope_init_kernel() {
    int n = blockIdx.x;          // 0..255
    int d = threadIdx.x;         // 0..63
    int gy = n >> 4, gx = n & 15;
    int pos = (d < 32) ? gy : gx;
    int dd  = (d < 32) ? d : d - 32;
    float val;
    if (dd < 16) {
        float inv = expf(-9.210340371976184f * (2.0f * dd) / 32.0f);
        val = sinf((float)pos * inv);
    } else {
        float inv = expf(-9.210340371976184f * (2.0f * (dd - 16)) / 32.0f);
        val = cosf((float)pos * inv);
    }
    g_cosT[n * 64 + d] = cosf(val);
    g_sinT[n * 64 + d] = sinf(val);
}

// ---------------------------------------------------------------------------
// Patch / im2col builder
// ---------------------------------------------------------------------------
__global__ void patch_kernel(const float* __restrict__ state, float* __restrict__ P) {
    int bn = blockIdx.x;
    int b = bn >> 8, n = bn & 255;
    int gy = n >> 4, gx = n & 15;
    int p = threadIdx.x;               // 0..63
    int py = p >> 3, px = p & 7;
    int y = gy * 8 + py, x = gx * 8 + px;
    const float* sb = state + (size_t)b * Hc * Wc;
    float* row = P + (size_t)bn * 768;
    for (int k = p; k < 768; k += 64) row[k] = 0.f;

    float v[3][3];
    #pragma unroll
    for (int di = 0; di < 3; di++) {
        int yy = min(max(y + di - 1, 0), Hc - 1);
        #pragma unroll
        for (int dj = 0; dj < 3; dj++) {
            int xx = min(max(x + dj - 1, 0), Wc - 1);
            v[di][dj] = sb[yy * Wc + xx];
        }
    }
    float sx = (v[0][2] + 2.f * v[1][2] + v[2][2]) - (v[0][0] + 2.f * v[1][0] + v[2][0]);
    float sy = (v[2][0] + 2.f * v[2][1] + v[2][2]) - (v[0][0] + 2.f * v[0][1] + v[0][2]);
    int id = (int)sb[y * Wc + x];
    __syncthreads();
    row[id * 64 + p]  = 1.f;
    row[640 + p]      = sx;
    row[704 + p]      = sy;
}

// ---------------------------------------------------------------------------
// TF32 tensor-core GEMM: C[M,N] = act(A[M,K] @ W[N,K]^T + bias) (+ res)
// BM=128, BN=64, BK=16, 256 threads (8 warps), warp tile m64 x n16.
// M%128==0, N%64==0, K%16==0.
// ---------------------------------------------------------------------------
__global__ __launch_bounds__(256)
void gemm_tf32_kernel(const float* __restrict__ A, const float* __restrict__ W,
                      const float* __restrict__ bias, const float* __restrict__ res,
                      float* __restrict__ C, int M, int N, int K, int act) {
    // stride 20: MMA fragment LDS patterns are bank-conflict-free
    __shared__ uint32_t As[2][128][20];
    __shared__ uint32_t Bs[2][64][20];

    int tid = threadIdx.x;
    int m0 = blockIdx.y * 128, n0 = blockIdx.x * 64;
    int warp = tid >> 5, lane = tid & 31;
    int wm = warp & 1, wn = warp >> 1;   // wm 0..1 (m 64 each), wn 0..3 (n 16 each)
    int q = lane >> 2, t = lane & 3;

    int aRow = tid >> 2;                 // 0..63
    int k4   = (tid & 3) << 2;           // 0,4,8,12
    const float* Aptr  = A + (size_t)(m0 + aRow) * K + k4;
    const float* Aptr2 = Aptr + (size_t)64 * K;
    const float* Wptr  = W + (size_t)(n0 + aRow) * K + k4;

    float acc[4][2][4];
    #pragma unroll
    for (int mt = 0; mt < 4; mt++)
        #pragma unroll
        for (int nt = 0; nt < 2; nt++)
            #pragma unroll
            for (int i = 0; i < 4; i++) acc[mt][nt][i] = 0.f;

    int ntiles = K >> 4;
    float4 av0 = *(const float4*)(Aptr);
    float4 av1 = *(const float4*)(Aptr2);
    float4 bv  = *(const float4*)(Wptr);
    int buf = 0;
    As[0][aRow][k4 + 0] = f2tf32(av0.x); As[0][aRow][k4 + 1] = f2tf32(av0.y);
    As[0][aRow][k4 + 2] = f2tf32(av0.z); As[0][aRow][k4 + 3] = f2tf32(av0.w);
    As[0][aRow + 64][k4 + 0] = f2tf32(av1.x); As[0][aRow + 64][k4 + 1] = f2tf32(av1.y);
    As[0][aRow + 64][k4 + 2] = f2tf32(av1.z); As[0][aRow + 64][k4 + 3] = f2tf32(av1.w);
    Bs[0][aRow][k4 + 0] = f2tf32(bv.x); Bs[0][aRow][k4 + 1] = f2tf32(bv.y);
    Bs[0][aRow][k4 + 2] = f2tf32(bv.z); Bs[0][aRow][k4 + 3] = f2tf32(bv.w);
    __syncthreads();

    for (int kt = 0; kt < ntiles; kt++) {
        bool more = (kt + 1 < ntiles);
        if (more) {
            av0 = *(const float4*)(Aptr  + (kt + 1) * 16);
            av1 = *(const float4*)(Aptr2 + (kt + 1) * 16);
            bv  = *(const float4*)(Wptr  + (kt + 1) * 16);
        }
        #pragma unroll
        for (int ks = 0; ks < 2; ks++) {
            int kc = ks * 8 + t;
            uint32_t af[4][4], bf[2][2];
            #pragma unroll
            for (int mt = 0; mt < 4; mt++) {
                int r = wm * 64 + mt * 16 + q;
                af[mt][0] = As[buf][r][kc];
                af[mt][1] = As[buf][r + 8][kc];
                af[mt][2] = As[buf][r][kc + 4];
                af[mt][3] = As[buf][r + 8][kc + 4];
            }
            #pragma unroll
            for (int nt = 0; nt < 2; nt++) {
                int n = wn * 16 + nt * 8 + q;
                bf[nt][0] = Bs[buf][n][kc];
                bf[nt][1] = Bs[buf][n][kc + 4];
            }
            #pragma unroll
            for (int mt = 0; mt < 4; mt++)
                #pragma unroll
                for (int nt = 0; nt < 2; nt++)
                    mma_tf32(acc[mt][nt], af[mt], bf[nt]);
        }
        __syncthreads();
        if (more) {
            buf ^= 1;
            As[buf][aRow][k4 + 0] = f2tf32(av0.x); As[buf][aRow][k4 + 1] = f2tf32(av0.y);
            As[buf][aRow][k4 + 2] = f2tf32(av0.z); As[buf][aRow][k4 + 3] = f2tf32(av0.w);
            As[buf][aRow + 64][k4 + 0] = f2tf32(av1.x); As[buf][aRow + 64][k4 + 1] = f2tf32(av1.y);
            As[buf][aRow + 64][k4 + 2] = f2tf32(av1.z); As[buf][aRow + 64][k4 + 3] = f2tf32(av1.w);
            Bs[buf][aRow][k4 + 0] = f2tf32(bv.x); Bs[buf][aRow][k4 + 1] = f2tf32(bv.y);
            Bs[buf][aRow][k4 + 2] = f2tf32(bv.z); Bs[buf][aRow][k4 + 3] = f2tf32(bv.w);
            __syncthreads();
        }
    }

    // Epilogue
    #pragma unroll
    for (int mt = 0; mt < 4; mt++) {
        #pragma unroll
        for (int nt = 0; nt < 2; nt++) {
            int gm0 = m0 + wm * 64 + mt * 16 + q;
            int gn  = n0 + wn * 16 + nt * 8 + 2 * t;
            float b0 = bias ? bias[gn]     : 0.f;
            float b1 = bias ? bias[gn + 1] : 0.f;
            #pragma unroll
            for (int half = 0; half < 2; half++) {
                int gm = gm0 + half * 8;
                float c0 = acc[mt][nt][half * 2 + 0] + b0;
                float c1 = acc[mt][nt][half * 2 + 1] + b1;
                if (act == 1) { c0 = gelu_exact(c0); c1 = gelu_exact(c1); }
                size_t idx = (size_t)gm * N + gn;
                if (res) { c0 += res[idx]; c1 += res[idx + 1]; }
                *(float2*)(C + idx) = make_float2(c0, c1);
            }
        }
    }
}

static inline void gemm_tf32(const float* A, const float* W, const float* bias,
                             const float* res, float* C, int M, int N, int K, int act) {
    dim3 grid(N / 64, M / 128);
    gemm_tf32_kernel<<<grid, 256>>>(A, W, bias, res, C, M, N, K, act);
}

// ---------------------------------------------------------------------------
// Exact-fp32 fallback SGEMM (slot-loop GEMMs). 64x64 tile, 4x4/thread.
// ---------------------------------------------------------------------------
__global__ __launch_bounds__(256)
void gemm_nt_kernel(const float* __restrict__ A, const float* __restrict__ W,
                    const float* __restrict__ bias, const float* __restrict__ res,
                    float* __restrict__ C, int M, int N, int K, int act) {
    __shared__ float As[16][68];
    __shared__ float Ws[16][68];
    int tid  = threadIdx.x;
    int m0 = blockIdx.y * 64, n0 = blockIdx.x * 64;
    int lrow = tid >> 2;
    int lk   = (tid & 3) << 2;
    int ty4  = (tid >> 4) << 2;
    int tx4  = (tid & 15) << 2;

    float acc[4][4] = {};
    const float* Ap = A + (size_t)(m0 + lrow) * K + lk;
    const float* Wp = W + (size_t)(n0 + lrow) * K + lk;

    for (int kt = 0; kt < K; kt += 16) {
        float4 av = *(const float4*)(Ap + kt);
        float4 wv = *(const float4*)(Wp + kt);
        As[lk + 0][lrow] = av.x; As[lk + 1][lrow] = av.y;
        As[lk + 2][lrow] = av.z; As[lk + 3][lrow] = av.w;
        Ws[lk + 0][lrow] = wv.x; Ws[lk + 1][lrow] = wv.y;
        Ws[lk + 2][lrow] = wv.z; Ws[lk + 3][lrow] = wv.w;
        __syncthreads();
        #pragma unroll
        for (int kk = 0; kk < 16; kk++) {
            float4 a = *(const float4*)&As[kk][ty4];
            float4 w = *(const float4*)&Ws[kk][tx4];
            float ar[4] = {a.x, a.y, a.z, a.w};
            float wr[4] = {w.x, w.y, w.z, w.w};
            #pragma unroll
            for (int i = 0; i < 4; i++)
                #pragma unroll
                for (int j = 0; j < 4; j++)
                    acc[i][j] += ar[i] * wr[j];
        }
        __syncthreads();
    }

    #pragma unroll
    for (int i = 0; i < 4; i++) {
        int gm = m0 + ty4 + i;
        #pragma unroll
        for (int j = 0; j < 4; j++) {
            int gn = n0 + tx4 + j;
            float c = acc[i][j];
            if (bias) c += bias[gn];
            if (act == 1) c = gelu_exact(c);
            size_t idx = (size_t)gm * N + gn;
            if (res) c += res[idx];
            C[idx] = c;
        }
    }
}

static inline void gemm_nt(const float* A, const float* W, const float* bias,
                           const float* res, float* C, int M, int N, int K, int act) {
    dim3 grid(N / 64, M / 64);
    gemm_nt_kernel<<<grid, 256>>>(A, W, bias, res, C, M, N, K, act);
}

// ---------------------------------------------------------------------------
// LayerNorm over last dim
// ---------------------------------------------------------------------------
__global__ void ln_kernel(const float* __restrict__ x, const float* __restrict__ g,
                          const float* __restrict__ b, float* __restrict__ y, int cols) {
    __shared__ float sh[32];
    int row = blockIdx.x;
    const float* xr = x + (size_t)row * cols;
    float s = 0.f;
    for (int c = threadIdx.x; c < cols; c += blockDim.x) s += xr[c];
    float mean = block_reduce_sum(s, sh) / (float)cols;
    float v = 0.f;
    for (int c = threadIdx.x; c < cols; c += blockDim.x) {
        float d = xr[c] - mean; v += d * d;
    }
    float var = block_reduce_sum(v, sh) / (float)cols;
    float inv = rsqrtf(var + 1e-5f);
    float* yr = y + (size_t)row * cols;
    for (int c = threadIdx.x; c < cols; c += blockDim.x)
        yr[c] = (xr[c] - mean) * inv * g[c] + b[c];
}

// ---------------------------------------------------------------------------
// RoPE apply to q,k inside the packed qkv buffer (row = b*256+n, 768 cols)
// ---------------------------------------------------------------------------
__global__ void rope_apply_kernel(float* __restrict__ qkv) {
    int row = blockIdx.x;
    int n = row & 255;
    int g = threadIdx.x >> 5;   // 0..7 -> (s,h)
    int t = threadIdx.x & 31;
    int s = g >> 2, h = g & 3;
    __shared__ float sh[8][64];
    float* p = qkv + (size_t)row * 768 + s * 256 + h * 64;
    sh[g][t]      = p[t];
    sh[g][t + 32] = p[t + 32];
    __syncwarp();
    float c1 = g_cosT[n * 64 + t],      s1 = g_sinT[n * 64 + t];
    float c2 = g_cosT[n * 64 + t + 32], s2 = g_sinT[n * 64 + t + 32];
    float o1 = sh[g][t]      * c1 - sh[g][2 * t + 1] * s1;
    float o2 = sh[g][t + 32] * c2 + sh[g][2 * t]     * s2;
    p[t]      = o1;
    p[t + 32] = o2;
}

// ---------------------------------------------------------------------------
// Attention: one thread per query, online softmax, 64-key smem tiles.
// ---------------------------------------------------------------------------
__global__ __launch_bounds__(256)
void attn_kernel(const float* __restrict__ qkv, float* __restrict__ ao) {
    int h = blockIdx.x, b = blockIdx.y;
    int n = threadIdx.x;
    const float* base = qkv + (size_t)b * 256 * 768;

    float q[64];
    {
        const float* qp = base + (size_t)n * 768 + h * 64;
        #pragma unroll
        for (int d = 0; d < 64; d++) q[d] = qp[d];
    }
    float m = -1e30f, l = 0.f;
    float acc[64];
    #pragma unroll
    for (int d = 0; d < 64; d++) acc[d] = 0.f;

    __shared__ float Ks[64][65];
    __shared__ float Vs[64][65];

    for (int t0 = 0; t0 < 256; t0 += 64) {
        for (int idx = threadIdx.x; idx < 64 * 64; idx += 256) {
            int kr = idx >> 6, kd = idx & 63;
            const float* rp = base + (size_t)(t0 + kr) * 768 + h * 64;
            Ks[kr][kd] = rp[256 + kd];
            Vs[kr][kd] = rp[512 + kd];
        }
        __syncthreads();
        for (int j = 0; j < 64; j++) {
            float s0 = 0.f, s1 = 0.f, s2 = 0.f, s3 = 0.f;
            #pragma unroll
            for (int d = 0; d < 64; d += 4) {
                s0 += q[d]     * Ks[j][d];
                s1 += q[d + 1] * Ks[j][d + 1];
                s2 += q[d + 2] * Ks[j][d + 2];
                s3 += q[d + 3] * Ks[j][d + 3];
            }
            float s = ((s0 + s1) + (s2 + s3)) * 0.125f;
            if (s > m) {
                float corr = __expf(m - s);
                l = l * corr + 1.f;
                #pragma unroll
                for (int d = 0; d < 64; d++) acc[d] = acc[d] * corr + Vs[j][d];
                m = s;
            } else {
                float p = __expf(s - m);
                l += p;
                #pragma unroll
                for (int d = 0; d < 64; d++) acc[d] += p * Vs[j][d];
            }
        }
        __syncthreads();
    }
    float inv = 1.f / l;
    float* op = ao + ((size_t)b * 256 + n) * 256 + h * 64;
    #pragma unroll
    for (int d = 0; d < 64; d++) op[d] = acc[d] * inv;
}

// ---------------------------------------------------------------------------
// Slot attention pieces
// ---------------------------------------------------------------------------
__global__ void zero_slots_kernel(float* __restrict__ slots) {
    int idx = blockIdx.x * blockDim.x + threadIdx.x;
    if (idx < Bc * NSc * FDc) slots[idx] = 0.f;
}

__global__ void slot_logits_kernel(const float* __restrict__ kin,
                                   const float* __restrict__ qs,
                                   float* __restrict__ sattn) {
    int b = blockIdx.x;
    __shared__ float q[8][320];
    for (int i = threadIdx.x; i < 8 * 320; i += 256)
        q[i / 320][i % 320] = qs[b * 8 * 320 + i];
    __syncthreads();
    int warp = threadIdx.x >> 5, lane = threadIdx.x & 31;
    for (int n = warp; n < 256; n += 8) {
        const float* kr = kin + ((size_t)b * 256 + n) * 320;
        float part[8] = {0.f, 0.f, 0.f, 0.f, 0.f, 0.f, 0.f, 0.f};
        for (int f = lane; f < 320; f += 32) {
            float kv = kr[f];
            #pragma unroll
            for (int s = 0; s < 8; s++) part[s] += kv * q[s][f];
        }
        #pragma unroll
        for (int s = 0; s < 8; s++)
            #pragma unroll
            for (int o = 16; o; o >>= 1)
                part[s] += __shfl_xor_sync(0xffffffffu, part[s], o);
        if (lane == 0) {
            const float scale = 0.05590169943749474f;  // 1/sqrt(320)
            float mx = -1e30f;
            #pragma unroll
            for (int s = 0; s < 8; s++) { part[s] *= scale; mx = fmaxf(mx, part[s]); }
            float e[8], sum = 0.f;
            #pragma unroll
            for (int s = 0; s < 8; s++) { e[s] = expf(part[s] - mx); sum += e[s]; }
            float inv = 1.f / sum;
            #pragma unroll
            for (int s = 0; s < 8; s++)
                sattn[((size_t)b * 256 + n) * 8 + s] = e[s] * inv;
        }
    }
}

__global__ void colsum_kernel(const float* __restrict__ sattn, float* __restrict__ denom) {
    __shared__ float sh[32];
    int b = blockIdx.x;
    float part[8];
    #pragma unroll
    for (int s = 0; s < 8; s++) part[s] = 0.f;
    for (int n = threadIdx.x; n < 256; n += blockDim.x) {
        #pragma unroll
        for (int s = 0; s < 8; s++)
            part[s] += sattn[((size_t)b * 256 + n) * 8 + s] + 1e-8f;
    }
    #pragma unroll
    for (int s = 0; s < 8; s++) {
        float tot = block_reduce_sum(part[s], sh);
        if (threadIdx.x == 0) denom[b * 8 + s] = tot;
    }
}

// updates[b,s,f] = sum_n an[b,n,s]*vin[b,n,f]; vin read exactly once.
// grid(B), block 320.
__global__ __launch_bounds__(320)
void updates_kernel(const float* __restrict__ sattn,
                    const float* __restrict__ denom,
                    const float* __restrict__ vin,
                    float* __restrict__ upd) {
    int b = blockIdx.x;
    int f = threadIdx.x;
    __shared__ float an[256][8];
    __shared__ float inv[8];
    for (int i = threadIdx.x; i < 2048; i += 320)
        an[i >> 3][i & 7] = sattn[(size_t)b * 2048 + i] + 1e-8f;
    if (threadIdx.x < 8) inv[threadIdx.x] = 1.f / denom[b * 8 + threadIdx.x];
    __syncthreads();
    float acc[8] = {};
    const float* vp = vin + (size_t)b * 256 * 320 + f;
    for (int n = 0; n < 256; n++) {
        float v = vp[(size_t)n * 320];
        #pragma unroll
        for (int s = 0; s < 8; s++) acc[s] += an[n][s] * v;
    }
    #pragma unroll
    for (int s = 0; s < 8; s++)
        upd[((size_t)b * 8 + s) * 320 + f] = acc[s] * inv[s];
}

__global__ void gru_kernel(const float* __restrict__ gi, const float* __restrict__ gh,
                           float* __restrict__ slots) {
    int idx = blockIdx.x * blockDim.x + threadIdx.x;
    if (idx >= 512 * 320) return;
    int row = idx / 320, f = idx % 320;
    float ir = gi[row * 960 + f], iz = gi[row * 960 + 320 + f], in_ = gi[row * 960 + 640 + f];
    float hr = gh[row * 960 + f], hz = gh[row * 960 + 320 + f], hn  = gh[row * 960 + 640 + f];
    float r = 1.f / (1.f + expf(-(ir + hr)));
    float z = 1.f / (1.f + expf(-(iz + hz)));
    float nn = tanhf(in_ + r * hn);
    float hprev = slots[idx];
    slots[idx] = (1.f - z) * nn + z * hprev;
}

__global__ void output_kernel(const float* __restrict__ slots,
                              const float* __restrict__ sattn,
                              float* __restrict__ out) {
    int idx = blockIdx.x * blockDim.x + threadIdx.x;
    const int SLOTS = Bc * NSc * FDc;      // 163840
    const int MASKS = Bc * NSc * Nc;       // 131072
    if (idx < SLOTS) {
        out[idx] = slots[idx];
    } else if (idx < SLOTS + MASKS) {
        int k = idx - SLOTS;
        int b = k / (NSc * Nc);
        int r = k % (NSc * Nc);
        int s = r / Nc;
        int n = r % Nc;
        out[idx] = sattn[((size_t)b * Nc + n) * NSc + s];
    }
}

// ---------------------------------------------------------------------------
// Host launcher
// ---------------------------------------------------------------------------
template <typename T>
static float* sym_addr(T& sym) {
    void* p = nullptr;
    cudaGetSymbolAddress(&p, sym);
    return (float*)p;
}

extern "C" void kernel_launch(void* const* d_in, const int* in_sizes, int n_in,
                              void* d_out, int out_size) {
    const float* state    = (const float*)d_in[0];
    const float* conv_w   = (const float*)d_in[1];
    const float* conv_b   = (const float*)d_in[2];
    const float* mlp_ln_g = (const float*)d_in[3];
    const float* mlp_ln_b = (const float*)d_in[4];
    const float* mlp_w1   = (const float*)d_in[5];
    const float* mlp_b1   = (const float*)d_in[6];
    const float* mlp_w2   = (const float*)d_in[7];
    const float* mlp_b2   = (const float*)d_in[8];
    const float* qkv_w    = (const float*)d_in[9];
    const float* qkv_b    = (const float*)d_in[10];
    const float* proj_w   = (const float*)d_in[11];
    const float* proj_b   = (const float*)d_in[12];
    const float* ni_g     = (const float*)d_in[13];
    const float* ni_b     = (const float*)d_in[14];
    const float* ns_g     = (const float*)d_in[15];
    const float* ns_b     = (const float*)d_in[16];
    const float* nm_g     = (const float*)d_in[17];
    const float* nm_b     = (const float*)d_in[18];
    const float* q_w      = (const float*)d_in[19];
    const float* k_w      = (const float*)d_in[20];
    const float* v_w      = (const float*)d_in[21];
    const float* gru_wih  = (const float*)d_in[22];
    const float* gru_whh  = (const float*)d_in[23];
    const float* gru_bih  = (const float*)d_in[24];
    const float* gru_bhh  = (const float*)d_in[25];
    const float* smlp_w1  = (const float*)d_in[26];
    const float* smlp_b1  = (const float*)d_in[27];
    const float* smlp_w2  = (const float*)d_in[28];
    const float* smlp_b2  = (const float*)d_in[29];
    float* out = (float*)d_out;

    float* P     = sym_addr(g_P);
    float* x0    = sym_addr(g_x0);
    float* lnb   = sym_addr(g_ln);
    float* h1    = sym_addr(g_h1);
    float* x2    = sym_addr(g_x2);
    float* ao    = sym_addr(g_ao);
    float* x3    = sym_addr(g_x3);
    float* kin   = sym_addr(g_kin);
    float* vin   = sym_addr(g_vin);
    float* slots = sym_addr(g_slots);
    float* sln   = sym_addr(g_sln);
    float* qs    = sym_addr(g_qs);
    float* sattn = sym_addr(g_sattn);
    float* denom = sym_addr(g_denom);
    float* upd   = sym_addr(g_upd);
    float* gi    = sym_addr(g_gi);
    float* gh    = sym_addr(g_gh);
    float* m1    = sym_addr(g_m1);

    // 1. RoPE tables + patch matrix
    rope_init_kernel<<<Nc, HDc>>>();
    patch_kernel<<<TOK, 64>>>(state, P);

    // 2. Patch conv as GEMM (tensor cores)
    gemm_tf32(P, conv_w, conv_b, nullptr, x0, TOK, 256, 768, 0);

    // 3. Token MLP
    ln_kernel<<<TOK, 256>>>(x0, mlp_ln_g, mlp_ln_b, lnb, 256);
    gemm_tf32(lnb, mlp_w1, mlp_b1, nullptr, h1, TOK, 512, 256, 1);
    gemm_tf32(h1, mlp_w2, mlp_b2, nullptr, x2, TOK, 256, 512, 0);

    // 4. QKV + RoPE + attention + proj (residual with x2)
    gemm_tf32(x2, qkv_w, qkv_b, nullptr, P, TOK, 768, 256, 0);
    rope_apply_kernel<<<TOK, 256>>>(P);
    attn_kernel<<<dim3(HEADSc, Bc), 256>>>(P, ao);
    gemm_tf32(ao, proj_w, proj_b, x2, x3, TOK, 256, 256, 0);

    // 5. Norm + k/v projections
    ln_kernel<<<TOK, 256>>>(x3, ni_g, ni_b, lnb, 256);
    gemm_tf32(lnb, k_w, nullptr, nullptr, kin, TOK, 320, 256, 0);
    gemm_tf32(lnb, v_w, nullptr, nullptr, vin, TOK, 320, 256, 0);

    // 6. Slot attention, 3 iterations (exact fp32 path)
    zero_slots_kernel<<<(Bc * NSc * FDc + 255) / 256, 256>>>(slots);
    for (int it = 0; it < ITc; it++) {
        ln_kernel<<<Bc * NSc, 256>>>(slots, ns_g, ns_b, sln, 320);
        gemm_nt(sln, q_w, nullptr, nullptr, qs, Bc * NSc, 320, 320, 0);
        slot_logits_kernel<<<Bc, 256>>>(kin, qs, sattn);
        colsum_kernel<<<Bc, 256>>>(sattn, denom);
        updates_kernel<<<Bc, 320>>>(sattn, denom, vin, upd);
        gemm_nt(upd,   gru_wih, gru_bih, nullptr, gi, Bc * NSc, 960, 320, 0);
        gemm_nt(slots, gru_whh, gru_bhh, nullptr, gh, Bc * NSc, 960, 320, 0);
        gru_kernel<<<(512 * 320 + 255) / 256, 256>>>(gi, gh, slots);
        ln_kernel<<<Bc * NSc, 256>>>(slots, nm_g, nm_b, sln, 320);
        gemm_nt(sln, smlp_w1, smlp_b1, nullptr, m1, Bc * NSc, 640, 320, 1);
        gemm_nt(m1, smlp_w2, smlp_b2, slots, slots, Bc * NSc, 320, 640, 0);
    }

    // 7. Pack outputs
    int total = Bc * NSc * FDc + Bc * NSc * Nc;
    output_kernel<<<(total + 255) / 256, 256>>>(slots, sattn, out);
}

// round 3
// speedup vs baseline: 1.4668x; 1.1204x over previous
#include <cuda_runtime.h>
#include <math.h>
#include <stdint.h>

// ---------------------------------------------------------------------------
// Problem constants
// ---------------------------------------------------------------------------
constexpr int Bc = 64, Hc = 128, Wc = 128, PSc = 8, Gc = 16, Ec = 256;
constexpr int NSc = 8, ITc = 3, Vc = 10, FDc = 320, HEADSc = 4, HDc = 64;
constexpr int Nc = Gc * Gc;          // 256 tokens per image
constexpr int TOK = Bc * Nc;         // 16384 rows

// ---------------------------------------------------------------------------
// Device scratch
// ---------------------------------------------------------------------------
__device__ float g_P   [TOK * 768];        // im2col patches; reused for QKV
__device__ float g_x0  [TOK * Ec];
__device__ float g_ln  [TOK * Ec];
__device__ float g_h1  [TOK * 512];
__device__ float g_x2  [TOK * Ec];
__device__ float g_ao  [TOK * Ec];
__device__ float g_x3  [TOK * Ec];
__device__ float g_kin [TOK * FDc];
__device__ float g_vin [TOK * FDc];
__device__ float g_cosT[Nc * HDc];
__device__ float g_sinT[Nc * HDc];
__device__ float g_slots[Bc * NSc * FDc];
__device__ float g_sln  [Bc * NSc * FDc];
__device__ float g_qs   [Bc * NSc * FDc];
__device__ float g_sattn[Bc * Nc * NSc];
__device__ float g_denom[Bc * NSc];
__device__ float g_upd  [Bc * NSc * FDc];
__device__ float g_gi   [Bc * NSc * 3 * FDc];
__device__ float g_gh   [Bc * NSc * 3 * FDc];
__device__ float g_m1   [Bc * NSc * 2 * FDc];

// ---------------------------------------------------------------------------
// Helpers
// ---------------------------------------------------------------------------
__device__ __forceinline__ float gelu_exact(float x) {
    return 0.5f * x * (1.0f + erff(x * 0.70710678118654752f));
}

__device__ __forceinline__ uint32_t f2tf32(float x) {
    uint32_t r;
    asm("cvt.rna.tf32.f32 %0, %1;" : "=r"(r) : "f"(x));
    return r;
}

__device__ __forceinline__ void mma_tf32(float (&d)[4], const uint32_t (&a)[4],
                                         const uint32_t (&b)[2]) {
    asm volatile(
        "mma.sync.aligned.m16n8k8.row.col.f32.tf32.tf32.f32 "
        "{%0,%1,%2,%3}, {%4,%5,%6,%7}, {%8,%9}, {%0,%1,%2,%3};\n"
        : "+f"(d[0]), "+f"(d[1]), "+f"(d[2]), "+f"(d[3])
        : "r"(a[0]), "r"(a[1]), "r"(a[2]), "r"(a[3]), "r"(b[0]), "r"(b[1]));
}

// ---------------------------------------------------------------------------
// RoPE tables
// ---------------------------------------------------------------------------
__global__ void rope_init_kernel() {
    int n = blockIdx.x;          // 0..255
    int d = threadIdx.x;         // 0..63
    int gy = n >> 4, gx = n & 15;
    int pos = (d < 32) ? gy : gx;
    int dd  = (d < 32) ? d : d - 32;
    float val;
    if (dd < 16) {
        float inv = expf(-9.210340371976184f * (2.0f * dd) / 32.0f);
        val = sinf((float)pos * inv);
    } else {
        float inv = expf(-9.210340371976184f * (2.0f * (dd - 16)) / 32.0f);
        val = cosf((float)pos * inv);
    }
    g_cosT[n * 64 + d] = cosf(val);
    g_sinT[n * 64 + d] = sinf(val);
}

// ---------------------------------------------------------------------------
// Patch / im2col builder
// ---------------------------------------------------------------------------
__global__ void patch_kernel(const float* __restrict__ state, float* __restrict__ P) {
    int bn = blockIdx.x;
    int b = bn >> 8, n = bn & 255;
    int gy = n >> 4, gx = n & 15;
    int p = threadIdx.x;               // 0..63
    int py = p >> 3, px = p & 7;
    int y = gy * 8 + py, x = gx * 8 + px;
    const float* sb = state + (size_t)b * Hc * Wc;
    float* row = P + (size_t)bn * 768;
    for (int k = p; k < 768; k += 64) row[k] = 0.f;

    float v[3][3];
    #pragma unroll
    for (int di = 0; di < 3; di++) {
        int yy = min(max(y + di - 1, 0), Hc - 1);
        #pragma unroll
        for (int dj = 0; dj < 3; dj++) {
            int xx = min(max(x + dj - 1, 0), Wc - 1);
            v[di][dj] = sb[yy * Wc + xx];
        }
    }
    float sx = (v[0][2] + 2.f * v[1][2] + v[2][2]) - (v[0][0] + 2.f * v[1][0] + v[2][0]);
    float sy = (v[2][0] + 2.f * v[2][1] + v[2][2]) - (v[0][0] + 2.f * v[0][1] + v[0][2]);
    int id = (int)sb[y * Wc + x];
    __syncthreads();
    row[id * 64 + p]  = 1.f;
    row[640 + p]      = sx;
    row[704 + p]      = sy;
}

// ---------------------------------------------------------------------------
// TF32 tensor-core GEMM (fast path, big GEMMs): BM=128, BN=64, BK=16
// ---------------------------------------------------------------------------
__global__ __launch_bounds__(256)
void gemm_tf32_kernel(const float* __restrict__ A, const float* __restrict__ W,
                      const float* __restrict__ bias, const float* __restrict__ res,
                      float* __restrict__ C, int M, int N, int K, int act) {
    __shared__ uint32_t As[2][128][20];
    __shared__ uint32_t Bs[2][64][20];

    int tid = threadIdx.x;
    int m0 = blockIdx.y * 128, n0 = blockIdx.x * 64;
    int warp = tid >> 5, lane = tid & 31;
    int wm = warp & 1, wn = warp >> 1;
    int q = lane >> 2, t = lane & 3;

    int aRow = tid >> 2;
    int k4   = (tid & 3) << 2;
    const float* Aptr  = A + (size_t)(m0 + aRow) * K + k4;
    const float* Aptr2 = Aptr + (size_t)64 * K;
    const float* Wptr  = W + (size_t)(n0 + aRow) * K + k4;

    float acc[4][2][4];
    #pragma unroll
    for (int mt = 0; mt < 4; mt++)
        #pragma unroll
        for (int nt = 0; nt < 2; nt++)
            #pragma unroll
            for (int i = 0; i < 4; i++) acc[mt][nt][i] = 0.f;

    int ntiles = K >> 4;
    float4 av0 = *(const float4*)(Aptr);
    float4 av1 = *(const float4*)(Aptr2);
    float4 bv  = *(const float4*)(Wptr);
    int buf = 0;
    As[0][aRow][k4 + 0] = f2tf32(av0.x); As[0][aRow][k4 + 1] = f2tf32(av0.y);
    As[0][aRow][k4 + 2] = f2tf32(av0.z); As[0][aRow][k4 + 3] = f2tf32(av0.w);
    As[0][aRow + 64][k4 + 0] = f2tf32(av1.x); As[0][aRow + 64][k4 + 1] = f2tf32(av1.y);
    As[0][aRow + 64][k4 + 2] = f2tf32(av1.z); As[0][aRow + 64][k4 + 3] = f2tf32(av1.w);
    Bs[0][aRow][k4 + 0] = f2tf32(bv.x); Bs[0][aRow][k4 + 1] = f2tf32(bv.y);
    Bs[0][aRow][k4 + 2] = f2tf32(bv.z); Bs[0][aRow][k4 + 3] = f2tf32(bv.w);
    __syncthreads();

    for (int kt = 0; kt < ntiles; kt++) {
        bool more = (kt + 1 < ntiles);
        if (more) {
            av0 = *(const float4*)(Aptr  + (kt + 1) * 16);
            av1 = *(const float4*)(Aptr2 + (kt + 1) * 16);
            bv  = *(const float4*)(Wptr  + (kt + 1) * 16);
        }
        #pragma unroll
        for (int ks = 0; ks < 2; ks++) {
            int kc = ks * 8 + t;
            uint32_t af[4][4], bf[2][2];
            #pragma unroll
            for (int mt = 0; mt < 4; mt++) {
                int r = wm * 64 + mt * 16 + q;
                af[mt][0] = As[buf][r][kc];
                af[mt][1] = As[buf][r + 8][kc];
                af[mt][2] = As[buf][r][kc + 4];
                af[mt][3] = As[buf][r + 8][kc + 4];
            }
            #pragma unroll
            for (int nt = 0; nt < 2; nt++) {
                int n = wn * 16 + nt * 8 + q;
                bf[nt][0] = Bs[buf][n][kc];
                bf[nt][1] = Bs[buf][n][kc + 4];
            }
            #pragma unroll
            for (int mt = 0; mt < 4; mt++)
                #pragma unroll
                for (int nt = 0; nt < 2; nt++)
                    mma_tf32(acc[mt][nt], af[mt], bf[nt]);
        }
        __syncthreads();
        if (more) {
            buf ^= 1;
            As[buf][aRow][k4 + 0] = f2tf32(av0.x); As[buf][aRow][k4 + 1] = f2tf32(av0.y);
            As[buf][aRow][k4 + 2] = f2tf32(av0.z); As[buf][aRow][k4 + 3] = f2tf32(av0.w);
            As[buf][aRow + 64][k4 + 0] = f2tf32(av1.x); As[buf][aRow + 64][k4 + 1] = f2tf32(av1.y);
            As[buf][aRow + 64][k4 + 2] = f2tf32(av1.z); As[buf][aRow + 64][k4 + 3] = f2tf32(av1.w);
            Bs[buf][aRow][k4 + 0] = f2tf32(bv.x); Bs[buf][aRow][k4 + 1] = f2tf32(bv.y);
            Bs[buf][aRow][k4 + 2] = f2tf32(bv.z); Bs[buf][aRow][k4 + 3] = f2tf32(bv.w);
            __syncthreads();
        }
    }

    #pragma unroll
    for (int mt = 0; mt < 4; mt++) {
        #pragma unroll
        for (int nt = 0; nt < 2; nt++) {
            int gm0 = m0 + wm * 64 + mt * 16 + q;
            int gn  = n0 + wn * 16 + nt * 8 + 2 * t;
            float b0 = bias ? bias[gn]     : 0.f;
            float b1 = bias ? bias[gn + 1] : 0.f;
            #pragma unroll
            for (int half = 0; half < 2; half++) {
                int gm = gm0 + half * 8;
                float c0 = acc[mt][nt][half * 2 + 0] + b0;
                float c1 = acc[mt][nt][half * 2 + 1] + b1;
                if (act == 1) { c0 = gelu_exact(c0); c1 = gelu_exact(c1); }
                size_t idx = (size_t)gm * N + gn;
                if (res) { c0 += res[idx]; c1 += res[idx + 1]; }
                *(float2*)(C + idx) = make_float2(c0, c1);
            }
        }
    }
}

static inline void gemm_tf32(const float* A, const float* W, const float* bias,
                             const float* res, float* C, int M, int N, int K, int act) {
    dim3 grid(N / 64, M / 128);
    gemm_tf32_kernel<<<grid, 256>>>(A, W, bias, res, C, M, N, K, act);
}

// ---------------------------------------------------------------------------
// 3xTF32 GEMM (near-fp32 accuracy) for slot-loop GEMMs. BM=BN=64, BK=16.
// hi/lo split: x = hi + lo, D += Ah*Bh + Ah*Bl + Al*Bh.
// ---------------------------------------------------------------------------
__global__ __launch_bounds__(256)
void gemm_tf32x3_kernel(const float* __restrict__ A, const float* __restrict__ W,
                        const float* __restrict__ bias, const float* __restrict__ res,
                        float* __restrict__ C, int M, int N, int K, int act) {
    __shared__ uint32_t Ah[64][20], Al[64][20], Bh[64][20], Bl[64][20];

    int tid = threadIdx.x;
    int m0 = blockIdx.y * 64, n0 = blockIdx.x * 64;
    int warp = tid >> 5, lane = tid & 31;
    int wm = warp & 1, wn = warp >> 1;      // wm: 32-row halves, wn: 16-col quarters
    int q = lane >> 2, t = lane & 3;

    int aRow = tid >> 2;
    int k4   = (tid & 3) << 2;
    const float* Aptr = A + (size_t)(m0 + aRow) * K + k4;
    const float* Wptr = W + (size_t)(n0 + aRow) * K + k4;

    float acc[2][2][4];
    #pragma unroll
    for (int mt = 0; mt < 2; mt++)
        #pragma unroll
        for (int nt = 0; nt < 2; nt++)
            #pragma unroll
            for (int i = 0; i < 4; i++) acc[mt][nt][i] = 0.f;

    for (int kt = 0; kt < K; kt += 16) {
        float4 av = *(const float4*)(Aptr + kt);
        float4 bv = *(const float4*)(Wptr + kt);
        float a4[4] = {av.x, av.y, av.z, av.w};
        float b4[4] = {bv.x, bv.y, bv.z, bv.w};
        #pragma unroll
        for (int i = 0; i < 4; i++) {
            uint32_t h = f2tf32(a4[i]);
            Ah[aRow][k4 + i] = h;
            Al[aRow][k4 + i] = f2tf32(a4[i] - __uint_as_float(h));
            h = f2tf32(b4[i]);
            Bh[aRow][k4 + i] = h;
            Bl[aRow][k4 + i] = f2tf32(b4[i] - __uint_as_float(h));
        }
        __syncthreads();
        #pragma unroll
        for (int ks = 0; ks < 2; ks++) {
            int kc = ks * 8 + t;
            uint32_t ah[2][4], al[2][4], bh[2][2], bl[2][2];
            #pragma unroll
            for (int mt = 0; mt < 2; mt++) {
                int r = wm * 32 + mt * 16 + q;
                ah[mt][0] = Ah[r][kc];   ah[mt][1] = Ah[r + 8][kc];
                ah[mt][2] = Ah[r][kc+4]; ah[mt][3] = Ah[r + 8][kc+4];
                al[mt][0] = Al[r][kc];   al[mt][1] = Al[r + 8][kc];
                al[mt][2] = Al[r][kc+4]; al[mt][3] = Al[r + 8][kc+4];
            }
            #pragma unroll
            for (int nt = 0; nt < 2; nt++) {
                int n = wn * 16 + nt * 8 + q;
                bh[nt][0] = Bh[n][kc]; bh[nt][1] = Bh[n][kc + 4];
                bl[nt][0] = Bl[n][kc]; bl[nt][1] = Bl[n][kc + 4];
            }
            #pragma unroll
            for (int mt = 0; mt < 2; mt++)
                #pragma unroll
                for (int nt = 0; nt < 2; nt++) {
                    mma_tf32(acc[mt][nt], al[mt], bh[nt]);
                    mma_tf32(acc[mt][nt], ah[mt], bl[nt]);
                    mma_tf32(acc[mt][nt], ah[mt], bh[nt]);
                }
        }
        __syncthreads();
    }

    #pragma unroll
    for (int mt = 0; mt < 2; mt++) {
        #pragma unroll
        for (int nt = 0; nt < 2; nt++) {
            int gm0 = m0 + wm * 32 + mt * 16 + q;
            int gn  = n0 + wn * 16 + nt * 8 + 2 * t;
            float b0 = bias ? bias[gn]     : 0.f;
            float b1 = bias ? bias[gn + 1] : 0.f;
            #pragma unroll
            for (int half = 0; half < 2; half++) {
                int gm = gm0 + half * 8;
                float c0 = acc[mt][nt][half * 2 + 0] + b0;
                float c1 = acc[mt][nt][half * 2 + 1] + b1;
                if (act == 1) { c0 = gelu_exact(c0); c1 = gelu_exact(c1); }
                size_t idx = (size_t)gm * N + gn;
                if (res) { c0 += res[idx]; c1 += res[idx + 1]; }
                *(float2*)(C + idx) = make_float2(c0, c1);
            }
        }
    }
}

static inline void gemm_x3(const float* A, const float* W, const float* bias,
                           const float* res, float* C, int M, int N, int K, int act) {
    dim3 grid(N / 64, M / 64);
    gemm_tf32x3_kernel<<<grid, 256>>>(A, W, bias, res, C, M, N, K, act);
}

// ---------------------------------------------------------------------------
// LayerNorm: warp per row, single pass, float4. cols % 4 == 0, rows % 8 == 0.
// ---------------------------------------------------------------------------
__global__ __launch_bounds__(256)
void ln_warp_kernel(const float* __restrict__ x, const float* __restrict__ g,
                    const float* __restrict__ b, float* __restrict__ y, int cols) {
    int row = blockIdx.x * 8 + (threadIdx.x >> 5);
    int lane = threadIdx.x & 31;
    int cols4 = cols >> 2;
    const float4* xr = (const float4*)(x + (size_t)row * cols);
    float s = 0.f, sq = 0.f;
    for (int c = lane; c < cols4; c += 32) {
        float4 v = xr[c];
        s  += (v.x + v.y) + (v.z + v.w);
        sq += v.x * v.x + v.y * v.y + v.z * v.z + v.w * v.w;
    }
    #pragma unroll
    for (int o = 16; o; o >>= 1) {
        s  += __shfl_xor_sync(0xffffffffu, s, o);
        sq += __shfl_xor_sync(0xffffffffu, sq, o);
    }
    float mean = s / (float)cols;
    float var = sq / (float)cols - mean * mean;
    float inv = rsqrtf(fmaxf(var, 0.f) + 1e-5f);
    float4* yr = (float4*)(y + (size_t)row * cols);
    const float4* g4 = (const float4*)g;
    const float4* b4 = (const float4*)b;
    for (int c = lane; c < cols4; c += 32) {
        float4 v = xr[c], gg = g4[c], bb = b4[c], o;
        o.x = (v.x - mean) * inv * gg.x + bb.x;
        o.y = (v.y - mean) * inv * gg.y + bb.y;
        o.z = (v.z - mean) * inv * gg.z + bb.z;
        o.w = (v.w - mean) * inv * gg.w + bb.w;
        yr[c] = o;
    }
}

// ---------------------------------------------------------------------------
// RoPE apply
// ---------------------------------------------------------------------------
__global__ void rope_apply_kernel(float* __restrict__ qkv) {
    int row = blockIdx.x;
    int n = row & 255;
    int g = threadIdx.x >> 5;
    int t = threadIdx.x & 31;
    int s = g >> 2, h = g & 3;
    __shared__ float sh[8][64];
    float* p = qkv + (size_t)row * 768 + s * 256 + h * 64;
    sh[g][t]      = p[t];
    sh[g][t + 32] = p[t + 32];
    __syncwarp();
    float c1 = g_cosT[n * 64 + t],      s1 = g_sinT[n * 64 + t];
    float c2 = g_cosT[n * 64 + t + 32], s2 = g_sinT[n * 64 + t + 32];
    float o1 = sh[g][t]      * c1 - sh[g][2 * t + 1] * s1;
    float o2 = sh[g][t + 32] * c2 + sh[g][2 * t]     * s2;
    p[t]      = o1;
    p[t + 32] = o2;
}

// ---------------------------------------------------------------------------
// Attention: thread per query (128 q/block), float4 everywhere,
// K/V rows broadcast from smem (stride 68 -> float4-aligned, conflict-free).
// grid (HEADS, B, 2), block 128.
// ---------------------------------------------------------------------------
__global__ __launch_bounds__(128)
void attn_kernel(const float* __restrict__ qkv, float* __restrict__ ao) {
    int h = blockIdx.x, b = blockIdx.y;
    int n = blockIdx.z * 128 + threadIdx.x;
    const float* base = qkv + (size_t)b * 256 * 768;

    float4 q4[16];
    {
        const float4* qp = (const float4*)(base + (size_t)n * 768 + h * 64);
        #pragma unroll
        for (int i = 0; i < 16; i++) q4[i] = qp[i];
    }
    float m = -1e30f, l = 0.f;
    float4 a4[16];
    #pragma unroll
    for (int i = 0; i < 16; i++) a4[i] = make_float4(0.f, 0.f, 0.f, 0.f);

    __shared__ float Ks[64][68];
    __shared__ float Vs[64][68];

    for (int t0 = 0; t0 < 256; t0 += 64) {
        for (int idx = threadIdx.x; idx < 64 * 16; idx += 128) {
            int kr = idx >> 4, c4 = idx & 15;
            const float4* rp = (const float4*)(base + (size_t)(t0 + kr) * 768 + h * 64);
            ((float4*)Ks[kr])[c4] = rp[64 + c4];    // K at +256 floats
            ((float4*)Vs[kr])[c4] = rp[128 + c4];   // V at +512 floats
        }
        __syncthreads();
        for (int j = 0; j < 64; j++) {
            const float4* kr4 = (const float4*)Ks[j];
            float s0 = 0.f, s1 = 0.f, s2 = 0.f, s3 = 0.f;
            #pragma unroll
            for (int i = 0; i < 16; i++) {
                float4 k = kr4[i];
                s0 += q4[i].x * k.x; s1 += q4[i].y * k.y;
                s2 += q4[i].z * k.z; s3 += q4[i].w * k.w;
            }
            float s = ((s0 + s1) + (s2 + s3)) * 0.125f;
            const float4* vr4 = (const float4*)Vs[j];
            if (s > m) {
                float corr = __expf(m - s);
                l = l * corr + 1.f;
                #pragma unroll
                for (int i = 0; i < 16; i++) {
                    float4 v = vr4[i];
                    a4[i].x = a4[i].x * corr + v.x;
                    a4[i].y = a4[i].y * corr + v.y;
                    a4[i].z = a4[i].z * corr + v.z;
                    a4[i].w = a4[i].w * corr + v.w;
                }
                m = s;
            } else {
                float p = __expf(s - m);
                l += p;
                #pragma unroll
                for (int i = 0; i < 16; i++) {
                    float4 v = vr4[i];
                    a4[i].x += p * v.x; a4[i].y += p * v.y;
                    a4[i].z += p * v.z; a4[i].w += p * v.w;
                }
            }
        }
        __syncthreads();
    }
    float inv = 1.f / l;
    float4* op = (float4*)(ao + ((size_t)b * 256 + n) * 256 + h * 64);
    #pragma unroll
    for (int i = 0; i < 16; i++) {
        float4 v = a4[i];
        op[i] = make_float4(v.x * inv, v.y * inv, v.z * inv, v.w * inv);
    }
}

// ---------------------------------------------------------------------------
// Slot attention pieces
// ---------------------------------------------------------------------------
__global__ void zero_slots_kernel(float* __restrict__ slots) {
    int idx = blockIdx.x * blockDim.x + threadIdx.x;
    if (idx < Bc * NSc * FDc) slots[idx] = 0.f;
}

// logits + softmax over slots + column-sum (denominator), fused. grid(B).
__global__ __launch_bounds__(256)
void slot_logits_kernel(const float* __restrict__ kin,
                        const float* __restrict__ qs,
                        float* __restrict__ sattn,
                        float* __restrict__ denom) {
    int b = blockIdx.x;
    __shared__ float q[8][320];
    __shared__ float sat[256][8];
    for (int i = threadIdx.x; i < 8 * 320; i += 256)
        q[i / 320][i % 320] = qs[b * 8 * 320 + i];
    __syncthreads();
    int warp = threadIdx.x >> 5, lane = threadIdx.x & 31;
    for (int n = warp; n < 256; n += 8) {
        const float* kr = kin + ((size_t)b * 256 + n) * 320;
        float part[8] = {};
        for (int f = lane; f < 320; f += 32) {
            float kv = kr[f];
            #pragma unroll
            for (int s = 0; s < 8; s++) part[s] += kv * q[s][f];
        }
        #pragma unroll
        for (int s = 0; s < 8; s++)
            #pragma unroll
            for (int o = 16; o; o >>= 1)
                part[s] += __shfl_xor_sync(0xffffffffu, part[s], o);
        if (lane == 0) {
            const float scale = 0.05590169943749474f;  // 1/sqrt(320)
            float mx = -1e30f;
            #pragma unroll
            for (int s = 0; s < 8; s++) { part[s] *= scale; mx = fmaxf(mx, part[s]); }
            float e[8], sum = 0.f;
            #pragma unroll
            for (int s = 0; s < 8; s++) { e[s] = expf(part[s] - mx); sum += e[s]; }
            float inv = 1.f / sum;
            #pragma unroll
            for (int s = 0; s < 8; s++) sat[n][s] = e[s] * inv;
        }
    }
    __syncthreads();
    // denominator: warp s sums column s
    {
        float d = 0.f;
        for (int n = lane; n < 256; n += 32) d += sat[n][warp] + 1e-8f;
        #pragma unroll
        for (int o = 16; o; o >>= 1) d += __shfl_xor_sync(0xffffffffu, d, o);
        if (lane == 0) denom[b * 8 + warp] = d;
    }
    // write attention to gmem
    for (int i = threadIdx.x; i < 2048; i += 256)
        sattn[(size_t)b * 2048 + i] = sat[i >> 3][i & 7];
}

// updates[b,s,f] = sum_n an[b,n,s]*vin[b,n,f]; vin read exactly once.
__global__ __launch_bounds__(320)
void updates_kernel(const float* __restrict__ sattn,
                    const float* __restrict__ denom,
                    const float* __restrict__ vin,
                    float* __restrict__ upd) {
    int b = blockIdx.x;
    int f = threadIdx.x;
    __shared__ float an[256][8];
    __shared__ float inv[8];
    for (int i = threadIdx.x; i < 2048; i += 320)
        an[i >> 3][i & 7] = sattn[(size_t)b * 2048 + i] + 1e-8f;
    if (threadIdx.x < 8) inv[threadIdx.x] = 1.f / denom[b * 8 + threadIdx.x];
    __syncthreads();
    float acc[8] = {};
    const float* vp = vin + (size_t)b * 256 * 320 + f;
    for (int n = 0; n < 256; n++) {
        float v = vp[(size_t)n * 320];
        #pragma unroll
        for (int s = 0; s < 8; s++) acc[s] += an[n][s] * v;
    }
    #pragma unroll
    for (int s = 0; s < 8; s++)
        upd[((size_t)b * 8 + s) * 320 + f] = acc[s] * inv[s];
}

// GRU gate combine + nm-LayerNorm fused. Warp per row (512 rows), grid 64.
__global__ __launch_bounds__(256)
void gru_ln_kernel(const float* __restrict__ gi, const float* __restrict__ gh,
                   float* __restrict__ slots,
                   const float* __restrict__ nm_g, const float* __restrict__ nm_b,
                   float* __restrict__ sln) {
    int row = blockIdx.x * 8 + (threadIdx.x >> 5);
    int lane = threadIdx.x & 31;
    const float* gir = gi + (size_t)row * 960;
    const float* ghr = gh + (size_t)row * 960;
    float* sr = slots + (size_t)row * 320;
    float news[10];
    float s = 0.f, sq = 0.f;
    #pragma unroll
    for (int i = 0; i < 10; i++) {
        int f = lane + 32 * i;
        float ir = gir[f], iz = gir[320 + f], in_ = gir[640 + f];
        float hr = ghr[f], hz = ghr[320 + f], hn  = ghr[640 + f];
        float r = 1.f / (1.f + __expf(-(ir + hr)));
        float z = 1.f / (1.f + __expf(-(iz + hz)));
        float nn = tanhf(in_ + r * hn);
        float v = (1.f - z) * nn + z * sr[f];
        news[i] = v;
        s += v; sq += v * v;
    }
    #pragma unroll
    for (int o = 16; o; o >>= 1) {
        s  += __shfl_xor_sync(0xffffffffu, s, o);
        sq += __shfl_xor_sync(0xffffffffu, sq, o);
    }
    float mean = s / 320.f;
    float var = sq / 320.f - mean * mean;
    float inv = rsqrtf(fmaxf(var, 0.f) + 1e-5f);
    float* lr = sln + (size_t)row * 320;
    #pragma unroll
    for (int i = 0; i < 10; i++) {
        int f = lane + 32 * i;
        sr[f] = news[i];
        lr[f] = (news[i] - mean) * inv * nm_g[f] + nm_b[f];
    }
}

__global__ void output_kernel(const float* __restrict__ slots,
                              const float* __restrict__ sattn,
                              float* __restrict__ out) {
    int idx = blockIdx.x * blockDim.x + threadIdx.x;
    const int SLOTS = Bc * NSc * FDc;      // 163840
    const int MASKS = Bc * NSc * Nc;       // 131072
    if (idx < SLOTS) {
        out[idx] = slots[idx];
    } else if (idx < SLOTS + MASKS) {
        int k = idx - SLOTS;
        int b = k / (NSc * Nc);
        int r = k % (NSc * Nc);
        int s = r / Nc;
        int n = r % Nc;
        out[idx] = sattn[((size_t)b * Nc + n) * NSc + s];
    }
}

// ---------------------------------------------------------------------------
// Host launcher
// ---------------------------------------------------------------------------
template <typename T>
static float* sym_addr(T& sym) {
    void* p = nullptr;
    cudaGetSymbolAddress(&p, sym);
    return (float*)p;
}

extern "C" void kernel_launch(void* const* d_in, const int* in_sizes, int n_in,
                              void* d_out, int out_size) {
    const float* state    = (const float*)d_in[0];
    const float* conv_w   = (const float*)d_in[1];
    const float* conv_b   = (const float*)d_in[2];
    const float* mlp_ln_g = (const float*)d_in[3];
    const float* mlp_ln_b = (const float*)d_in[4];
    const float* mlp_w1   = (const float*)d_in[5];
    const float* mlp_b1   = (const float*)d_in[6];
    const float* mlp_w2   = (const float*)d_in[7];
    const float* mlp_b2   = (const float*)d_in[8];
    const float* qkv_w    = (const float*)d_in[9];
    const float* qkv_b    = (const float*)d_in[10];
    const float* proj_w   = (const float*)d_in[11];
    const float* proj_b   = (const float*)d_in[12];
    const float* ni_g     = (const float*)d_in[13];
    const float* ni_b     = (const float*)d_in[14];
    const float* ns_g     = (const float*)d_in[15];
    const float* ns_b     = (const float*)d_in[16];
    const float* nm_g     = (const float*)d_in[17];
    const float* nm_b     = (const float*)d_in[18];
    const float* q_w      = (const float*)d_in[19];
    const float* k_w      = (const float*)d_in[20];
    const float* v_w      = (const float*)d_in[21];
    const float* gru_wih  = (const float*)d_in[22];
    const float* gru_whh  = (const float*)d_in[23];
    const float* gru_bih  = (const float*)d_in[24];
    const float* gru_bhh  = (const float*)d_in[25];
    const float* smlp_w1  = (const float*)d_in[26];
    const float* smlp_b1  = (const float*)d_in[27];
    const float* smlp_w2  = (const float*)d_in[28];
    const float* smlp_b2  = (const float*)d_in[29];
    float* out = (float*)d_out;

    float* P     = sym_addr(g_P);
    float* x0    = sym_addr(g_x0);
    float* lnb   = sym_addr(g_ln);
    float* h1    = sym_addr(g_h1);
    float* x2    = sym_addr(g_x2);
    float* ao    = sym_addr(g_ao);
    float* x3    = sym_addr(g_x3);
    float* kin   = sym_addr(g_kin);
    float* vin   = sym_addr(g_vin);
    float* slots = sym_addr(g_slots);
    float* sln   = sym_addr(g_sln);
    float* qs    = sym_addr(g_qs);
    float* sattn = sym_addr(g_sattn);
    float* denom = sym_addr(g_denom);
    float* upd   = sym_addr(g_upd);
    float* gi    = sym_addr(g_gi);
    float* gh    = sym_addr(g_gh);
    float* m1    = sym_addr(g_m1);

    // 1. RoPE tables + patch matrix
    rope_init_kernel<<<Nc, HDc>>>();
    patch_kernel<<<TOK, 64>>>(state, P);

    // 2. Patch conv as GEMM (tensor cores)
    gemm_tf32(P, conv_w, conv_b, nullptr, x0, TOK, 256, 768, 0);

    // 3. Token MLP
    ln_warp_kernel<<<TOK / 8, 256>>>(x0, mlp_ln_g, mlp_ln_b, lnb, 256);
    gemm_tf32(lnb, mlp_w1, mlp_b1, nullptr, h1, TOK, 512, 256, 1);
    gemm_tf32(h1, mlp_w2, mlp_b2, nullptr, x2, TOK, 256, 512, 0);

    // 4. QKV + RoPE + attention + proj (residual with x2)
    gemm_tf32(x2, qkv_w, qkv_b, nullptr, P, TOK, 768, 256, 0);
    rope_apply_kernel<<<TOK, 256>>>(P);
    attn_kernel<<<dim3(HEADSc, Bc, 2), 128>>>(P, ao);
    gemm_tf32(ao, proj_w, proj_b, x2, x3, TOK, 256, 256, 0);

    // 5. Norm + k/v projections
    ln_warp_kernel<<<TOK / 8, 256>>>(x3, ni_g, ni_b, lnb, 256);
    gemm_tf32(lnb, k_w, nullptr, nullptr, kin, TOK, 320, 256, 0);
    gemm_tf32(lnb, v_w, nullptr, nullptr, vin, TOK, 320, 256, 0);

    // 6. Slot attention, 3 iterations (3xTF32 precision)
    zero_slots_kernel<<<(Bc * NSc * FDc + 255) / 256, 256>>>(slots);
    for (int it = 0; it < ITc; it++) {
        ln_warp_kernel<<<Bc * NSc / 8, 256>>>(slots, ns_g, ns_b, sln, 320);
        gemm_x3(sln, q_w, nullptr, nullptr, qs, Bc * NSc, 320, 320, 0);
        slot_logits_kernel<<<Bc, 256>>>(kin, qs, sattn, denom);
        updates_kernel<<<Bc, 320>>>(sattn, denom, vin, upd);
        gemm_x3(upd,   gru_wih, gru_bih, nullptr, gi, Bc * NSc, 960, 320, 0);
        gemm_x3(slots, gru_whh, gru_bhh, nullptr, gh, Bc * NSc, 960, 320, 0);
        gru_ln_kernel<<<Bc * NSc / 8, 256>>>(gi, gh, slots, nm_g, nm_b, sln);
        gemm_x3(sln, smlp_w1, smlp_b1, nullptr, m1, Bc * NSc, 640, 320, 1);
        gemm_x3(m1, smlp_w2, smlp_b2, slots, slots, Bc * NSc, 320, 640, 0);
    }

    // 7. Pack outputs
    int total = Bc * NSc * FDc + Bc * NSc * Nc;
    output_kernel<<<(total + 255) / 256, 256>>>(slots, sattn, out);
}

// round 4
// speedup vs baseline: 1.8337x; 1.2502x over previous
#include <cuda_runtime.h>
#include <math.h>
#include <stdint.h>

// ---------------------------------------------------------------------------
// Problem constants
// ---------------------------------------------------------------------------
constexpr int Bc = 64, Hc = 128, Wc = 128, PSc = 8, Gc = 16, Ec = 256;
constexpr int NSc = 8, ITc = 3, Vc = 10, FDc = 320, HEADSc = 4, HDc = 64;
constexpr int Nc = Gc * Gc;          // 256 tokens per image
constexpr int TOK = Bc * Nc;         // 16384 rows

// ---------------------------------------------------------------------------
// Device scratch
// ---------------------------------------------------------------------------
__device__ float g_P   [TOK * 768];        // im2col patches; reused for QKV
__device__ float g_x0  [TOK * Ec];
__device__ float g_ln  [TOK * Ec];
__device__ float g_h1  [TOK * 512];
__device__ float g_x2  [TOK * Ec];
__device__ float g_ao  [TOK * Ec];
__device__ float g_x3  [TOK * Ec];
__device__ float g_kin [TOK * FDc];
__device__ float g_vin [TOK * FDc];
__device__ float g_cosT[Nc * HDc];
__device__ float g_sinT[Nc * HDc];
__device__ float g_slots[Bc * NSc * FDc];
__device__ float g_sln  [Bc * NSc * FDc];
__device__ float g_qs   [Bc * NSc * FDc];
__device__ float g_sattn[Bc * Nc * NSc];
__device__ float g_denom[Bc * NSc];
__device__ float g_upd  [Bc * NSc * FDc];
__device__ float g_gi   [Bc * NSc * 3 * FDc];
__device__ float g_gh   [Bc * NSc * 3 * FDc];
__device__ float g_m1   [Bc * NSc * 2 * FDc];

// ---------------------------------------------------------------------------
// Helpers
// ---------------------------------------------------------------------------
__device__ __forceinline__ float gelu_exact(float x) {
    return 0.5f * x * (1.0f + erff(x * 0.70710678118654752f));
}

__device__ __forceinline__ uint32_t f2tf32(float x) {
    uint32_t r;
    asm("cvt.rna.tf32.f32 %0, %1;" : "=r"(r) : "f"(x));
    return r;
}

__device__ __forceinline__ void mma_tf32(float (&d)[4], const uint32_t (&a)[4],
                                         const uint32_t (&b)[2]) {
    asm volatile(
        "mma.sync.aligned.m16n8k8.row.col.f32.tf32.tf32.f32 "
        "{%0,%1,%2,%3}, {%4,%5,%6,%7}, {%8,%9}, {%0,%1,%2,%3};\n"
        : "+f"(d[0]), "+f"(d[1]), "+f"(d[2]), "+f"(d[3])
        : "r"(a[0]), "r"(a[1]), "r"(a[2]), "r"(a[3]), "r"(b[0]), "r"(b[1]));
}

// ---------------------------------------------------------------------------
// RoPE tables
// ---------------------------------------------------------------------------
__global__ void rope_init_kernel() {
    int n = blockIdx.x;          // 0..255
    int d = threadIdx.x;         // 0..63
    int gy = n >> 4, gx = n & 15;
    int pos = (d < 32) ? gy : gx;
    int dd  = (d < 32) ? d : d - 32;
    float val;
    if (dd < 16) {
        float inv = expf(-9.210340371976184f * (2.0f * dd) / 32.0f);
        val = sinf((float)pos * inv);
    } else {
        float inv = expf(-9.210340371976184f * (2.0f * (dd - 16)) / 32.0f);
        val = cosf((float)pos * inv);
    }
    g_cosT[n * 64 + d] = cosf(val);
    g_sinT[n * 64 + d] = sinf(val);
}

// ---------------------------------------------------------------------------
// Patch / im2col builder
// ---------------------------------------------------------------------------
__global__ void patch_kernel(const float* __restrict__ state, float* __restrict__ P) {
    int bn = blockIdx.x;
    int b = bn >> 8, n = bn & 255;
    int gy = n >> 4, gx = n & 15;
    int p = threadIdx.x;               // 0..63
    int py = p >> 3, px = p & 7;
    int y = gy * 8 + py, x = gx * 8 + px;
    const float* sb = state + (size_t)b * Hc * Wc;
    float* row = P + (size_t)bn * 768;
    for (int k = p; k < 768; k += 64) row[k] = 0.f;

    float v[3][3];
    #pragma unroll
    for (int di = 0; di < 3; di++) {
        int yy = min(max(y + di - 1, 0), Hc - 1);
        #pragma unroll
        for (int dj = 0; dj < 3; dj++) {
            int xx = min(max(x + dj - 1, 0), Wc - 1);
            v[di][dj] = sb[yy * Wc + xx];
        }
    }
    float sx = (v[0][2] + 2.f * v[1][2] + v[2][2]) - (v[0][0] + 2.f * v[1][0] + v[2][0]);
    float sy = (v[2][0] + 2.f * v[2][1] + v[2][2]) - (v[0][0] + 2.f * v[0][1] + v[0][2]);
    int id = (int)sb[y * Wc + x];
    __syncthreads();
    row[id * 64 + p]  = 1.f;
    row[640 + p]      = sx;
    row[704 + p]      = sy;
}

// ---------------------------------------------------------------------------
// TF32 tensor-core GEMM: BM=128, BN=128, BK=16, 256 threads (8 warps),
// warp tile m32 x n64. Supports split weight (Wa rows < nsplit, Wb rest)
// and split output (Ca cols < nsplit stride nsplit, Cb rest stride N-nsplit).
// For plain GEMMs pass nsplit=N, Wb=Cb=nullptr.
// ---------------------------------------------------------------------------
__global__ __launch_bounds__(256)
void gemm128_kernel(const float* __restrict__ A,
                    const float* __restrict__ Wa, const float* __restrict__ Wb,
                    int nsplit,
                    const float* __restrict__ bias, const float* __restrict__ res,
                    float* __restrict__ Ca, float* __restrict__ Cb,
                    int M, int N, int K, int act) {
    __shared__ uint32_t As[2][128][20];
    __shared__ uint32_t Bs[2][128][20];

    int tid = threadIdx.x;
    int m0 = blockIdx.y * 128, n0 = blockIdx.x * 128;
    int warp = tid >> 5, lane = tid & 31;
    int wm = warp & 3, wn = warp >> 2;   // wm: 4 x 32 rows, wn: 2 x 64 cols
    int q = lane >> 2, t = lane & 3;

    int r  = tid >> 2;                   // 0..63
    int k4 = (tid & 3) << 2;

    const float* Ap0 = A + (size_t)(m0 + r) * K + k4;
    const float* Ap1 = Ap0 + (size_t)64 * K;
    int nr0 = n0 + r, nr1 = n0 + r + 64;
    const float* Wp0 = (nr0 < nsplit) ? Wa + (size_t)nr0 * K + k4
                                      : Wb + (size_t)(nr0 - nsplit) * K + k4;
    const float* Wp1 = (nr1 < nsplit) ? Wa + (size_t)nr1 * K + k4
                                      : Wb + (size_t)(nr1 - nsplit) * K + k4;

    float acc[2][8][4];
    #pragma unroll
    for (int mt = 0; mt < 2; mt++)
        #pragma unroll
        for (int nt = 0; nt < 8; nt++)
            #pragma unroll
            for (int i = 0; i < 4; i++) acc[mt][nt][i] = 0.f;

    int ntiles = K >> 4;
    float4 a0 = *(const float4*)Ap0;
    float4 a1 = *(const float4*)Ap1;
    float4 b0 = *(const float4*)Wp0;
    float4 b1 = *(const float4*)Wp1;
    int buf = 0;
    As[0][r][k4+0] = f2tf32(a0.x); As[0][r][k4+1] = f2tf32(a0.y);
    As[0][r][k4+2] = f2tf32(a0.z); As[0][r][k4+3] = f2tf32(a0.w);
    As[0][r+64][k4+0] = f2tf32(a1.x); As[0][r+64][k4+1] = f2tf32(a1.y);
    As[0][r+64][k4+2] = f2tf32(a1.z); As[0][r+64][k4+3] = f2tf32(a1.w);
    Bs[0][r][k4+0] = f2tf32(b0.x); Bs[0][r][k4+1] = f2tf32(b0.y);
    Bs[0][r][k4+2] = f2tf32(b0.z); Bs[0][r][k4+3] = f2tf32(b0.w);
    Bs[0][r+64][k4+0] = f2tf32(b1.x); Bs[0][r+64][k4+1] = f2tf32(b1.y);
    Bs[0][r+64][k4+2] = f2tf32(b1.z); Bs[0][r+64][k4+3] = f2tf32(b1.w);
    __syncthreads();

    for (int kt = 0; kt < ntiles; kt++) {
        bool more = (kt + 1 < ntiles);
        if (more) {
            a0 = *(const float4*)(Ap0 + (kt + 1) * 16);
            a1 = *(const float4*)(Ap1 + (kt + 1) * 16);
            b0 = *(const float4*)(Wp0 + (kt + 1) * 16);
            b1 = *(const float4*)(Wp1 + (kt + 1) * 16);
        }
        #pragma unroll
        for (int ks = 0; ks < 2; ks++) {
            int kc = ks * 8 + t;
            uint32_t af[2][4], bf[8][2];
            #pragma unroll
            for (int mt = 0; mt < 2; mt++) {
                int rr = wm * 32 + mt * 16 + q;
                af[mt][0] = As[buf][rr][kc];
                af[mt][1] = As[buf][rr + 8][kc];
                af[mt][2] = As[buf][rr][kc + 4];
                af[mt][3] = As[buf][rr + 8][kc + 4];
            }
            #pragma unroll
            for (int nt = 0; nt < 8; nt++) {
                int nn = wn * 64 + nt * 8 + q;
                bf[nt][0] = Bs[buf][nn][kc];
                bf[nt][1] = Bs[buf][nn][kc + 4];
            }
            #pragma unroll
            for (int mt = 0; mt < 2; mt++)
                #pragma unroll
                for (int nt = 0; nt < 8; nt++)
                    mma_tf32(acc[mt][nt], af[mt], bf[nt]);
        }
        __syncthreads();
        if (more) {
            buf ^= 1;
            As[buf][r][k4+0] = f2tf32(a0.x); As[buf][r][k4+1] = f2tf32(a0.y);
            As[buf][r][k4+2] = f2tf32(a0.z); As[buf][r][k4+3] = f2tf32(a0.w);
            As[buf][r+64][k4+0] = f2tf32(a1.x); As[buf][r+64][k4+1] = f2tf32(a1.y);
            As[buf][r+64][k4+2] = f2tf32(a1.z); As[buf][r+64][k4+3] = f2tf32(a1.w);
            Bs[buf][r][k4+0] = f2tf32(b0.x); Bs[buf][r][k4+1] = f2tf32(b0.y);
            Bs[buf][r][k4+2] = f2tf32(b0.z); Bs[buf][r][k4+3] = f2tf32(b0.w);
            Bs[buf][r+64][k4+0] = f2tf32(b1.x); Bs[buf][r+64][k4+1] = f2tf32(b1.y);
            Bs[buf][r+64][k4+2] = f2tf32(b1.z); Bs[buf][r+64][k4+3] = f2tf32(b1.w);
            __syncthreads();
        }
    }

    int strideB = N - nsplit;
    #pragma unroll
    for (int mt = 0; mt < 2; mt++) {
        #pragma unroll
        for (int nt = 0; nt < 8; nt++) {
            int gm0 = m0 + wm * 32 + mt * 16 + q;
            int gn  = n0 + wn * 64 + nt * 8 + 2 * t;
            float bb0 = bias ? bias[gn]     : 0.f;
            float bb1 = bias ? bias[gn + 1] : 0.f;
            #pragma unroll
            for (int half = 0; half < 2; half++) {
                int gm = gm0 + half * 8;
                float c0 = acc[mt][nt][half * 2 + 0] + bb0;
                float c1 = acc[mt][nt][half * 2 + 1] + bb1;
                if (act == 1) { c0 = gelu_exact(c0); c1 = gelu_exact(c1); }
                if (gn < nsplit) {
                    size_t idx = (size_t)gm * nsplit + gn;
                    if (res) { c0 += res[idx]; c1 += res[idx + 1]; }
                    *(float2*)(Ca + idx) = make_float2(c0, c1);
                } else {
                    size_t idx = (size_t)gm * strideB + (gn - nsplit);
                    *(float2*)(Cb + idx) = make_float2(c0, c1);
                }
            }
        }
    }
}

static inline void gemm128(const float* A, const float* W, const float* bias,
                           const float* res, float* C, int M, int N, int K, int act) {
    dim3 grid(N / 128, M / 128);
    gemm128_kernel<<<grid, 256>>>(A, W, nullptr, N, bias, res, C, nullptr, M, N, K, act);
}

// ---------------------------------------------------------------------------
// 3xTF32 GEMM (near-fp32 accuracy) for slot-loop GEMMs. BM=BN=64, BK=16.
// ---------------------------------------------------------------------------
__global__ __launch_bounds__(256)
void gemm_tf32x3_kernel(const float* __restrict__ A, const float* __restrict__ W,
                        const float* __restrict__ bias, const float* __restrict__ res,
                        float* __restrict__ C, int M, int N, int K, int act) {
    __shared__ uint32_t Ah[64][20], Al[64][20], Bh[64][20], Bl[64][20];

    int tid = threadIdx.x;
    int m0 = blockIdx.y * 64, n0 = blockIdx.x * 64;
    int warp = tid >> 5, lane = tid & 31;
    int wm = warp & 1, wn = warp >> 1;
    int q = lane >> 2, t = lane & 3;

    int aRow = tid >> 2;
    int k4   = (tid & 3) << 2;
    const float* Aptr = A + (size_t)(m0 + aRow) * K + k4;
    const float* Wptr = W + (size_t)(n0 + aRow) * K + k4;

    float acc[2][2][4];
    #pragma unroll
    for (int mt = 0; mt < 2; mt++)
        #pragma unroll
        for (int nt = 0; nt < 2; nt++)
            #pragma unroll
            for (int i = 0; i < 4; i++) acc[mt][nt][i] = 0.f;

    for (int kt = 0; kt < K; kt += 16) {
        float4 av = *(const float4*)(Aptr + kt);
        float4 bv = *(const float4*)(Wptr + kt);
        float a4[4] = {av.x, av.y, av.z, av.w};
        float b4[4] = {bv.x, bv.y, bv.z, bv.w};
        #pragma unroll
        for (int i = 0; i < 4; i++) {
            uint32_t h = f2tf32(a4[i]);
            Ah[aRow][k4 + i] = h;
            Al[aRow][k4 + i] = f2tf32(a4[i] - __uint_as_float(h));
            h = f2tf32(b4[i]);
            Bh[aRow][k4 + i] = h;
            Bl[aRow][k4 + i] = f2tf32(b4[i] - __uint_as_float(h));
        }
        __syncthreads();
        #pragma unroll
        for (int ks = 0; ks < 2; ks++) {
            int kc = ks * 8 + t;
            uint32_t ah[2][4], al[2][4], bh[2][2], bl[2][2];
            #pragma unroll
            for (int mt = 0; mt < 2; mt++) {
                int rr = wm * 32 + mt * 16 + q;
                ah[mt][0] = Ah[rr][kc];   ah[mt][1] = Ah[rr + 8][kc];
                ah[mt][2] = Ah[rr][kc+4]; ah[mt][3] = Ah[rr + 8][kc+4];
                al[mt][0] = Al[rr][kc];   al[mt][1] = Al[rr + 8][kc];
                al[mt][2] = Al[rr][kc+4]; al[mt][3] = Al[rr + 8][kc+4];
            }
            #pragma unroll
            for (int nt = 0; nt < 2; nt++) {
                int nn = wn * 16 + nt * 8 + q;
                bh[nt][0] = Bh[nn][kc]; bh[nt][1] = Bh[nn][kc + 4];
                bl[nt][0] = Bl[nn][kc]; bl[nt][1] = Bl[nn][kc + 4];
            }
            #pragma unroll
            for (int mt = 0; mt < 2; mt++)
                #pragma unroll
                for (int nt = 0; nt < 2; nt++) {
                    mma_tf32(acc[mt][nt], al[mt], bh[nt]);
                    mma_tf32(acc[mt][nt], ah[mt], bl[nt]);
                    mma_tf32(acc[mt][nt], ah[mt], bh[nt]);
                }
        }
        __syncthreads();
    }

    #pragma unroll
    for (int mt = 0; mt < 2; mt++) {
        #pragma unroll
        for (int nt = 0; nt < 2; nt++) {
            int gm0 = m0 + wm * 32 + mt * 16 + q;
            int gn  = n0 + wn * 16 + nt * 8 + 2 * t;
            float b0 = bias ? bias[gn]     : 0.f;
            float b1 = bias ? bias[gn + 1] : 0.f;
            #pragma unroll
            for (int half = 0; half < 2; half++) {
                int gm = gm0 + half * 8;
                float c0 = acc[mt][nt][half * 2 + 0] + b0;
                float c1 = acc[mt][nt][half * 2 + 1] + b1;
                if (act == 1) { c0 = gelu_exact(c0); c1 = gelu_exact(c1); }
                size_t idx = (size_t)gm * N + gn;
                if (res) { c0 += res[idx]; c1 += res[idx + 1]; }
                *(float2*)(C + idx) = make_float2(c0, c1);
            }
        }
    }
}

static inline void gemm_x3(const float* A, const float* W, const float* bias,
                           const float* res, float* C, int M, int N, int K, int act) {
    dim3 grid(N / 64, M / 64);
    gemm_tf32x3_kernel<<<grid, 256>>>(A, W, bias, res, C, M, N, K, act);
}

// ---------------------------------------------------------------------------
// LayerNorm: warp per row, single pass, float4.
// ---------------------------------------------------------------------------
__global__ __launch_bounds__(256)
void ln_warp_kernel(const float* __restrict__ x, const float* __restrict__ g,
                    const float* __restrict__ b, float* __restrict__ y, int cols) {
    int row = blockIdx.x * 8 + (threadIdx.x >> 5);
    int lane = threadIdx.x & 31;
    int cols4 = cols >> 2;
    const float4* xr = (const float4*)(x + (size_t)row * cols);
    float s = 0.f, sq = 0.f;
    for (int c = lane; c < cols4; c += 32) {
        float4 v = xr[c];
        s  += (v.x + v.y) + (v.z + v.w);
        sq += v.x * v.x + v.y * v.y + v.z * v.z + v.w * v.w;
    }
    #pragma unroll
    for (int o = 16; o; o >>= 1) {
        s  += __shfl_xor_sync(0xffffffffu, s, o);
        sq += __shfl_xor_sync(0xffffffffu, sq, o);
    }
    float mean = s / (float)cols;
    float var = sq / (float)cols - mean * mean;
    float inv = rsqrtf(fmaxf(var, 0.f) + 1e-5f);
    float4* yr = (float4*)(y + (size_t)row * cols);
    const float4* g4 = (const float4*)g;
    const float4* b4 = (const float4*)b;
    for (int c = lane; c < cols4; c += 32) {
        float4 v = xr[c], gg = g4[c], bb = b4[c], o;
        o.x = (v.x - mean) * inv * gg.x + bb.x;
        o.y = (v.y - mean) * inv * gg.y + bb.y;
        o.z = (v.z - mean) * inv * gg.z + bb.z;
        o.w = (v.w - mean) * inv * gg.w + bb.w;
        yr[c] = o;
    }
}

// ---------------------------------------------------------------------------
// RoPE apply
// ---------------------------------------------------------------------------
__global__ void rope_apply_kernel(float* __restrict__ qkv) {
    int row = blockIdx.x;
    int n = row & 255;
    int g = threadIdx.x >> 5;
    int t = threadIdx.x & 31;
    int s = g >> 2, h = g & 3;
    __shared__ float sh[8][64];
    float* p = qkv + (size_t)row * 768 + s * 256 + h * 64;
    sh[g][t]      = p[t];
    sh[g][t + 32] = p[t + 32];
    __syncwarp();
    float c1 = g_cosT[n * 64 + t],      s1 = g_sinT[n * 64 + t];
    float c2 = g_cosT[n * 64 + t + 32], s2 = g_sinT[n * 64 + t + 32];
    float o1 = sh[g][t]      * c1 - sh[g][2 * t + 1] * s1;
    float o2 = sh[g][t + 32] * c2 + sh[g][2 * t]     * s2;
    p[t]      = o1;
    p[t + 32] = o2;
}

// ---------------------------------------------------------------------------
// Attention via tf32 MMA, flash-style. Block = 128 threads (4 warps),
// each block handles 64 queries for one (b,h). grid (4 qtiles, 4 h, 64 b).
// Dynamic smem: Qs/Ks/Vs/Ps, each 64 rows x stride 68 (u32 tf32 bits).
// ---------------------------------------------------------------------------
__global__ __launch_bounds__(128)
void attn_mma_kernel(const float* __restrict__ qkv, float* __restrict__ ao) {
    extern __shared__ uint32_t sm[];
    uint32_t (*Qs)[68] = (uint32_t(*)[68])(sm);
    uint32_t (*Ks)[68] = (uint32_t(*)[68])(sm + 64 * 68);
    uint32_t (*Vs)[68] = (uint32_t(*)[68])(sm + 2 * 64 * 68);
    uint32_t (*Ps)[68] = (uint32_t(*)[68])(sm + 3 * 64 * 68);

    int qt = blockIdx.x, h = blockIdx.y, b = blockIdx.z;
    int tid = threadIdx.x;
    int warp = tid >> 5, lane = tid & 31;
    int q = lane >> 2, t = lane & 3;

    const float* base = qkv + (size_t)b * 256 * 768 + h * 64;

    // Load Q tile (64 x 64), convert to tf32
    for (int idx = tid; idx < 64 * 16; idx += 128) {
        int r = idx >> 4, c4 = idx & 15;
        float4 v = *(const float4*)(base + (size_t)(qt * 64 + r) * 768 + c4 * 4);
        Qs[r][c4 * 4 + 0] = f2tf32(v.x);
        Qs[r][c4 * 4 + 1] = f2tf32(v.y);
        Qs[r][c4 * 4 + 2] = f2tf32(v.z);
        Qs[r][c4 * 4 + 3] = f2tf32(v.w);
    }
    __syncthreads();

    // Q fragments (warp owns rows warp*16 .. +15)
    uint32_t aq[8][4];
    #pragma unroll
    for (int kk = 0; kk < 8; kk++) {
        int rr = warp * 16 + q;
        aq[kk][0] = Qs[rr][8 * kk + t];
        aq[kk][1] = Qs[rr + 8][8 * kk + t];
        aq[kk][2] = Qs[rr][8 * kk + t + 4];
        aq[kk][3] = Qs[rr + 8][8 * kk + t + 4];
    }

    float m0 = -1e30f, m1 = -1e30f, l0 = 0.f, l1 = 0.f;
    float o[8][4];
    #pragma unroll
    for (int nt = 0; nt < 8; nt++)
        #pragma unroll
        for (int i = 0; i < 4; i++) o[nt][i] = 0.f;

    for (int kt = 0; kt < 4; kt++) {
        // Load K/V tiles (64 keys x 64 d), tf32
        for (int idx = tid; idx < 64 * 16; idx += 128) {
            int r = idx >> 4, c4 = idx & 15;
            const float* rp = base + (size_t)(kt * 64 + r) * 768;
            float4 kv = *(const float4*)(rp + 256 + c4 * 4);
            float4 vv = *(const float4*)(rp + 512 + c4 * 4);
            Ks[r][c4 * 4 + 0] = f2tf32(kv.x); Ks[r][c4 * 4 + 1] = f2tf32(kv.y);
            Ks[r][c4 * 4 + 2] = f2tf32(kv.z); Ks[r][c4 * 4 + 3] = f2tf32(kv.w);
            Vs[r][c4 * 4 + 0] = f2tf32(vv.x); Vs[r][c4 * 4 + 1] = f2tf32(vv.y);
            Vs[r][c4 * 4 + 2] = f2tf32(vv.z); Vs[r][c4 * 4 + 3] = f2tf32(vv.w);
        }
        __syncthreads();

        // S = Q @ K^T for this tile (16 x 64 per warp)
        float s[8][4];
        #pragma unroll
        for (int nt = 0; nt < 8; nt++)
            #pragma unroll
            for (int i = 0; i < 4; i++) s[nt][i] = 0.f;
        #pragma unroll
        for (int kk = 0; kk < 8; kk++) {
            #pragma unroll
            for (int nt = 0; nt < 8; nt++) {
                uint32_t bf[2] = {Ks[nt * 8 + q][8 * kk + t],
                                  Ks[nt * 8 + q][8 * kk + t + 4]};
                mma_tf32(s[nt], aq[kk], bf);
            }
        }

        // Online softmax (rows q and q+8 of this warp's 16)
        float rmax0 = -1e30f, rmax1 = -1e30f;
        #pragma unroll
        for (int nt = 0; nt < 8; nt++) {
            s[nt][0] *= 0.125f; s[nt][1] *= 0.125f;
            s[nt][2] *= 0.125f; s[nt][3] *= 0.125f;
            rmax0 = fmaxf(rmax0, fmaxf(s[nt][0], s[nt][1]));
            rmax1 = fmaxf(rmax1, fmaxf(s[nt][2], s[nt][3]));
        }
        rmax0 = fmaxf(rmax0, __shfl_xor_sync(0xffffffffu, rmax0, 1));
        rmax0 = fmaxf(rmax0, __shfl_xor_sync(0xffffffffu, rmax0, 2));
        rmax1 = fmaxf(rmax1, __shfl_xor_sync(0xffffffffu, rmax1, 1));
        rmax1 = fmaxf(rmax1, __shfl_xor_sync(0xffffffffu, rmax1, 2));
        float nm0 = fmaxf(m0, rmax0), nm1 = fmaxf(m1, rmax1);
        float c0 = __expf(m0 - nm0), c1 = __expf(m1 - nm1);
        m0 = nm0; m1 = nm1;
        float rs0 = 0.f, rs1 = 0.f;
        #pragma unroll
        for (int nt = 0; nt < 8; nt++) {
            s[nt][0] = __expf(s[nt][0] - m0);
            s[nt][1] = __expf(s[nt][1] - m0);
            s[nt][2] = __expf(s[nt][2] - m1);
            s[nt][3] = __expf(s[nt][3] - m1);
            rs0 += s[nt][0] + s[nt][1];
            rs1 += s[nt][2] + s[nt][3];
        }
        rs0 += __shfl_xor_sync(0xffffffffu, rs0, 1);
        rs0 += __shfl_xor_sync(0xffffffffu, rs0, 2);
        rs1 += __shfl_xor_sync(0xffffffffu, rs1, 1);
        rs1 += __shfl_xor_sync(0xffffffffu, rs1, 2);
        l0 = l0 * c0 + rs0;
        l1 = l1 * c1 + rs1;
        #pragma unroll
        for (int nt = 0; nt < 8; nt++) {
            o[nt][0] *= c0; o[nt][1] *= c0;
            o[nt][2] *= c1; o[nt][3] *= c1;
        }

        // Write P (tf32) to this warp's Ps region, re-fragment for PV
        #pragma unroll
        for (int nt = 0; nt < 8; nt++) {
            int col = nt * 8 + 2 * t;
            Ps[warp * 16 + q][col]         = f2tf32(s[nt][0]);
            Ps[warp * 16 + q][col + 1]     = f2tf32(s[nt][1]);
            Ps[warp * 16 + q + 8][col]     = f2tf32(s[nt][2]);
            Ps[warp * 16 + q + 8][col + 1] = f2tf32(s[nt][3]);
        }
        __syncwarp();

        // O += P @ V  (V used directly: B-frag b0 = V[k=key][n=d])
        #pragma unroll
        for (int kk = 0; kk < 8; kk++) {
            uint32_t pa[4];
            pa[0] = Ps[warp * 16 + q][8 * kk + t];
            pa[1] = Ps[warp * 16 + q + 8][8 * kk + t];
            pa[2] = Ps[warp * 16 + q][8 * kk + t + 4];
            pa[3] = Ps[warp * 16 + q + 8][8 * kk + t + 4];
            #pragma unroll
            for (int nt = 0; nt < 8; nt++) {
                uint32_t bf[2] = {Vs[8 * kk + t][8 * nt + q],
                                  Vs[8 * kk + t + 4][8 * nt + q]};
                mma_tf32(o[nt], pa, bf);
            }
        }
        __syncthreads();
    }

    // Epilogue
    float inv0 = 1.f / l0, inv1 = 1.f / l1;
    int r0 = qt * 64 + warp * 16 + q;
    #pragma unroll
    for (int nt = 0; nt < 8; nt++) {
        int col = h * 64 + nt * 8 + 2 * t;
        float* p0 = ao + ((size_t)b * 256 + r0) * 256 + col;
        float* p1 = ao + ((size_t)b * 256 + r0 + 8) * 256 + col;
        *(float2*)p0 = make_float2(o[nt][0] * inv0, o[nt][1] * inv0);
        *(float2*)p1 = make_float2(o[nt][2] * inv1, o[nt][3] * inv1);
    }
}

// ---------------------------------------------------------------------------
// Slot attention pieces
// ---------------------------------------------------------------------------
__global__ void zero_slots_kernel(float* __restrict__ slots) {
    int idx = blockIdx.x * blockDim.x + threadIdx.x;
    if (idx < Bc * NSc * FDc) slots[idx] = 0.f;
}

__global__ __launch_bounds__(256)
void slot_logits_kernel(const float* __restrict__ kin,
                        const float* __restrict__ qs,
                        float* __restrict__ sattn,
                        float* __restrict__ denom) {
    int b = blockIdx.x;
    __shared__ float q[8][320];
    __shared__ float sat[256][8];
    for (int i = threadIdx.x; i < 8 * 320; i += 256)
        q[i / 320][i % 320] = qs[b * 8 * 320 + i];
    __syncthreads();
    int warp = threadIdx.x >> 5, lane = threadIdx.x & 31;
    for (int n = warp; n < 256; n += 8) {
        const float* kr = kin + ((size_t)b * 256 + n) * 320;
        float part[8] = {};
        for (int f = lane; f < 320; f += 32) {
            float kv = kr[f];
            #pragma unroll
            for (int s = 0; s < 8; s++) part[s] += kv * q[s][f];
        }
        #pragma unroll
        for (int s = 0; s < 8; s++)
            #pragma unroll
            for (int o = 16; o; o >>= 1)
                part[s] += __shfl_xor_sync(0xffffffffu, part[s], o);
        if (lane == 0) {
            const float scale = 0.05590169943749474f;  // 1/sqrt(320)
            float mx = -1e30f;
            #pragma unroll
            for (int s = 0; s < 8; s++) { part[s] *= scale; mx = fmaxf(mx, part[s]); }
            float e[8], sum = 0.f;
            #pragma unroll
            for (int s = 0; s < 8; s++) { e[s] = expf(part[s] - mx); sum += e[s]; }
            float inv = 1.f / sum;
            #pragma unroll
            for (int s = 0; s < 8; s++) sat[n][s] = e[s] * inv;
        }
    }
    __syncthreads();
    {
        float d = 0.f;
        for (int n = lane; n < 256; n += 32) d += sat[n][warp] + 1e-8f;
        #pragma unroll
        for (int o = 16; o; o >>= 1) d += __shfl_xor_sync(0xffffffffu, d, o);
        if (lane == 0) denom[b * 8 + warp] = d;
    }
    for (int i = threadIdx.x; i < 2048; i += 256)
        sattn[(size_t)b * 2048 + i] = sat[i >> 3][i & 7];
}

__global__ __launch_bounds__(320)
void updates_kernel(const float* __restrict__ sattn,
                    const float* __restrict__ denom,
                    const float* __restrict__ vin,
                    float* __restrict__ upd) {
    int b = blockIdx.x;
    int f = threadIdx.x;
    __shared__ float an[256][8];
    __shared__ float inv[8];
    for (int i = threadIdx.x; i < 2048; i += 320)
        an[i >> 3][i & 7] = sattn[(size_t)b * 2048 + i] + 1e-8f;
    if (threadIdx.x < 8) inv[threadIdx.x] = 1.f / denom[b * 8 + threadIdx.x];
    __syncthreads();
    float acc[8] = {};
    const float* vp = vin + (size_t)b * 256 * 320 + f;
    for (int n = 0; n < 256; n++) {
        float v = vp[(size_t)n * 320];
        #pragma unroll
        for (int s = 0; s < 8; s++) acc[s] += an[n][s] * v;
    }
    #pragma unroll
    for (int s = 0; s < 8; s++)
        upd[((size_t)b * 8 + s) * 320 + f] = acc[s] * inv[s];
}

__global__ __launch_bounds__(256)
void gru_ln_kernel(const float* __restrict__ gi, const float* __restrict__ gh,
                   float* __restrict__ slots,
                   const float* __restrict__ nm_g, const float* __restrict__ nm_b,
                   float* __restrict__ sln) {
    int row = blockIdx.x * 8 + (threadIdx.x >> 5);
    int lane = threadIdx.x & 31;
    const float* gir = gi + (size_t)row * 960;
    const float* ghr = gh + (size_t)row * 960;
    float* sr = slots + (size_t)row * 320;
    float news[10];
    float s = 0.f, sq = 0.f;
    #pragma unroll
    for (int i = 0; i < 10; i++) {
        int f = lane + 32 * i;
        float ir = gir[f], iz = gir[320 + f], in_ = gir[640 + f];
        float hr = ghr[f], hz = ghr[320 + f], hn  = ghr[640 + f];
        float r = 1.f / (1.f + __expf(-(ir + hr)));
        float z = 1.f / (1.f + __expf(-(iz + hz)));
        float nn = tanhf(in_ + r * hn);
        float v = (1.f - z) * nn + z * sr[f];
        news[i] = v;
        s += v; sq += v * v;
    }
    #pragma unroll
    for (int o = 16; o; o >>= 1) {
        s  += __shfl_xor_sync(0xffffffffu, s, o);
        sq += __shfl_xor_sync(0xffffffffu, sq, o);
    }
    float mean = s / 320.f;
    float var = sq / 320.f - mean * mean;
    float inv = rsqrtf(fmaxf(var, 0.f) + 1e-5f);
    float* lr = sln + (size_t)row * 320;
    #pragma unroll
    for (int i = 0; i < 10; i++) {
        int f = lane + 32 * i;
        sr[f] = news[i];
        lr[f] = (news[i] - mean) * inv * nm_g[f] + nm_b[f];
    }
}

__global__ void output_kernel(const float* __restrict__ slots,
                              const float* __restrict__ sattn,
                              float* __restrict__ out) {
    int idx = blockIdx.x * blockDim.x + threadIdx.x;
    const int SLOTS = Bc * NSc * FDc;      // 163840
    const int MASKS = Bc * NSc * Nc;       // 131072
    if (idx < SLOTS) {
        out[idx] = slots[idx];
    } else if (idx < SLOTS + MASKS) {
        int k = idx - SLOTS;
        int b = k / (NSc * Nc);
        int r = k % (NSc * Nc);
        int s = r / Nc;
        int n = r % Nc;
        out[idx] = sattn[((size_t)b * Nc + n) * NSc + s];
    }
}

// ---------------------------------------------------------------------------
// Host launcher
// ---------------------------------------------------------------------------
template <typename T>
static float* sym_addr(T& sym) {
    void* p = nullptr;
    cudaGetSymbolAddress(&p, sym);
    return (float*)p;
}

extern "C" void kernel_launch(void* const* d_in, const int* in_sizes, int n_in,
                              void* d_out, int out_size) {
    const float* state    = (const float*)d_in[0];
    const float* conv_w   = (const float*)d_in[1];
    const float* conv_b   = (const float*)d_in[2];
    const float* mlp_ln_g = (const float*)d_in[3];
    const float* mlp_ln_b = (const float*)d_in[4];
    const float* mlp_w1   = (const float*)d_in[5];
    const float* mlp_b1   = (const float*)d_in[6];
    const float* mlp_w2   = (const float*)d_in[7];
    const float* mlp_b2   = (const float*)d_in[8];
    const float* qkv_w    = (const float*)d_in[9];
    const float* qkv_b    = (const float*)d_in[10];
    const float* proj_w   = (const float*)d_in[11];
    const float* proj_b   = (const float*)d_in[12];
    const float* ni_g     = (const float*)d_in[13];
    const float* ni_b     = (const float*)d_in[14];
    const float* ns_g     = (const float*)d_in[15];
    const float* ns_b     = (const float*)d_in[16];
    const float* nm_g     = (const float*)d_in[17];
    const float* nm_b     = (const float*)d_in[18];
    const float* q_w      = (const float*)d_in[19];
    const float* k_w      = (const float*)d_in[20];
    const float* v_w      = (const float*)d_in[21];
    const float* gru_wih  = (const float*)d_in[22];
    const float* gru_whh  = (const float*)d_in[23];
    const float* gru_bih  = (const float*)d_in[24];
    const float* gru_bhh  = (const float*)d_in[25];
    const float* smlp_w1  = (const float*)d_in[26];
    const float* smlp_b1  = (const float*)d_in[27];
    const float* smlp_w2  = (const float*)d_in[28];
    const float* smlp_b2  = (const float*)d_in[29];
    float* out = (float*)d_out;

    float* P     = sym_addr(g_P);
    float* x0    = sym_addr(g_x0);
    float* lnb   = sym_addr(g_ln);
    float* h1    = sym_addr(g_h1);
    float* x2    = sym_addr(g_x2);
    float* ao    = sym_addr(g_ao);
    float* x3    = sym_addr(g_x3);
    float* kin   = sym_addr(g_kin);
    float* vin   = sym_addr(g_vin);
    float* slots = sym_addr(g_slots);
    float* sln   = sym_addr(g_sln);
    float* qs    = sym_addr(g_qs);
    float* sattn = sym_addr(g_sattn);
    float* denom = sym_addr(g_denom);
    float* upd   = sym_addr(g_upd);
    float* gi    = sym_addr(g_gi);
    float* gh    = sym_addr(g_gh);
    float* m1    = sym_addr(g_m1);

    const int ATTN_SMEM = 4 * 64 * 68 * 4;   // 69632 bytes
    cudaFuncSetAttribute(attn_mma_kernel,
                         cudaFuncAttributeMaxDynamicSharedMemorySize, ATTN_SMEM);

    // 1. RoPE tables + patch matrix
    rope_init_kernel<<<Nc, HDc>>>();
    patch_kernel<<<TOK, 64>>>(state, P);

    // 2. Patch conv as GEMM (tensor cores)
    gemm128(P, conv_w, conv_b, nullptr, x0, TOK, 256, 768, 0);

    // 3. Token MLP
    ln_warp_kernel<<<TOK / 8, 256>>>(x0, mlp_ln_g, mlp_ln_b, lnb, 256);
    gemm128(lnb, mlp_w1, mlp_b1, nullptr, h1, TOK, 512, 256, 1);
    gemm128(h1, mlp_w2, mlp_b2, nullptr, x2, TOK, 256, 512, 0);

    // 4. QKV + RoPE + attention (tensor cores) + proj (residual with x2)
    gemm128(x2, qkv_w, qkv_b, nullptr, P, TOK, 768, 256, 0);
    rope_apply_kernel<<<TOK, 256>>>(P);
    attn_mma_kernel<<<dim3(4, HEADSc, Bc), 128, ATTN_SMEM>>>(P, ao);
    gemm128(ao, proj_w, proj_b, x2, x3, TOK, 256, 256, 0);

    // 5. Norm + fused k/v projection (N = 640, split at 320)
    ln_warp_kernel<<<TOK / 8, 256>>>(x3, ni_g, ni_b, lnb, 256);
    {
        dim3 grid(640 / 128, TOK / 128);
        gemm128_kernel<<<grid, 256>>>(lnb, k_w, v_w, 320, nullptr, nullptr,
                                      kin, vin, TOK, 640, 256, 0);
    }

    // 6. Slot attention, 3 iterations (3xTF32 precision)
    zero_slots_kernel<<<(Bc * NSc * FDc + 255) / 256, 256>>>(slots);
    for (int it = 0; it < ITc; it++) {
        ln_warp_kernel<<<Bc * NSc / 8, 256>>>(slots, ns_g, ns_b, sln, 320);
        gemm_x3(sln, q_w, nullptr, nullptr, qs, Bc * NSc, 320, 320, 0);
        slot_logits_kernel<<<Bc, 256>>>(kin, qs, sattn, denom);
        updates_kernel<<<Bc, 320>>>(sattn, denom, vin, upd);
        gemm_x3(upd,   gru_wih, gru_bih, nullptr, gi, Bc * NSc, 960, 320, 0);
        gemm_x3(slots, gru_whh, gru_bhh, nullptr, gh, Bc * NSc, 960, 320, 0);
        gru_ln_kernel<<<Bc * NSc / 8, 256>>>(gi, gh, slots, nm_g, nm_b, sln);
        gemm_x3(sln, smlp_w1, smlp_b1, nullptr, m1, Bc * NSc, 640, 320, 1);
        gemm_x3(m1, smlp_w2, smlp_b2, slots, slots, Bc * NSc, 320, 640, 0);
    }

    // 7. Pack outputs
    int total = Bc * NSc * FDc + Bc * NSc * Nc;
    output_kernel<<<(total + 255) / 256, 256>>>(slots, sattn, out);
}

// round 5
// speedup vs baseline: 1.8660x; 1.0176x over previous
#include <cuda_runtime.h>
#include <math.h>
#include <stdint.h>

// ---------------------------------------------------------------------------
// Problem constants
// ---------------------------------------------------------------------------
constexpr int Bc = 64, Hc = 128, Wc = 128, PSc = 8, Gc = 16, Ec = 256;
constexpr int NSc = 8, ITc = 3, Vc = 10, FDc = 320, HEADSc = 4, HDc = 64;
constexpr int Nc = Gc * Gc;          // 256 tokens per image
constexpr int TOK = Bc * Nc;         // 16384 rows

// ---------------------------------------------------------------------------
// Device scratch
// ---------------------------------------------------------------------------
__device__ float g_P   [TOK * 768];        // im2col patches; reused for QKV
__device__ float g_x0  [TOK * Ec];
__device__ float g_ln  [TOK * Ec];
__device__ float g_h1  [TOK * 512];
__device__ float g_x2  [TOK * Ec];
__device__ float g_ao  [TOK * Ec];
__device__ float g_x3  [TOK * Ec];
__device__ float g_kin [TOK * FDc];
__device__ float g_vin [TOK * FDc];
__device__ float g_cosT[Nc * HDc];
__device__ float g_sinT[Nc * HDc];
__device__ float g_slots[Bc * NSc * FDc];
__device__ float g_sln  [Bc * NSc * FDc];
__device__ float g_qs   [Bc * NSc * FDc];
__device__ float g_sattn[Bc * Nc * NSc];
__device__ float g_denom[Bc * NSc];
__device__ float g_upd  [Bc * NSc * FDc];
__device__ float g_gi   [Bc * NSc * 3 * FDc];
__device__ float g_gh   [Bc * NSc * 3 * FDc];
__device__ float g_m1   [Bc * NSc * 2 * FDc];

// ---------------------------------------------------------------------------
// Helpers
// ---------------------------------------------------------------------------
__device__ __forceinline__ float gelu_exact(float x) {
    return 0.5f * x * (1.0f + erff(x * 0.70710678118654752f));
}

__device__ __forceinline__ uint32_t f2tf32(float x) {
    uint32_t r;
    asm("cvt.rna.tf32.f32 %0, %1;" : "=r"(r) : "f"(x));
    return r;
}

__device__ __forceinline__ void mma_tf32(float (&d)[4], const uint32_t (&a)[4],
                                         const uint32_t (&b)[2]) {
    asm volatile(
        "mma.sync.aligned.m16n8k8.row.col.f32.tf32.tf32.f32 "
        "{%0,%1,%2,%3}, {%4,%5,%6,%7}, {%8,%9}, {%0,%1,%2,%3};\n"
        : "+f"(d[0]), "+f"(d[1]), "+f"(d[2]), "+f"(d[3])
        : "r"(a[0]), "r"(a[1]), "r"(a[2]), "r"(a[3]), "r"(b[0]), "r"(b[1]));
}

// ---------------------------------------------------------------------------
// RoPE tables
// ---------------------------------------------------------------------------
__global__ void rope_init_kernel() {
    int n = blockIdx.x;          // 0..255
    int d = threadIdx.x;         // 0..63
    int gy = n >> 4, gx = n & 15;
    int pos = (d < 32) ? gy : gx;
    int dd  = (d < 32) ? d : d - 32;
    float val;
    if (dd < 16) {
        float inv = expf(-9.210340371976184f * (2.0f * dd) / 32.0f);
        val = sinf((float)pos * inv);
    } else {
        float inv = expf(-9.210340371976184f * (2.0f * (dd - 16)) / 32.0f);
        val = cosf((float)pos * inv);
    }
    g_cosT[n * 64 + d] = cosf(val);
    g_sinT[n * 64 + d] = sinf(val);
}

// ---------------------------------------------------------------------------
// Patch / im2col builder
// ---------------------------------------------------------------------------
__global__ void patch_kernel(const float* __restrict__ state, float* __restrict__ P) {
    int bn = blockIdx.x;
    int b = bn >> 8, n = bn & 255;
    int gy = n >> 4, gx = n & 15;
    int p = threadIdx.x;               // 0..63
    int py = p >> 3, px = p & 7;
    int y = gy * 8 + py, x = gx * 8 + px;
    const float* sb = state + (size_t)b * Hc * Wc;
    float* row = P + (size_t)bn * 768;
    for (int k = p; k < 768; k += 64) row[k] = 0.f;

    float v[3][3];
    #pragma unroll
    for (int di = 0; di < 3; di++) {
        int yy = min(max(y + di - 1, 0), Hc - 1);
        #pragma unroll
        for (int dj = 0; dj < 3; dj++) {
            int xx = min(max(x + dj - 1, 0), Wc - 1);
            v[di][dj] = sb[yy * Wc + xx];
        }
    }
    float sx = (v[0][2] + 2.f * v[1][2] + v[2][2]) - (v[0][0] + 2.f * v[1][0] + v[2][0]);
    float sy = (v[2][0] + 2.f * v[2][1] + v[2][2]) - (v[0][0] + 2.f * v[0][1] + v[0][2]);
    int id = (int)sb[y * Wc + x];
    __syncthreads();
    row[id * 64 + p]  = 1.f;
    row[640 + p]      = sx;
    row[704 + p]      = sy;
}

// ---------------------------------------------------------------------------
// TF32 tensor-core GEMM, fragment-major smem layout.
// BM=128, BN=128, BK=16, 256 threads (8 warps), warp tile m32 x n64.
// A tile: 16 (mtile,kchunk) tiles of 132 words; word (q*4+t)*4 + (hi+2*kw).
// B tile: 32 (ntile,kchunk) tiles of 66 words; word (q*4+t)*2 + kw.
// Fragment loads: A = one LDS.128 at lane*4, B = one LDS.64 at lane*2.
// Supports split weight/output for the fused kin/vin GEMM.
// ---------------------------------------------------------------------------
constexpr int ATILE = 132;            // words per A (mtile,kchunk) tile
constexpr int BTILE = 66;             // words per B (ntile,kchunk) tile
constexpr int ABUF  = 16 * ATILE;     // 2112 words
constexpr int BBUF  = 32 * BTILE;     // 2112 words

__global__ __launch_bounds__(256)
void gemm128_kernel(const float* __restrict__ A,
                    const float* __restrict__ Wa, const float* __restrict__ Wb,
                    int nsplit,
                    const float* __restrict__ bias, const float* __restrict__ res,
                    float* __restrict__ Ca, float* __restrict__ Cb,
                    int M, int N, int K, int act) {
    __shared__ uint32_t As[2][ABUF];
    __shared__ uint32_t Bs[2][BBUF];

    int tid = threadIdx.x;
    int m0 = blockIdx.y * 128, n0 = blockIdx.x * 128;
    int warp = tid >> 5, lane = tid & 31;
    int wm = warp & 3, wn = warp >> 2;   // wm: 4 x 32 rows, wn: 2 x 64 cols
    int q = lane >> 2, t = lane & 3;

    int r  = tid >> 2;                   // 0..63 (handles rows r and r+64)
    int k4 = (tid & 3) << 2;             // 0,4,8,12

    // store-side indexing (fragment-major)
    int q8     = r & 7;
    int hiA    = (r >> 3) & 1;           // same for r and r+64
    int mt0    = r >> 4;                 // mtile of row r; row r+64 -> mt0+4
    int kchunk = k4 >> 3;
    int kw     = (k4 >> 2) & 1;
    int baseA0 = (mt0 * 2 + kchunk) * ATILE       + q8 * 16 + (hiA + 2 * kw);
    int baseA1 = ((mt0 + 4) * 2 + kchunk) * ATILE + q8 * 16 + (hiA + 2 * kw);
    int nt0    = r >> 3;                 // ntile of col r; col r+64 -> nt0+8
    int baseB0 = (nt0 * 2 + kchunk) * BTILE       + q8 * 8 + kw;
    int baseB1 = ((nt0 + 8) * 2 + kchunk) * BTILE + q8 * 8 + kw;

    const float* Ap0 = A + (size_t)(m0 + r) * K + k4;
    const float* Ap1 = Ap0 + (size_t)64 * K;
    int nr0 = n0 + r, nr1 = n0 + r + 64;
    const float* Wp0 = (nr0 < nsplit) ? Wa + (size_t)nr0 * K + k4
                                      : Wb + (size_t)(nr0 - nsplit) * K + k4;
    const float* Wp1 = (nr1 < nsplit) ? Wa + (size_t)nr1 * K + k4
                                      : Wb + (size_t)(nr1 - nsplit) * K + k4;

    float acc[2][8][4];
    #pragma unroll
    for (int mt = 0; mt < 2; mt++)
        #pragma unroll
        for (int nt = 0; nt < 8; nt++)
            #pragma unroll
            for (int i = 0; i < 4; i++) acc[mt][nt][i] = 0.f;

    int ntiles = K >> 4;
    float4 a0 = *(const float4*)Ap0;
    float4 a1 = *(const float4*)Ap1;
    float4 b0 = *(const float4*)Wp0;
    float4 b1 = *(const float4*)Wp1;
    int buf = 0;
    {
        As[0][baseA0 + 0]  = f2tf32(a0.x); As[0][baseA0 + 4]  = f2tf32(a0.y);
        As[0][baseA0 + 8]  = f2tf32(a0.z); As[0][baseA0 + 12] = f2tf32(a0.w);
        As[0][baseA1 + 0]  = f2tf32(a1.x); As[0][baseA1 + 4]  = f2tf32(a1.y);
        As[0][baseA1 + 8]  = f2tf32(a1.z); As[0][baseA1 + 12] = f2tf32(a1.w);
        Bs[0][baseB0 + 0]  = f2tf32(b0.x); Bs[0][baseB0 + 2]  = f2tf32(b0.y);
        Bs[0][baseB0 + 4]  = f2tf32(b0.z); Bs[0][baseB0 + 6]  = f2tf32(b0.w);
        Bs[0][baseB1 + 0]  = f2tf32(b1.x); Bs[0][baseB1 + 2]  = f2tf32(b1.y);
        Bs[0][baseB1 + 4]  = f2tf32(b1.z); Bs[0][baseB1 + 6]  = f2tf32(b1.w);
    }
    __syncthreads();

    for (int kt = 0; kt < ntiles; kt++) {
        bool more = (kt + 1 < ntiles);
        if (more) {
            a0 = *(const float4*)(Ap0 + (kt + 1) * 16);
            a1 = *(const float4*)(Ap1 + (kt + 1) * 16);
            b0 = *(const float4*)(Wp0 + (kt + 1) * 16);
            b1 = *(const float4*)(Wp1 + (kt + 1) * 16);
        }
        #pragma unroll
        for (int ks = 0; ks < 2; ks++) {
            uint32_t af[2][4], bf[8][2];
            #pragma unroll
            for (int mt = 0; mt < 2; mt++) {
                int tile = (wm * 2 + mt) * 2 + ks;
                uint4 v = *(const uint4*)&As[buf][tile * ATILE + lane * 4];
                af[mt][0] = v.x; af[mt][1] = v.y; af[mt][2] = v.z; af[mt][3] = v.w;
            }
            #pragma unroll
            for (int nt = 0; nt < 8; nt++) {
                int tile = (wn * 8 + nt) * 2 + ks;
                uint2 v = *(const uint2*)&Bs[buf][tile * BTILE + lane * 2];
                bf[nt][0] = v.x; bf[nt][1] = v.y;
            }
            #pragma unroll
            for (int mt = 0; mt < 2; mt++)
                #pragma unroll
                for (int nt = 0; nt < 8; nt++)
                    mma_tf32(acc[mt][nt], af[mt], bf[nt]);
        }
        __syncthreads();
        if (more) {
            buf ^= 1;
            As[buf][baseA0 + 0]  = f2tf32(a0.x); As[buf][baseA0 + 4]  = f2tf32(a0.y);
            As[buf][baseA0 + 8]  = f2tf32(a0.z); As[buf][baseA0 + 12] = f2tf32(a0.w);
            As[buf][baseA1 + 0]  = f2tf32(a1.x); As[buf][baseA1 + 4]  = f2tf32(a1.y);
            As[buf][baseA1 + 8]  = f2tf32(a1.z); As[buf][baseA1 + 12] = f2tf32(a1.w);
            Bs[buf][baseB0 + 0]  = f2tf32(b0.x); Bs[buf][baseB0 + 2]  = f2tf32(b0.y);
            Bs[buf][baseB0 + 4]  = f2tf32(b0.z); Bs[buf][baseB0 + 6]  = f2tf32(b0.w);
            Bs[buf][baseB1 + 0]  = f2tf32(b1.x); Bs[buf][baseB1 + 2]  = f2tf32(b1.y);
            Bs[buf][baseB1 + 4]  = f2tf32(b1.z); Bs[buf][baseB1 + 6]  = f2tf32(b1.w);
            __syncthreads();
        }
    }

    int strideB = N - nsplit;
    #pragma unroll
    for (int mt = 0; mt < 2; mt++) {
        #pragma unroll
        for (int nt = 0; nt < 8; nt++) {
            int gm0 = m0 + wm * 32 + mt * 16 + q;
            int gn  = n0 + wn * 64 + nt * 8 + 2 * t;
            float bb0 = bias ? bias[gn]     : 0.f;
            float bb1 = bias ? bias[gn + 1] : 0.f;
            #pragma unroll
            for (int half = 0; half < 2; half++) {
                int gm = gm0 + half * 8;
                float c0 = acc[mt][nt][half * 2 + 0] + bb0;
                float c1 = acc[mt][nt][half * 2 + 1] + bb1;
                if (act == 1) { c0 = gelu_exact(c0); c1 = gelu_exact(c1); }
                if (gn < nsplit) {
                    size_t idx = (size_t)gm * nsplit + gn;
                    if (res) { c0 += res[idx]; c1 += res[idx + 1]; }
                    *(float2*)(Ca + idx) = make_float2(c0, c1);
                } else {
                    size_t idx = (size_t)gm * strideB + (gn - nsplit);
                    *(float2*)(Cb + idx) = make_float2(c0, c1);
                }
            }
        }
    }
}

static inline void gemm128(const float* A, const float* W, const float* bias,
                           const float* res, float* C, int M, int N, int K, int act) {
    dim3 grid(N / 128, M / 128);
    gemm128_kernel<<<grid, 256>>>(A, W, nullptr, N, bias, res, C, nullptr, M, N, K, act);
}

// ---------------------------------------------------------------------------
// 3xTF32 GEMM (near-fp32 accuracy) for slot-loop GEMMs. BM=BN=64, BK=16.
// ---------------------------------------------------------------------------
__global__ __launch_bounds__(256)
void gemm_tf32x3_kernel(const float* __restrict__ A, const float* __restrict__ W,
                        const float* __restrict__ bias, const float* __restrict__ res,
                        float* __restrict__ C, int M, int N, int K, int act) {
    __shared__ uint32_t Ah[64][20], Al[64][20], Bh[64][20], Bl[64][20];

    int tid = threadIdx.x;
    int m0 = blockIdx.y * 64, n0 = blockIdx.x * 64;
    int warp = tid >> 5, lane = tid & 31;
    int wm = warp & 1, wn = warp >> 1;
    int q = lane >> 2, t = lane & 3;

    int aRow = tid >> 2;
    int k4   = (tid & 3) << 2;
    const float* Aptr = A + (size_t)(m0 + aRow) * K + k4;
    const float* Wptr = W + (size_t)(n0 + aRow) * K + k4;

    float acc[2][2][4];
    #pragma unroll
    for (int mt = 0; mt < 2; mt++)
        #pragma unroll
        for (int nt = 0; nt < 2; nt++)
            #pragma unroll
            for (int i = 0; i < 4; i++) acc[mt][nt][i] = 0.f;

    for (int kt = 0; kt < K; kt += 16) {
        float4 av = *(const float4*)(Aptr + kt);
        float4 bv = *(const float4*)(Wptr + kt);
        float a4[4] = {av.x, av.y, av.z, av.w};
        float b4[4] = {bv.x, bv.y, bv.z, bv.w};
        #pragma unroll
        for (int i = 0; i < 4; i++) {
            uint32_t h = f2tf32(a4[i]);
            Ah[aRow][k4 + i] = h;
            Al[aRow][k4 + i] = f2tf32(a4[i] - __uint_as_float(h));
            h = f2tf32(b4[i]);
            Bh[aRow][k4 + i] = h;
            Bl[aRow][k4 + i] = f2tf32(b4[i] - __uint_as_float(h));
        }
        __syncthreads();
        #pragma unroll
        for (int ks = 0; ks < 2; ks++) {
            int kc = ks * 8 + t;
            uint32_t ah[2][4], al[2][4], bh[2][2], bl[2][2];
            #pragma unroll
            for (int mt = 0; mt < 2; mt++) {
                int rr = wm * 32 + mt * 16 + q;
                ah[mt][0] = Ah[rr][kc];   ah[mt][1] = Ah[rr + 8][kc];
                ah[mt][2] = Ah[rr][kc+4]; ah[mt][3] = Ah[rr + 8][kc+4];
                al[mt][0] = Al[rr][kc];   al[mt][1] = Al[rr + 8][kc];
                al[mt][2] = Al[rr][kc+4]; al[mt][3] = Al[rr + 8][kc+4];
            }
            #pragma unroll
            for (int nt = 0; nt < 2; nt++) {
                int nn = wn * 16 + nt * 8 + q;
                bh[nt][0] = Bh[nn][kc]; bh[nt][1] = Bh[nn][kc + 4];
                bl[nt][0] = Bl[nn][kc]; bl[nt][1] = Bl[nn][kc + 4];
            }
            #pragma unroll
            for (int mt = 0; mt < 2; mt++)
                #pragma unroll
                for (int nt = 0; nt < 2; nt++) {
                    mma_tf32(acc[mt][nt], al[mt], bh[nt]);
                    mma_tf32(acc[mt][nt], ah[mt], bl[nt]);
                    mma_tf32(acc[mt][nt], ah[mt], bh[nt]);
                }
        }
        __syncthreads();
    }

    #pragma unroll
    for (int mt = 0; mt < 2; mt++) {
        #pragma unroll
        for (int nt = 0; nt < 2; nt++) {
            int gm0 = m0 + wm * 32 + mt * 16 + q;
            int gn  = n0 + wn * 16 + nt * 8 + 2 * t;
            float b0 = bias ? bias[gn]     : 0.f;
            float b1 = bias ? bias[gn + 1] : 0.f;
            #pragma unroll
            for (int half = 0; half < 2; half++) {
                int gm = gm0 + half * 8;
                float c0 = acc[mt][nt][half * 2 + 0] + b0;
                float c1 = acc[mt][nt][half * 2 + 1] + b1;
                if (act == 1) { c0 = gelu_exact(c0); c1 = gelu_exact(c1); }
                size_t idx = (size_t)gm * N + gn;
                if (res) { c0 += res[idx]; c1 += res[idx + 1]; }
                *(float2*)(C + idx) = make_float2(c0, c1);
            }
        }
    }
}

static inline void gemm_x3(const float* A, const float* W, const float* bias,
                           const float* res, float* C, int M, int N, int K, int act) {
    dim3 grid(N / 64, M / 64);
    gemm_tf32x3_kernel<<<grid, 256>>>(A, W, bias, res, C, M, N, K, act);
}

// ---------------------------------------------------------------------------
// LayerNorm: warp per row, single pass, float4.
// ---------------------------------------------------------------------------
__global__ __launch_bounds__(256)
void ln_warp_kernel(const float* __restrict__ x, const float* __restrict__ g,
                    const float* __restrict__ b, float* __restrict__ y, int cols) {
    int row = blockIdx.x * 8 + (threadIdx.x >> 5);
    int lane = threadIdx.x & 31;
    int cols4 = cols >> 2;
    const float4* xr = (const float4*)(x + (size_t)row * cols);
    float s = 0.f, sq = 0.f;
    for (int c = lane; c < cols4; c += 32) {
        float4 v = xr[c];
        s  += (v.x + v.y) + (v.z + v.w);
        sq += v.x * v.x + v.y * v.y + v.z * v.z + v.w * v.w;
    }
    #pragma unroll
    for (int o = 16; o; o >>= 1) {
        s  += __shfl_xor_sync(0xffffffffu, s, o);
        sq += __shfl_xor_sync(0xffffffffu, sq, o);
    }
    float mean = s / (float)cols;
    float var = sq / (float)cols - mean * mean;
    float inv = rsqrtf(fmaxf(var, 0.f) + 1e-5f);
    float4* yr = (float4*)(y + (size_t)row * cols);
    const float4* g4 = (const float4*)g;
    const float4* b4 = (const float4*)b;
    for (int c = lane; c < cols4; c += 32) {
        float4 v = xr[c], gg = g4[c], bb = b4[c], o;
        o.x = (v.x - mean) * inv * gg.x + bb.x;
        o.y = (v.y - mean) * inv * gg.y + bb.y;
        o.z = (v.z - mean) * inv * gg.z + bb.z;
        o.w = (v.w - mean) * inv * gg.w + bb.w;
        yr[c] = o;
    }
}

// ---------------------------------------------------------------------------
// RoPE apply
// ---------------------------------------------------------------------------
__global__ void rope_apply_kernel(float* __restrict__ qkv) {
    int row = blockIdx.x;
    int n = row & 255;
    int g = threadIdx.x >> 5;
    int t = threadIdx.x & 31;
    int s = g >> 2, h = g & 3;
    __shared__ float sh[8][64];
    float* p = qkv + (size_t)row * 768 + s * 256 + h * 64;
    sh[g][t]      = p[t];
    sh[g][t + 32] = p[t + 32];
    __syncwarp();
    float c1 = g_cosT[n * 64 + t],      s1 = g_sinT[n * 64 + t];
    float c2 = g_cosT[n * 64 + t + 32], s2 = g_sinT[n * 64 + t + 32];
    float o1 = sh[g][t]      * c1 - sh[g][2 * t + 1] * s1;
    float o2 = sh[g][t + 32] * c2 + sh[g][2 * t]     * s2;
    p[t]      = o1;
    p[t + 32] = o2;
}

// ---------------------------------------------------------------------------
// Attention via tf32 MMA, flash-style. Block = 128 threads (4 warps),
// each block handles 64 queries for one (b,h). grid (4 qtiles, 4 h, 64 b).
// ---------------------------------------------------------------------------
__global__ __launch_bounds__(128)
void attn_mma_kernel(const float* __restrict__ qkv, float* __restrict__ ao) {
    extern __shared__ uint32_t sm[];
    uint32_t (*Qs)[68] = (uint32_t(*)[68])(sm);
    uint32_t (*Ks)[68] = (uint32_t(*)[68])(sm + 64 * 68);
    uint32_t (*Vs)[68] = (uint32_t(*)[68])(sm + 2 * 64 * 68);
    uint32_t (*Ps)[68] = (uint32_t(*)[68])(sm + 3 * 64 * 68);

    int qt = blockIdx.x, h = blockIdx.y, b = blockIdx.z;
    int tid = threadIdx.x;
    int warp = tid >> 5, lane = tid & 31;
    int q = lane >> 2, t = lane & 3;

    const float* base = qkv + (size_t)b * 256 * 768 + h * 64;

    for (int idx = tid; idx < 64 * 16; idx += 128) {
        int r = idx >> 4, c4 = idx & 15;
        float4 v = *(const float4*)(base + (size_t)(qt * 64 + r) * 768 + c4 * 4);
        Qs[r][c4 * 4 + 0] = f2tf32(v.x);
        Qs[r][c4 * 4 + 1] = f2tf32(v.y);
        Qs[r][c4 * 4 + 2] = f2tf32(v.z);
        Qs[r][c4 * 4 + 3] = f2tf32(v.w);
    }
    __syncthreads();

    uint32_t aq[8][4];
    #pragma unroll
    for (int kk = 0; kk < 8; kk++) {
        int rr = warp * 16 + q;
        aq[kk][0] = Qs[rr][8 * kk + t];
        aq[kk][1] = Qs[rr + 8][8 * kk + t];
        aq[kk][2] = Qs[rr][8 * kk + t + 4];
        aq[kk][3] = Qs[rr + 8][8 * kk + t + 4];
    }

    float m0 = -1e30f, m1 = -1e30f, l0 = 0.f, l1 = 0.f;
    float o[8][4];
    #pragma unroll
    for (int nt = 0; nt < 8; nt++)
        #pragma unroll
        for (int i = 0; i < 4; i++) o[nt][i] = 0.f;

    for (int kt = 0; kt < 4; kt++) {
        for (int idx = tid; idx < 64 * 16; idx += 128) {
            int r = idx >> 4, c4 = idx & 15;
            const float* rp = base + (size_t)(kt * 64 + r) * 768;
            float4 kv = *(const float4*)(rp + 256 + c4 * 4);
            float4 vv = *(const float4*)(rp + 512 + c4 * 4);
            Ks[r][c4 * 4 + 0] = f2tf32(kv.x); Ks[r][c4 * 4 + 1] = f2tf32(kv.y);
            Ks[r][c4 * 4 + 2] = f2tf32(kv.z); Ks[r][c4 * 4 + 3] = f2tf32(kv.w);
            Vs[r][c4 * 4 + 0] = f2tf32(vv.x); Vs[r][c4 * 4 + 1] = f2tf32(vv.y);
            Vs[r][c4 * 4 + 2] = f2tf32(vv.z); Vs[r][c4 * 4 + 3] = f2tf32(vv.w);
        }
        __syncthreads();

        float s[8][4];
        #pragma unroll
        for (int nt = 0; nt < 8; nt++)
            #pragma unroll
            for (int i = 0; i < 4; i++) s[nt][i] = 0.f;
        #pragma unroll
        for (int kk = 0; kk < 8; kk++) {
            #pragma unroll
            for (int nt = 0; nt < 8; nt++) {
                uint32_t bf[2] = {Ks[nt * 8 + q][8 * kk + t],
                                  Ks[nt * 8 + q][8 * kk + t + 4]};
                mma_tf32(s[nt], aq[kk], bf);
            }
        }

        float rmax0 = -1e30f, rmax1 = -1e30f;
        #pragma unroll
        for (int nt = 0; nt < 8; nt++) {
            s[nt][0] *= 0.125f; s[nt][1] *= 0.125f;
            s[nt][2] *= 0.125f; s[nt][3] *= 0.125f;
            rmax0 = fmaxf(rmax0, fmaxf(s[nt][0], s[nt][1]));
            rmax1 = fmaxf(rmax1, fmaxf(s[nt][2], s[nt][3]));
        }
        rmax0 = fmaxf(rmax0, __shfl_xor_sync(0xffffffffu, rmax0, 1));
        rmax0 = fmaxf(rmax0, __shfl_xor_sync(0xffffffffu, rmax0, 2));
        rmax1 = fmaxf(rmax1, __shfl_xor_sync(0xffffffffu, rmax1, 1));
        rmax1 = fmaxf(rmax1, __shfl_xor_sync(0xffffffffu, rmax1, 2));
        float nm0 = fmaxf(m0, rmax0), nm1 = fmaxf(m1, rmax1);
        float c0 = __expf(m0 - nm0), c1 = __expf(m1 - nm1);
        m0 = nm0; m1 = nm1;
        float rs0 = 0.f, rs1 = 0.f;
        #pragma unroll
        for (int nt = 0; nt < 8; nt++) {
            s[nt][0] = __expf(s[nt][0] - m0);
            s[nt][1] = __expf(s[nt][1] - m0);
            s[nt][2] = __expf(s[nt][2] - m1);
            s[nt][3] = __expf(s[nt][3] - m1);
            rs0 += s[nt][0] + s[nt][1];
            rs1 += s[nt][2] + s[nt][3];
        }
        rs0 += __shfl_xor_sync(0xffffffffu, rs0, 1);
        rs0 += __shfl_xor_sync(0xffffffffu, rs0, 2);
        rs1 += __shfl_xor_sync(0xffffffffu, rs1, 1);
        rs1 += __shfl_xor_sync(0xffffffffu, rs1, 2);
        l0 = l0 * c0 + rs0;
        l1 = l1 * c1 + rs1;
        #pragma unroll
        for (int nt = 0; nt < 8; nt++) {
            o[nt][0] *= c0; o[nt][1] *= c0;
            o[nt][2] *= c1; o[nt][3] *= c1;
        }

        #pragma unroll
        for (int nt = 0; nt < 8; nt++) {
            int col = nt * 8 + 2 * t;
            Ps[warp * 16 + q][col]         = f2tf32(s[nt][0]);
            Ps[warp * 16 + q][col + 1]     = f2tf32(s[nt][1]);
            Ps[warp * 16 + q + 8][col]     = f2tf32(s[nt][2]);
            Ps[warp * 16 + q + 8][col + 1] = f2tf32(s[nt][3]);
        }
        __syncwarp();

        #pragma unroll
        for (int kk = 0; kk < 8; kk++) {
            uint32_t pa[4];
            pa[0] = Ps[warp * 16 + q][8 * kk + t];
            pa[1] = Ps[warp * 16 + q + 8][8 * kk + t];
            pa[2] = Ps[warp * 16 + q][8 * kk + t + 4];
            pa[3] = Ps[warp * 16 + q + 8][8 * kk + t + 4];
            #pragma unroll
            for (int nt = 0; nt < 8; nt++) {
                uint32_t bf[2] = {Vs[8 * kk + t][8 * nt + q],
                                  Vs[8 * kk + t + 4][8 * nt + q]};
                mma_tf32(o[nt], pa, bf);
            }
        }
        __syncthreads();
    }

    float inv0 = 1.f / l0, inv1 = 1.f / l1;
    int r0 = qt * 64 + warp * 16 + q;
    #pragma unroll
    for (int nt = 0; nt < 8; nt++) {
        int col = h * 64 + nt * 8 + 2 * t;
        float* p0 = ao + ((size_t)b * 256 + r0) * 256 + col;
        float* p1 = ao + ((size_t)b * 256 + r0 + 8) * 256 + col;
        *(float2*)p0 = make_float2(o[nt][0] * inv0, o[nt][1] * inv0);
        *(float2*)p1 = make_float2(o[nt][2] * inv1, o[nt][3] * inv1);
    }
}

// ---------------------------------------------------------------------------
// Slot attention pieces
// ---------------------------------------------------------------------------
__global__ void zero_slots_kernel(float* __restrict__ slots) {
    int idx = blockIdx.x * blockDim.x + threadIdx.x;
    if (idx < Bc * NSc * FDc) slots[idx] = 0.f;
}

__global__ __launch_bounds__(256)
void slot_logits_kernel(const float* __restrict__ kin,
                        const float* __restrict__ qs,
                        float* __restrict__ sattn,
                        float* __restrict__ denom) {
    int b = blockIdx.x;
    __shared__ float q[8][320];
    __shared__ float sat[256][8];
    for (int i = threadIdx.x; i < 8 * 320; i += 256)
        q[i / 320][i % 320] = qs[b * 8 * 320 + i];
    __syncthreads();
    int warp = threadIdx.x >> 5, lane = threadIdx.x & 31;
    for (int n = warp; n < 256; n += 8) {
        const float* kr = kin + ((size_t)b * 256 + n) * 320;
        float part[8] = {};
        for (int f = lane; f < 320; f += 32) {
            float kv = kr[f];
            #pragma unroll
            for (int s = 0; s < 8; s++) part[s] += kv * q[s][f];
        }
        #pragma unroll
        for (int s = 0; s < 8; s++)
            #pragma unroll
            for (int o = 16; o; o >>= 1)
                part[s] += __shfl_xor_sync(0xffffffffu, part[s], o);
        if (lane == 0) {
            const float scale = 0.05590169943749474f;  // 1/sqrt(320)
            float mx = -1e30f;
            #pragma unroll
            for (int s = 0; s < 8; s++) { part[s] *= scale; mx = fmaxf(mx, part[s]); }
            float e[8], sum = 0.f;
            #pragma unroll
            for (int s = 0; s < 8; s++) { e[s] = expf(part[s] - mx); sum += e[s]; }
            float inv = 1.f / sum;
            #pragma unroll
            for (int s = 0; s < 8; s++) sat[n][s] = e[s] * inv;
        }
    }
    __syncthreads();
    {
        float d = 0.f;
        for (int n = lane; n < 256; n += 32) d += sat[n][warp] + 1e-8f;
        #pragma unroll
        for (int o = 16; o; o >>= 1) d += __shfl_xor_sync(0xffffffffu, d, o);
        if (lane == 0) denom[b * 8 + warp] = d;
    }
    for (int i = threadIdx.x; i < 2048; i += 256)
        sattn[(size_t)b * 2048 + i] = sat[i >> 3][i & 7];
}

__global__ __launch_bounds__(320)
void updates_kernel(const float* __restrict__ sattn,
                    const float* __restrict__ denom,
                    const float* __restrict__ vin,
                    float* __restrict__ upd) {
    int b = blockIdx.x;
    int f = threadIdx.x;
    __shared__ float an[256][8];
    __shared__ float inv[8];
    for (int i = threadIdx.x; i < 2048; i += 320)
        an[i >> 3][i & 7] = sattn[(size_t)b * 2048 + i] + 1e-8f;
    if (threadIdx.x < 8) inv[threadIdx.x] = 1.f / denom[b * 8 + threadIdx.x];
    __syncthreads();
    float acc[8] = {};
    const float* vp = vin + (size_t)b * 256 * 320 + f;
    for (int n = 0; n < 256; n++) {
        float v = vp[(size_t)n * 320];
        #pragma unroll
        for (int s = 0; s < 8; s++) acc[s] += an[n][s] * v;
    }
    #pragma unroll
    for (int s = 0; s < 8; s++)
        upd[((size_t)b * 8 + s) * 320 + f] = acc[s] * inv[s];
}

__global__ __launch_bounds__(256)
void gru_ln_kernel(const float* __restrict__ gi, const float* __restrict__ gh,
                   float* __restrict__ slots,
                   const float* __restrict__ nm_g, const float* __restrict__ nm_b,
                   float* __restrict__ sln) {
    int row = blockIdx.x * 8 + (threadIdx.x >> 5);
    int lane = threadIdx.x & 31;
    const float* gir = gi + (size_t)row * 960;
    const float* ghr = gh + (size_t)row * 960;
    float* sr = slots + (size_t)row * 320;
    float news[10];
    float s = 0.f, sq = 0.f;
    #pragma unroll
    for (int i = 0; i < 10; i++) {
        int f = lane + 32 * i;
        float ir = gir[f], iz = gir[320 + f], in_ = gir[640 + f];
        float hr = ghr[f], hz = ghr[320 + f], hn  = ghr[640 + f];
        float r = 1.f / (1.f + __expf(-(ir + hr)));
        float z = 1.f / (1.f + __expf(-(iz + hz)));
        float nn = tanhf(in_ + r * hn);
        float v = (1.f - z) * nn + z * sr[f];
        news[i] = v;
        s += v; sq += v * v;
    }
    #pragma unroll
    for (int o = 16; o; o >>= 1) {
        s  += __shfl_xor_sync(0xffffffffu, s, o);
        sq += __shfl_xor_sync(0xffffffffu, sq, o);
    }
    float mean = s / 320.f;
    float var = sq / 320.f - mean * mean;
    float inv = rsqrtf(fmaxf(var, 0.f) + 1e-5f);
    float* lr = sln + (size_t)row * 320;
    #pragma unroll
    for (int i = 0; i < 10; i++) {
        int f = lane + 32 * i;
        sr[f] = news[i];
        lr[f] = (news[i] - mean) * inv * nm_g[f] + nm_b[f];
    }
}

__global__ void output_kernel(const float* __restrict__ slots,
                              const float* __restrict__ sattn,
                              float* __restrict__ out) {
    int idx = blockIdx.x * blockDim.x + threadIdx.x;
    const int SLOTS = Bc * NSc * FDc;      // 163840
    const int MASKS = Bc * NSc * Nc;       // 131072
    if (idx < SLOTS) {
        out[idx] = slots[idx];
    } else if (idx < SLOTS + MASKS) {
        int k = idx - SLOTS;
        int b = k / (NSc * Nc);
        int r = k % (NSc * Nc);
        int s = r / Nc;
        int n = r % Nc;
        out[idx] = sattn[((size_t)b * Nc + n) * NSc + s];
    }
}

// ---------------------------------------------------------------------------
// Host launcher
// ---------------------------------------------------------------------------
template <typename T>
static float* sym_addr(T& sym) {
    void* p = nullptr;
    cudaGetSymbolAddress(&p, sym);
    return (float*)p;
}

extern "C" void kernel_launch(void* const* d_in, const int* in_sizes, int n_in,
                              void* d_out, int out_size) {
    const float* state    = (const float*)d_in[0];
    const float* conv_w   = (const float*)d_in[1];
    const float* conv_b   = (const float*)d_in[2];
    const float* mlp_ln_g = (const float*)d_in[3];
    const float* mlp_ln_b = (const float*)d_in[4];
    const float* mlp_w1   = (const float*)d_in[5];
    const float* mlp_b1   = (const float*)d_in[6];
    const float* mlp_w2   = (const float*)d_in[7];
    const float* mlp_b2   = (const float*)d_in[8];
    const float* qkv_w    = (const float*)d_in[9];
    const float* qkv_b    = (const float*)d_in[10];
    const float* proj_w   = (const float*)d_in[11];
    const float* proj_b   = (const float*)d_in[12];
    const float* ni_g     = (const float*)d_in[13];
    const float* ni_b     = (const float*)d_in[14];
    const float* ns_g     = (const float*)d_in[15];
    const float* ns_b     = (const float*)d_in[16];
    const float* nm_g     = (const float*)d_in[17];
    const float* nm_b     = (const float*)d_in[18];
    const float* q_w      = (const float*)d_in[19];
    const float* k_w      = (const float*)d_in[20];
    const float* v_w      = (const float*)d_in[21];
    const float* gru_wih  = (const float*)d_in[22];
    const float* gru_whh  = (const float*)d_in[23];
    const float* gru_bih  = (const float*)d_in[24];
    const float* gru_bhh  = (const float*)d_in[25];
    const float* smlp_w1  = (const float*)d_in[26];
    const float* smlp_b1  = (const float*)d_in[27];
    const float* smlp_w2  = (const float*)d_in[28];
    const float* smlp_b2  = (const float*)d_in[29];
    float* out = (float*)d_out;

    float* P     = sym_addr(g_P);
    float* x0    = sym_addr(g_x0);
    float* lnb   = sym_addr(g_ln);
    float* h1    = sym_addr(g_h1);
    float* x2    = sym_addr(g_x2);
    float* ao    = sym_addr(g_ao);
    float* x3    = sym_addr(g_x3);
    float* kin   = sym_addr(g_kin);
    float* vin   = sym_addr(g_vin);
    float* slots = sym_addr(g_slots);
    float* sln   = sym_addr(g_sln);
    float* qs    = sym_addr(g_qs);
    float* sattn = sym_addr(g_sattn);
    float* denom = sym_addr(g_denom);
    float* upd   = sym_addr(g_upd);
    float* gi    = sym_addr(g_gi);
    float* gh    = sym_addr(g_gh);
    float* m1    = sym_addr(g_m1);

    const int ATTN_SMEM = 4 * 64 * 68 * 4;   // 69632 bytes
    cudaFuncSetAttribute(attn_mma_kernel,
                         cudaFuncAttributeMaxDynamicSharedMemorySize, ATTN_SMEM);

    // 1. RoPE tables + patch matrix
    rope_init_kernel<<<Nc, HDc>>>();
    patch_kernel<<<TOK, 64>>>(state, P);

    // 2. Patch conv as GEMM (tensor cores)
    gemm128(P, conv_w, conv_b, nullptr, x0, TOK, 256, 768, 0);

    // 3. Token MLP
    ln_warp_kernel<<<TOK / 8, 256>>>(x0, mlp_ln_g, mlp_ln_b, lnb, 256);
    gemm128(lnb, mlp_w1, mlp_b1, nullptr, h1, TOK, 512, 256, 1);
    gemm128(h1, mlp_w2, mlp_b2, nullptr, x2, TOK, 256, 512, 0);

    // 4. QKV + RoPE + attention (tensor cores) + proj (residual with x2)
    gemm128(x2, qkv_w, qkv_b, nullptr, P, TOK, 768, 256, 0);
    rope_apply_kernel<<<TOK, 256>>>(P);
    attn_mma_kernel<<<dim3(4, HEADSc, Bc), 128, ATTN_SMEM>>>(P, ao);
    gemm128(ao, proj_w, proj_b, x2, x3, TOK, 256, 256, 0);

    // 5. Norm + fused k/v projection (N = 640, split at 320)
    ln_warp_kernel<<<TOK / 8, 256>>>(x3, ni_g, ni_b, lnb, 256);
    {
        dim3 grid(640 / 128, TOK / 128);
        gemm128_kernel<<<grid, 256>>>(lnb, k_w, v_w, 320, nullptr, nullptr,
                                      kin, vin, TOK, 640, 256, 0);
    }

    // 6. Slot attention, 3 iterations (3xTF32 precision)
    zero_slots_kernel<<<(Bc * NSc * FDc + 255) / 256, 256>>>(slots);
    for (int it = 0; it < ITc; it++) {
        ln_warp_kernel<<<Bc * NSc / 8, 256>>>(slots, ns_g, ns_b, sln, 320);
        gemm_x3(sln, q_w, nullptr, nullptr, qs, Bc * NSc, 320, 320, 0);
        slot_logits_kernel<<<Bc, 256>>>(kin, qs, sattn, denom);
        updates_kernel<<<Bc, 320>>>(sattn, denom, vin, upd);
        gemm_x3(upd,   gru_wih, gru_bih, nullptr, gi, Bc * NSc, 960, 320, 0);
        gemm_x3(slots, gru_whh, gru_bhh, nullptr, gh, Bc * NSc, 960, 320, 0);
        gru_ln_kernel<<<Bc * NSc / 8, 256>>>(gi, gh, slots, nm_g, nm_b, sln);
        gemm_x3(sln, smlp_w1, smlp_b1, nullptr, m1, Bc * NSc, 640, 320, 1);
        gemm_x3(m1, smlp_w2, smlp_b2, slots, slots, Bc * NSc, 320, 640, 0);
    }

    // 7. Pack outputs
    int total = Bc * NSc * FDc + Bc * NSc * Nc;
    output_kernel<<<(total + 255) / 256, 256>>>(slots, sattn, out);
}

// round 6
// speedup vs baseline: 2.7686x; 1.4837x over previous
#include <cuda_runtime.h>
#include <math.h>
#include <stdint.h>

// ---------------------------------------------------------------------------
// Problem constants
// ---------------------------------------------------------------------------
constexpr int Bc = 64, Hc = 128, Wc = 128, PSc = 8, Gc = 16, Ec = 256;
constexpr int NSc = 8, ITc = 3, Vc = 10, FDc = 320, HEADSc = 4, HDc = 64;
constexpr int Nc = Gc * Gc;          // 256 tokens per image
constexpr int TOK = Bc * Nc;         // 16384 rows

// ---------------------------------------------------------------------------
// Device scratch
// ---------------------------------------------------------------------------
__device__ float g_P   [TOK * 768];        // im2col patches; reused for QKV
__device__ float g_x0  [TOK * Ec];
__device__ float g_ln  [TOK * Ec];
__device__ float g_h1  [TOK * 512];
__device__ float g_x2  [TOK * Ec];
__device__ float g_ao  [TOK * Ec];
__device__ float g_x3  [TOK * Ec];
__device__ float g_cosT[Nc * HDc];
__device__ float g_sinT[Nc * HDc];
// slot path (collapsed: one row per batch, slots identical across s)
__device__ float g_xbar [Bc * Ec];         // mean over tokens of lnb
__device__ float g_vbar [Bc * FDc];        // = xbar @ v_w^T (== updates rows)
__device__ float g_slots[Bc * FDc];        // per-b slot vector
__device__ float g_sln  [Bc * FDc];
__device__ float g_gi   [Bc * 3 * FDc];    // iteration-invariant
__device__ float g_gh   [Bc * 3 * FDc];
__device__ float g_m1   [Bc * 2 * FDc];

// ---------------------------------------------------------------------------
// Helpers
// ---------------------------------------------------------------------------
__device__ __forceinline__ float gelu_exact(float x) {
    return 0.5f * x * (1.0f + erff(x * 0.70710678118654752f));
}

__device__ __forceinline__ uint32_t f2tf32(float x) {
    uint32_t r;
    asm("cvt.rna.tf32.f32 %0, %1;" : "=r"(r) : "f"(x));
    return r;
}

__device__ __forceinline__ void mma_tf32(float (&d)[4], const uint32_t (&a)[4],
                                         const uint32_t (&b)[2]) {
    asm volatile(
        "mma.sync.aligned.m16n8k8.row.col.f32.tf32.tf32.f32 "
        "{%0,%1,%2,%3}, {%4,%5,%6,%7}, {%8,%9}, {%0,%1,%2,%3};\n"
        : "+f"(d[0]), "+f"(d[1]), "+f"(d[2]), "+f"(d[3])
        : "r"(a[0]), "r"(a[1]), "r"(a[2]), "r"(a[3]), "r"(b[0]), "r"(b[1]));
}

// ---------------------------------------------------------------------------
// RoPE tables
// ---------------------------------------------------------------------------
__global__ void rope_init_kernel() {
    int n = blockIdx.x;          // 0..255
    int d = threadIdx.x;         // 0..63
    int gy = n >> 4, gx = n & 15;
    int pos = (d < 32) ? gy : gx;
    int dd  = (d < 32) ? d : d - 32;
    float val;
    if (dd < 16) {
        float inv = expf(-9.210340371976184f * (2.0f * dd) / 32.0f);
        val = sinf((float)pos * inv);
    } else {
        float inv = expf(-9.210340371976184f * (2.0f * (dd - 16)) / 32.0f);
        val = cosf((float)pos * inv);
    }
    g_cosT[n * 64 + d] = cosf(val);
    g_sinT[n * 64 + d] = sinf(val);
}

// ---------------------------------------------------------------------------
// Patch / im2col builder
// ---------------------------------------------------------------------------
__global__ void patch_kernel(const float* __restrict__ state, float* __restrict__ P) {
    int bn = blockIdx.x;
    int b = bn >> 8, n = bn & 255;
    int gy = n >> 4, gx = n & 15;
    int p = threadIdx.x;               // 0..63
    int py = p >> 3, px = p & 7;
    int y = gy * 8 + py, x = gx * 8 + px;
    const float* sb = state + (size_t)b * Hc * Wc;
    float* row = P + (size_t)bn * 768;
    for (int k = p; k < 768; k += 64) row[k] = 0.f;

    float v[3][3];
    #pragma unroll
    for (int di = 0; di < 3; di++) {
        int yy = min(max(y + di - 1, 0), Hc - 1);
        #pragma unroll
        for (int dj = 0; dj < 3; dj++) {
            int xx = min(max(x + dj - 1, 0), Wc - 1);
            v[di][dj] = sb[yy * Wc + xx];
        }
    }
    float sx = (v[0][2] + 2.f * v[1][2] + v[2][2]) - (v[0][0] + 2.f * v[1][0] + v[2][0]);
    float sy = (v[2][0] + 2.f * v[2][1] + v[2][2]) - (v[0][0] + 2.f * v[0][1] + v[0][2]);
    int id = (int)sb[y * Wc + x];
    __syncthreads();
    row[id * 64 + p]  = 1.f;
    row[640 + p]      = sx;
    row[704 + p]      = sy;
}

// ---------------------------------------------------------------------------
// TF32 tensor-core GEMM, fragment-major smem layout.
// BM=128, BN=128, BK=16, 256 threads (8 warps), warp tile m32 x n64.
// ---------------------------------------------------------------------------
constexpr int ATILE = 132;
constexpr int BTILE = 66;
constexpr int ABUF  = 16 * ATILE;
constexpr int BBUF  = 32 * BTILE;

__global__ __launch_bounds__(256)
void gemm128_kernel(const float* __restrict__ A,
                    const float* __restrict__ W,
                    const float* __restrict__ bias, const float* __restrict__ res,
                    float* __restrict__ C,
                    int M, int N, int K, int act) {
    __shared__ uint32_t As[2][ABUF];
    __shared__ uint32_t Bs[2][BBUF];

    int tid = threadIdx.x;
    int m0 = blockIdx.y * 128, n0 = blockIdx.x * 128;
    int warp = tid >> 5, lane = tid & 31;
    int wm = warp & 3, wn = warp >> 2;
    int q = lane >> 2, t = lane & 3;

    int r  = tid >> 2;
    int k4 = (tid & 3) << 2;

    int q8     = r & 7;
    int hiA    = (r >> 3) & 1;
    int mt0    = r >> 4;
    int kchunk = k4 >> 3;
    int kw     = (k4 >> 2) & 1;
    int baseA0 = (mt0 * 2 + kchunk) * ATILE       + q8 * 16 + (hiA + 2 * kw);
    int baseA1 = ((mt0 + 4) * 2 + kchunk) * ATILE + q8 * 16 + (hiA + 2 * kw);
    int nt0    = r >> 3;
    int baseB0 = (nt0 * 2 + kchunk) * BTILE       + q8 * 8 + kw;
    int baseB1 = ((nt0 + 8) * 2 + kchunk) * BTILE + q8 * 8 + kw;

    const float* Ap0 = A + (size_t)(m0 + r) * K + k4;
    const float* Ap1 = Ap0 + (size_t)64 * K;
    const float* Wp0 = W + (size_t)(n0 + r) * K + k4;
    const float* Wp1 = W + (size_t)(n0 + r + 64) * K + k4;

    float acc[2][8][4];
    #pragma unroll
    for (int mt = 0; mt < 2; mt++)
        #pragma unroll
        for (int nt = 0; nt < 8; nt++)
            #pragma unroll
            for (int i = 0; i < 4; i++) acc[mt][nt][i] = 0.f;

    int ntiles = K >> 4;
    float4 a0 = *(const float4*)Ap0;
    float4 a1 = *(const float4*)Ap1;
    float4 b0 = *(const float4*)Wp0;
    float4 b1 = *(const float4*)Wp1;
    int buf = 0;
    {
        As[0][baseA0 + 0]  = f2tf32(a0.x); As[0][baseA0 + 4]  = f2tf32(a0.y);
        As[0][baseA0 + 8]  = f2tf32(a0.z); As[0][baseA0 + 12] = f2tf32(a0.w);
        As[0][baseA1 + 0]  = f2tf32(a1.x); As[0][baseA1 + 4]  = f2tf32(a1.y);
        As[0][baseA1 + 8]  = f2tf32(a1.z); As[0][baseA1 + 12] = f2tf32(a1.w);
        Bs[0][baseB0 + 0]  = f2tf32(b0.x); Bs[0][baseB0 + 2]  = f2tf32(b0.y);
        Bs[0][baseB0 + 4]  = f2tf32(b0.z); Bs[0][baseB0 + 6]  = f2tf32(b0.w);
        Bs[0][baseB1 + 0]  = f2tf32(b1.x); Bs[0][baseB1 + 2]  = f2tf32(b1.y);
        Bs[0][baseB1 + 4]  = f2tf32(b1.z); Bs[0][baseB1 + 6]  = f2tf32(b1.w);
    }
    __syncthreads();

    for (int kt = 0; kt < ntiles; kt++) {
        bool more = (kt + 1 < ntiles);
        if (more) {
            a0 = *(const float4*)(Ap0 + (kt + 1) * 16);
            a1 = *(const float4*)(Ap1 + (kt + 1) * 16);
            b0 = *(const float4*)(Wp0 + (kt + 1) * 16);
            b1 = *(const float4*)(Wp1 + (kt + 1) * 16);
        }
        #pragma unroll
        for (int ks = 0; ks < 2; ks++) {
            uint32_t af[2][4], bf[8][2];
            #pragma unroll
            for (int mt = 0; mt < 2; mt++) {
                int tile = (wm * 2 + mt) * 2 + ks;
                uint4 v = *(const uint4*)&As[buf][tile * ATILE + lane * 4];
                af[mt][0] = v.x; af[mt][1] = v.y; af[mt][2] = v.z; af[mt][3] = v.w;
            }
            #pragma unroll
            for (int nt = 0; nt < 8; nt++) {
                int tile = (wn * 8 + nt) * 2 + ks;
                uint2 v = *(const uint2*)&Bs[buf][tile * BTILE + lane * 2];
                bf[nt][0] = v.x; bf[nt][1] = v.y;
            }
            #pragma unroll
            for (int mt = 0; mt < 2; mt++)
                #pragma unroll
                for (int nt = 0; nt < 8; nt++)
                    mma_tf32(acc[mt][nt], af[mt], bf[nt]);
        }
        __syncthreads();
        if (more) {
            buf ^= 1;
            As[buf][baseA0 + 0]  = f2tf32(a0.x); As[buf][baseA0 + 4]  = f2tf32(a0.y);
            As[buf][baseA0 + 8]  = f2tf32(a0.z); As[buf][baseA0 + 12] = f2tf32(a0.w);
            As[buf][baseA1 + 0]  = f2tf32(a1.x); As[buf][baseA1 + 4]  = f2tf32(a1.y);
            As[buf][baseA1 + 8]  = f2tf32(a1.z); As[buf][baseA1 + 12] = f2tf32(a1.w);
            Bs[buf][baseB0 + 0]  = f2tf32(b0.x); Bs[buf][baseB0 + 2]  = f2tf32(b0.y);
            Bs[buf][baseB0 + 4]  = f2tf32(b0.z); Bs[buf][baseB0 + 6]  = f2tf32(b0.w);
            Bs[buf][baseB1 + 0]  = f2tf32(b1.x); Bs[buf][baseB1 + 2]  = f2tf32(b1.y);
            Bs[buf][baseB1 + 4]  = f2tf32(b1.z); Bs[buf][baseB1 + 6]  = f2tf32(b1.w);
            __syncthreads();
        }
    }

    #pragma unroll
    for (int mt = 0; mt < 2; mt++) {
        #pragma unroll
        for (int nt = 0; nt < 8; nt++) {
            int gm0 = m0 + wm * 32 + mt * 16 + q;
            int gn  = n0 + wn * 64 + nt * 8 + 2 * t;
            float bb0 = bias ? bias[gn]     : 0.f;
            float bb1 = bias ? bias[gn + 1] : 0.f;
            #pragma unroll
            for (int half = 0; half < 2; half++) {
                int gm = gm0 + half * 8;
                float c0 = acc[mt][nt][half * 2 + 0] + bb0;
                float c1 = acc[mt][nt][half * 2 + 1] + bb1;
                if (act == 1) { c0 = gelu_exact(c0); c1 = gelu_exact(c1); }
                size_t idx = (size_t)gm * N + gn;
                if (res) { c0 += res[idx]; c1 += res[idx + 1]; }
                *(float2*)(C + idx) = make_float2(c0, c1);
            }
        }
    }
}

static inline void gemm128(const float* A, const float* W, const float* bias,
                           const float* res, float* C, int M, int N, int K, int act) {
    dim3 grid(N / 128, M / 128);
    gemm128_kernel<<<grid, 256>>>(A, W, bias, res, C, M, N, K, act);
}

// ---------------------------------------------------------------------------
// 3xTF32 GEMM (near-fp32 accuracy) for slot-loop GEMMs. BM=BN=64, BK=16.
// ---------------------------------------------------------------------------
__global__ __launch_bounds__(256)
void gemm_tf32x3_kernel(const float* __restrict__ A, const float* __restrict__ W,
                        const float* __restrict__ bias, const float* __restrict__ res,
                        float* __restrict__ C, int M, int N, int K, int act) {
    __shared__ uint32_t Ah[64][20], Al[64][20], Bh[64][20], Bl[64][20];

    int tid = threadIdx.x;
    int m0 = blockIdx.y * 64, n0 = blockIdx.x * 64;
    int warp = tid >> 5, lane = tid & 31;
    int wm = warp & 1, wn = warp >> 1;
    int q = lane >> 2, t = lane & 3;

    int aRow = tid >> 2;
    int k4   = (tid & 3) << 2;
    const float* Aptr = A + (size_t)(m0 + aRow) * K + k4;
    const float* Wptr = W + (size_t)(n0 + aRow) * K + k4;

    float acc[2][2][4];
    #pragma unroll
    for (int mt = 0; mt < 2; mt++)
        #pragma unroll
        for (int nt = 0; nt < 2; nt++)
            #pragma unroll
            for (int i = 0; i < 4; i++) acc[mt][nt][i] = 0.f;

    for (int kt = 0; kt < K; kt += 16) {
        float4 av = *(const float4*)(Aptr + kt);
        float4 bv = *(const float4*)(Wptr + kt);
        float a4[4] = {av.x, av.y, av.z, av.w};
        float b4[4] = {bv.x, bv.y, bv.z, bv.w};
        #pragma unroll
        for (int i = 0; i < 4; i++) {
            uint32_t h = f2tf32(a4[i]);
            Ah[aRow][k4 + i] = h;
            Al[aRow][k4 + i] = f2tf32(a4[i] - __uint_as_float(h));
            h = f2tf32(b4[i]);
            Bh[aRow][k4 + i] = h;
            Bl[aRow][k4 + i] = f2tf32(b4[i] - __uint_as_float(h));
        }
        __syncthreads();
        #pragma unroll
        for (int ks = 0; ks < 2; ks++) {
            int kc = ks * 8 + t;
            uint32_t ah[2][4], al[2][4], bh[2][2], bl[2][2];
            #pragma unroll
            for (int mt = 0; mt < 2; mt++) {
                int rr = wm * 32 + mt * 16 + q;
                ah[mt][0] = Ah[rr][kc];   ah[mt][1] = Ah[rr + 8][kc];
                ah[mt][2] = Ah[rr][kc+4]; ah[mt][3] = Ah[rr + 8][kc+4];
                al[mt][0] = Al[rr][kc];   al[mt][1] = Al[rr + 8][kc];
                al[mt][2] = Al[rr][kc+4]; al[mt][3] = Al[rr + 8][kc+4];
            }
            #pragma unroll
            for (int nt = 0; nt < 2; nt++) {
                int nn = wn * 16 + nt * 8 + q;
                bh[nt][0] = Bh[nn][kc]; bh[nt][1] = Bh[nn][kc + 4];
                bl[nt][0] = Bl[nn][kc]; bl[nt][1] = Bl[nn][kc + 4];
            }
            #pragma unroll
            for (int mt = 0; mt < 2; mt++)
                #pragma unroll
                for (int nt = 0; nt < 2; nt++) {
                    mma_tf32(acc[mt][nt], al[mt], bh[nt]);
                    mma_tf32(acc[mt][nt], ah[mt], bl[nt]);
                    mma_tf32(acc[mt][nt], ah[mt], bh[nt]);
                }
        }
        __syncthreads();
    }

    #pragma unroll
    for (int mt = 0; mt < 2; mt++) {
        #pragma unroll
        for (int nt = 0; nt < 2; nt++) {
            int gm0 = m0 + wm * 32 + mt * 16 + q;
            int gn  = n0 + wn * 16 + nt * 8 + 2 * t;
            float b0 = bias ? bias[gn]     : 0.f;
            float b1 = bias ? bias[gn + 1] : 0.f;
            #pragma unroll
            for (int half = 0; half < 2; half++) {
                int gm = gm0 + half * 8;
                float c0 = acc[mt][nt][half * 2 + 0] + b0;
                float c1 = acc[mt][nt][half * 2 + 1] + b1;
                if (act == 1) { c0 = gelu_exact(c0); c1 = gelu_exact(c1); }
                size_t idx = (size_t)gm * N + gn;
                if (res) { c0 += res[idx]; c1 += res[idx + 1]; }
                *(float2*)(C + idx) = make_float2(c0, c1);
            }
        }
    }
}

static inline void gemm_x3(const float* A, const float* W, const float* bias,
                           const float* res, float* C, int M, int N, int K, int act) {
    dim3 grid(N / 64, M / 64);
    gemm_tf32x3_kernel<<<grid, 256>>>(A, W, bias, res, C, M, N, K, act);
}

// ---------------------------------------------------------------------------
// LayerNorm: warp per row, single pass, float4.
// ---------------------------------------------------------------------------
__global__ __launch_bounds__(256)
void ln_warp_kernel(const float* __restrict__ x, const float* __restrict__ g,
                    const float* __restrict__ b, float* __restrict__ y, int cols) {
    int row = blockIdx.x * 8 + (threadIdx.x >> 5);
    int lane = threadIdx.x & 31;
    int cols4 = cols >> 2;
    const float4* xr = (const float4*)(x + (size_t)row * cols);
    float s = 0.f, sq = 0.f;
    for (int c = lane; c < cols4; c += 32) {
        float4 v = xr[c];
        s  += (v.x + v.y) + (v.z + v.w);
        sq += v.x * v.x + v.y * v.y + v.z * v.z + v.w * v.w;
    }
    #pragma unroll
    for (int o = 16; o; o >>= 1) {
        s  += __shfl_xor_sync(0xffffffffu, s, o);
        sq += __shfl_xor_sync(0xffffffffu, sq, o);
    }
    float mean = s / (float)cols;
    float var = sq / (float)cols - mean * mean;
    float inv = rsqrtf(fmaxf(var, 0.f) + 1e-5f);
    float4* yr = (float4*)(y + (size_t)row * cols);
    const float4* g4 = (const float4*)g;
    const float4* b4 = (const float4*)b;
    for (int c = lane; c < cols4; c += 32) {
        float4 v = xr[c], gg = g4[c], bb = b4[c], o;
        o.x = (v.x - mean) * inv * gg.x + bb.x;
        o.y = (v.y - mean) * inv * gg.y + bb.y;
        o.z = (v.z - mean) * inv * gg.z + bb.z;
        o.w = (v.w - mean) * inv * gg.w + bb.w;
        yr[c] = o;
    }
}

// ---------------------------------------------------------------------------
// RoPE apply
// ---------------------------------------------------------------------------
__global__ void rope_apply_kernel(float* __restrict__ qkv) {
    int row = blockIdx.x;
    int n = row & 255;
    int g = threadIdx.x >> 5;
    int t = threadIdx.x & 31;
    int s = g >> 2, h = g & 3;
    __shared__ float sh[8][64];
    float* p = qkv + (size_t)row * 768 + s * 256 + h * 64;
    sh[g][t]      = p[t];
    sh[g][t + 32] = p[t + 32];
    __syncwarp();
    float c1 = g_cosT[n * 64 + t],      s1 = g_sinT[n * 64 + t];
    float c2 = g_cosT[n * 64 + t + 32], s2 = g_sinT[n * 64 + t + 32];
    float o1 = sh[g][t]      * c1 - sh[g][2 * t + 1] * s1;
    float o2 = sh[g][t + 32] * c2 + sh[g][2 * t]     * s2;
    p[t]      = o1;
    p[t + 32] = o2;
}

// ---------------------------------------------------------------------------
// Attention via tf32 MMA, flash-style. Block = 128 threads (4 warps),
// each block handles 64 queries for one (b,h). grid (4 qtiles, 4 h, 64 b).
// ---------------------------------------------------------------------------
__global__ __launch_bounds__(128)
void attn_mma_kernel(const float* __restrict__ qkv, float* __restrict__ ao) {
    extern __shared__ uint32_t sm[];
    uint32_t (*Qs)[68] = (uint32_t(*)[68])(sm);
    uint32_t (*Ks)[68] = (uint32_t(*)[68])(sm + 64 * 68);
    uint32_t (*Vs)[68] = (uint32_t(*)[68])(sm + 2 * 64 * 68);
    uint32_t (*Ps)[68] = (uint32_t(*)[68])(sm + 3 * 64 * 68);

    int qt = blockIdx.x, h = blockIdx.y, b = blockIdx.z;
    int tid = threadIdx.x;
    int warp = tid >> 5, lane = tid & 31;
    int q = lane >> 2, t = lane & 3;

    const float* base = qkv + (size_t)b * 256 * 768 + h * 64;

    for (int idx = tid; idx < 64 * 16; idx += 128) {
        int r = idx >> 4, c4 = idx & 15;
        float4 v = *(const float4*)(base + (size_t)(qt * 64 + r) * 768 + c4 * 4);
        Qs[r][c4 * 4 + 0] = f2tf32(v.x);
        Qs[r][c4 * 4 + 1] = f2tf32(v.y);
        Qs[r][c4 * 4 + 2] = f2tf32(v.z);
        Qs[r][c4 * 4 + 3] = f2tf32(v.w);
    }
    __syncthreads();

    uint32_t aq[8][4];
    #pragma unroll
    for (int kk = 0; kk < 8; kk++) {
        int rr = warp * 16 + q;
        aq[kk][0] = Qs[rr][8 * kk + t];
        aq[kk][1] = Qs[rr + 8][8 * kk + t];
        aq[kk][2] = Qs[rr][8 * kk + t + 4];
        aq[kk][3] = Qs[rr + 8][8 * kk + t + 4];
    }

    float m0 = -1e30f, m1 = -1e30f, l0 = 0.f, l1 = 0.f;
    float o[8][4];
    #pragma unroll
    for (int nt = 0; nt < 8; nt++)
        #pragma unroll
        for (int i = 0; i < 4; i++) o[nt][i] = 0.f;

    for (int kt = 0; kt < 4; kt++) {
        for (int idx = tid; idx < 64 * 16; idx += 128) {
            int r = idx >> 4, c4 = idx & 15;
            const float* rp = base + (size_t)(kt * 64 + r) * 768;
            float4 kv = *(const float4*)(rp + 256 + c4 * 4);
            float4 vv = *(const float4*)(rp + 512 + c4 * 4);
            Ks[r][c4 * 4 + 0] = f2tf32(kv.x); Ks[r][c4 * 4 + 1] = f2tf32(kv.y);
            Ks[r][c4 * 4 + 2] = f2tf32(kv.z); Ks[r][c4 * 4 + 3] = f2tf32(kv.w);
            Vs[r][c4 * 4 + 0] = f2tf32(vv.x); Vs[r][c4 * 4 + 1] = f2tf32(vv.y);
            Vs[r][c4 * 4 + 2] = f2tf32(vv.z); Vs[r][c4 * 4 + 3] = f2tf32(vv.w);
        }
        __syncthreads();

        float s[8][4];
        #pragma unroll
        for (int nt = 0; nt < 8; nt++)
            #pragma unroll
            for (int i = 0; i < 4; i++) s[nt][i] = 0.f;
        #pragma unroll
        for (int kk = 0; kk < 8; kk++) {
            #pragma unroll
            for (int nt = 0; nt < 8; nt++) {
                uint32_t bf[2] = {Ks[nt * 8 + q][8 * kk + t],
                                  Ks[nt * 8 + q][8 * kk + t + 4]};
                mma_tf32(s[nt], aq[kk], bf);
            }
        }

        float rmax0 = -1e30f, rmax1 = -1e30f;
        #pragma unroll
        for (int nt = 0; nt < 8; nt++) {
            s[nt][0] *= 0.125f; s[nt][1] *= 0.125f;
            s[nt][2] *= 0.125f; s[nt][3] *= 0.125f;
            rmax0 = fmaxf(rmax0, fmaxf(s[nt][0], s[nt][1]));
            rmax1 = fmaxf(rmax1, fmaxf(s[nt][2], s[nt][3]));
        }
        rmax0 = fmaxf(rmax0, __shfl_xor_sync(0xffffffffu, rmax0, 1));
        rmax0 = fmaxf(rmax0, __shfl_xor_sync(0xffffffffu, rmax0, 2));
        rmax1 = fmaxf(rmax1, __shfl_xor_sync(0xffffffffu, rmax1, 1));
        rmax1 = fmaxf(rmax1, __shfl_xor_sync(0xffffffffu, rmax1, 2));
        float nm0 = fmaxf(m0, rmax0), nm1 = fmaxf(m1, rmax1);
        float c0 = __expf(m0 - nm0), c1 = __expf(m1 - nm1);
        m0 = nm0; m1 = nm1;
        float rs0 = 0.f, rs1 = 0.f;
        #pragma unroll
        for (int nt = 0; nt < 8; nt++) {
            s[nt][0] = __expf(s[nt][0] - m0);
            s[nt][1] = __expf(s[nt][1] - m0);
            s[nt][2] = __expf(s[nt][2] - m1);
            s[nt][3] = __expf(s[nt][3] - m1);
            rs0 += s[nt][0] + s[nt][1];
            rs1 += s[nt][2] + s[nt][3];
        }
        rs0 += __shfl_xor_sync(0xffffffffu, rs0, 1);
        rs0 += __shfl_xor_sync(0xffffffffu, rs0, 2);
        rs1 += __shfl_xor_sync(0xffffffffu, rs1, 1);
        rs1 += __shfl_xor_sync(0xffffffffu, rs1, 2);
        l0 = l0 * c0 + rs0;
        l1 = l1 * c1 + rs1;
        #pragma unroll
        for (int nt = 0; nt < 8; nt++) {
            o[nt][0] *= c0; o[nt][1] *= c0;
            o[nt][2] *= c1; o[nt][3] *= c1;
        }

        #pragma unroll
        for (int nt = 0; nt < 8; nt++) {
            int col = nt * 8 + 2 * t;
            Ps[warp * 16 + q][col]         = f2tf32(s[nt][0]);
            Ps[warp * 16 + q][col + 1]     = f2tf32(s[nt][1]);
            Ps[warp * 16 + q + 8][col]     = f2tf32(s[nt][2]);
            Ps[warp * 16 + q + 8][col + 1] = f2tf32(s[nt][3]);
        }
        __syncwarp();

        #pragma unroll
        for (int kk = 0; kk < 8; kk++) {
            uint32_t pa[4];
            pa[0] = Ps[warp * 16 + q][8 * kk + t];
            pa[1] = Ps[warp * 16 + q + 8][8 * kk + t];
            pa[2] = Ps[warp * 16 + q][8 * kk + t + 4];
            pa[3] = Ps[warp * 16 + q + 8][8 * kk + t + 4];
            #pragma unroll
            for (int nt = 0; nt < 8; nt++) {
                uint32_t bf[2] = {Vs[8 * kk + t][8 * nt + q],
                                  Vs[8 * kk + t + 4][8 * nt + q]};
                mma_tf32(o[nt], pa, bf);
            }
        }
        __syncthreads();
    }

    float inv0 = 1.f / l0, inv1 = 1.f / l1;
    int r0 = qt * 64 + warp * 16 + q;
    #pragma unroll
    for (int nt = 0; nt < 8; nt++) {
        int col = h * 64 + nt * 8 + 2 * t;
        float* p0 = ao + ((size_t)b * 256 + r0) * 256 + col;
        float* p1 = ao + ((size_t)b * 256 + r0 + 8) * 256 + col;
        *(float2*)p0 = make_float2(o[nt][0] * inv0, o[nt][1] * inv0);
        *(float2*)p1 = make_float2(o[nt][2] * inv1, o[nt][3] * inv1);
    }
}

// ---------------------------------------------------------------------------
// Collapsed slot path.
// Slots are provably identical across s (zero init, symmetric updates):
// softmax over s of constant logits = 1/8, token-normalized an = 1/256,
// so updates = mean_n(v_in) = (mean_n lnb) @ v_w^T, same every iteration.
// ---------------------------------------------------------------------------

// column mean over 256 tokens per batch: xbar[b, c] = mean_n lnb[b*256+n, c]
__global__ __launch_bounds__(256)
void colmean_kernel(const float* __restrict__ lnb, float* __restrict__ xbar) {
    int b = blockIdx.x;
    int c = threadIdx.x;
    const float* p = lnb + (size_t)b * 256 * 256 + c;
    float s = 0.f;
    #pragma unroll 8
    for (int n = 0; n < 256; n++) s += p[(size_t)n * 256];
    xbar[b * 256 + c] = s * (1.f / 256.f);
}

__global__ void zero_slots_kernel(float* __restrict__ slots) {
    int idx = blockIdx.x * blockDim.x + threadIdx.x;
    if (idx < Bc * FDc) slots[idx] = 0.f;
}

// GRU gate combine + nm-LayerNorm fused. Warp per row (64 rows), grid 8.
__global__ __launch_bounds__(256)
void gru_ln_kernel(const float* __restrict__ gi, const float* __restrict__ gh,
                   float* __restrict__ slots,
                   const float* __restrict__ nm_g, const float* __restrict__ nm_b,
                   float* __restrict__ sln) {
    int row = blockIdx.x * 8 + (threadIdx.x >> 5);
    int lane = threadIdx.x & 31;
    const float* gir = gi + (size_t)row * 960;
    const float* ghr = gh + (size_t)row * 960;
    float* sr = slots + (size_t)row * 320;
    float news[10];
    float s = 0.f, sq = 0.f;
    #pragma unroll
    for (int i = 0; i < 10; i++) {
        int f = lane + 32 * i;
        float ir = gir[f], iz = gir[320 + f], in_ = gir[640 + f];
        float hr = ghr[f], hz = ghr[320 + f], hn  = ghr[640 + f];
        float r = 1.f / (1.f + __expf(-(ir + hr)));
        float z = 1.f / (1.f + __expf(-(iz + hz)));
        float nn = tanhf(in_ + r * hn);
        float v = (1.f - z) * nn + z * sr[f];
        news[i] = v;
        s += v; sq += v * v;
    }
    #pragma unroll
    for (int o = 16; o; o >>= 1) {
        s  += __shfl_xor_sync(0xffffffffu, s, o);
        sq += __shfl_xor_sync(0xffffffffu, sq, o);
    }
    float mean = s / 320.f;
    float var = sq / 320.f - mean * mean;
    float inv = rsqrtf(fmaxf(var, 0.f) + 1e-5f);
    float* lr = sln + (size_t)row * 320;
    #pragma unroll
    for (int i = 0; i < 10; i++) {
        int f = lane + 32 * i;
        sr[f] = news[i];
        lr[f] = (news[i] - mean) * inv * nm_g[f] + nm_b[f];
    }
}

// out = [slots broadcast to 8 slots per b (163840), masks = 0.125 (131072)]
__global__ void output_kernel(const float* __restrict__ slots,
                              float* __restrict__ out) {
    int idx = blockIdx.x * blockDim.x + threadIdx.x;
    const int SLOTS = Bc * NSc * FDc;      // 163840
    const int MASKS = Bc * NSc * Nc;       // 131072
    if (idx < SLOTS) {
        int b = idx / (NSc * FDc);
        int f = idx % FDc;
        out[idx] = slots[b * FDc + f];
    } else if (idx < SLOTS + MASKS) {
        out[idx] = 0.125f;
    }
}

// ---------------------------------------------------------------------------
// Host launcher
// ---------------------------------------------------------------------------
template <typename T>
static float* sym_addr(T& sym) {
    void* p = nullptr;
    cudaGetSymbolAddress(&p, sym);
    return (float*)p;
}

extern "C" void kernel_launch(void* const* d_in, const int* in_sizes, int n_in,
                              void* d_out, int out_size) {
    const float* state    = (const float*)d_in[0];
    const float* conv_w   = (const float*)d_in[1];
    const float* conv_b   = (const float*)d_in[2];
    const float* mlp_ln_g = (const float*)d_in[3];
    const float* mlp_ln_b = (const float*)d_in[4];
    const float* mlp_w1   = (const float*)d_in[5];
    const float* mlp_b1   = (const float*)d_in[6];
    const float* mlp_w2   = (const float*)d_in[7];
    const float* mlp_b2   = (const float*)d_in[8];
    const float* qkv_w    = (const float*)d_in[9];
    const float* qkv_b    = (const float*)d_in[10];
    const float* proj_w   = (const float*)d_in[11];
    const float* proj_b   = (const float*)d_in[12];
    const float* ni_g     = (const float*)d_in[13];
    const float* ni_b     = (const float*)d_in[14];
    // ns_g (15), ns_b (16): dead — logits path collapses
    const float* nm_g     = (const float*)d_in[17];
    const float* nm_b     = (const float*)d_in[18];
    // q_w (19), k_w (20): dead
    const float* v_w      = (const float*)d_in[21];
    const float* gru_wih  = (const float*)d_in[22];
    const float* gru_whh  = (const float*)d_in[23];
    const float* gru_bih  = (const float*)d_in[24];
    const float* gru_bhh  = (const float*)d_in[25];
    const float* smlp_w1  = (const float*)d_in[26];
    const float* smlp_b1  = (const float*)d_in[27];
    const float* smlp_w2  = (const float*)d_in[28];
    const float* smlp_b2  = (const float*)d_in[29];
    float* out = (float*)d_out;

    float* P     = sym_addr(g_P);
    float* x0    = sym_addr(g_x0);
    float* lnb   = sym_addr(g_ln);
    float* h1    = sym_addr(g_h1);
    float* x2    = sym_addr(g_x2);
    float* ao    = sym_addr(g_ao);
    float* x3    = sym_addr(g_x3);
    float* xbar  = sym_addr(g_xbar);
    float* vbar  = sym_addr(g_vbar);
    float* slots = sym_addr(g_slots);
    float* sln   = sym_addr(g_sln);
    float* gi    = sym_addr(g_gi);
    float* gh    = sym_addr(g_gh);
    float* m1    = sym_addr(g_m1);

    const int ATTN_SMEM = 4 * 64 * 68 * 4;   // 69632 bytes
    cudaFuncSetAttribute(attn_mma_kernel,
                         cudaFuncAttributeMaxDynamicSharedMemorySize, ATTN_SMEM);

    // 1. RoPE tables + patch matrix
    rope_init_kernel<<<Nc, HDc>>>();
    patch_kernel<<<TOK, 64>>>(state, P);

    // 2. Patch conv as GEMM (tensor cores)
    gemm128(P, conv_w, conv_b, nullptr, x0, TOK, 256, 768, 0);

    // 3. Token MLP
    ln_warp_kernel<<<TOK / 8, 256>>>(x0, mlp_ln_g, mlp_ln_b, lnb, 256);
    gemm128(lnb, mlp_w1, mlp_b1, nullptr, h1, TOK, 512, 256, 1);
    gemm128(h1, mlp_w2, mlp_b2, nullptr, x2, TOK, 256, 512, 0);

    // 4. QKV + RoPE + attention (tensor cores) + proj (residual with x2)
    gemm128(x2, qkv_w, qkv_b, nullptr, P, TOK, 768, 256, 0);
    rope_apply_kernel<<<TOK, 256>>>(P);
    attn_mma_kernel<<<dim3(4, HEADSc, Bc), 128, ATTN_SMEM>>>(P, ao);
    gemm128(ao, proj_w, proj_b, x2, x3, TOK, 256, 256, 0);

    // 5. Norm + collapsed slot-attention prologue:
    //    vbar = (mean_n LN(x3)) @ v_w^T ; gi = vbar @ wih^T + bih (loop-invariant)
    ln_warp_kernel<<<TOK / 8, 256>>>(x3, ni_g, ni_b, lnb, 256);
    colmean_kernel<<<Bc, 256>>>(lnb, xbar);
    gemm_x3(xbar, v_w, nullptr, nullptr, vbar, Bc, 320, 256, 0);
    gemm_x3(vbar, gru_wih, gru_bih, nullptr, gi, Bc, 960, 320, 0);
    zero_slots_kernel<<<(Bc * FDc + 255) / 256, 256>>>(slots);

    // 6. Slot iterations (collapsed to one row per batch)
    for (int it = 0; it < ITc; it++) {
        gemm_x3(slots, gru_whh, gru_bhh, nullptr, gh, Bc, 960, 320, 0);
        gru_ln_kernel<<<Bc / 8, 256>>>(gi, gh, slots, nm_g, nm_b, sln);
        gemm_x3(sln, smlp_w1, smlp_b1, nullptr, m1, Bc, 640, 320, 1);
        gemm_x3(m1, smlp_w2, smlp_b2, slots, slots, Bc, 320, 640, 0);
    }

    // 7. Pack outputs: broadcast slots across 8 slots, masks = 1/8 exactly
    int total = Bc * NSc * FDc + Bc * NSc * Nc;
    output_kernel<<<(total + 255) / 256, 256>>>(slots, out);
}